// round 1
// baseline (speedup 1.0000x reference)
#include <cuda_runtime.h>
#include <cuda_bf16.h>
#include <cstdint>

// Problem constants
#define B_  2
#define S_  1024
#define H_  2048
#define NH_ 32
#define NKV_ 8
#define HD_ 64
#define M_  (B_ * S_)          // 2048 rows of (b,s)

// ---------------------------------------------------------------------------
// Scratch (device globals — no allocation allowed in kernel_launch)
// ---------------------------------------------------------------------------
__device__ float g_qraw[M_ * (NH_ * HD_)];   // 2048 x 2048
__device__ float g_kraw[M_ * (NKV_ * HD_)];  // 2048 x 512
__device__ float g_vraw[M_ * (NKV_ * HD_)];  // 2048 x 512
__device__ float g_qh[B_ * NH_ * S_ * HD_];  // [b,h,s,d]
__device__ float g_kh[B_ * NKV_ * S_ * HD_]; // [b,hk,s,d]
__device__ float g_vh[B_ * NKV_ * S_ * HD_]; // [b,hk,s,d]
__device__ float g_ctx[M_ * (NH_ * HD_)];    // [b,s, h*64+d]

// ---------------------------------------------------------------------------
// SGEMM: C[M,N] = A[M,K] @ B[K,N], all row-major, fp32.
// 128x128 tile, BK=8, 256 threads, 8x8 per thread.
// Requires M%128==0, N%128==0, K%8==0 (true for all launches here).
// ---------------------------------------------------------------------------
__global__ __launch_bounds__(256) void sgemm128(
    const float* __restrict__ A, const float* __restrict__ Bm,
    float* __restrict__ C, int M, int N, int K)
{
    __shared__ float As[8][128];
    __shared__ float Bs[8][128];

    const int tid = threadIdx.x;
    const int tx = tid & 15;          // 0..15  (col group)
    const int ty = tid >> 4;          // 0..15  (row group)
    const int brow = blockIdx.y * 128;
    const int bcol = blockIdx.x * 128;

    // A tile load: 128 rows x 8 cols = 256 float4
    const int arow = tid >> 1;        // 0..127
    const int acol = (tid & 1) * 4;   // 0 or 4
    // B tile load: 8 rows x 128 cols = 256 float4
    const int brow_l = tid >> 5;      // 0..7
    const int bcol_l = (tid & 31) * 4;

    const float* Aptr = A + (size_t)(brow + arow) * K + acol;
    const float* Bptr = Bm + (size_t)brow_l * N + bcol + bcol_l;

    float acc[8][8];
#pragma unroll
    for (int i = 0; i < 8; i++)
#pragma unroll
        for (int j = 0; j < 8; j++) acc[i][j] = 0.f;

    for (int k0 = 0; k0 < K; k0 += 8) {
        float4 a4 = *reinterpret_cast<const float4*>(Aptr + k0);
        float4 b4 = *reinterpret_cast<const float4*>(Bptr + (size_t)k0 * N);
        As[acol + 0][arow] = a4.x;
        As[acol + 1][arow] = a4.y;
        As[acol + 2][arow] = a4.z;
        As[acol + 3][arow] = a4.w;
        *reinterpret_cast<float4*>(&Bs[brow_l][bcol_l]) = b4;
        __syncthreads();
#pragma unroll
        for (int kk = 0; kk < 8; kk++) {
            float ra[8], rb[8];
#pragma unroll
            for (int i = 0; i < 8; i++) ra[i] = As[kk][ty * 8 + i];
#pragma unroll
            for (int j = 0; j < 8; j++) rb[j] = Bs[kk][tx * 8 + j];
#pragma unroll
            for (int i = 0; i < 8; i++)
#pragma unroll
                for (int j = 0; j < 8; j++) acc[i][j] += ra[i] * rb[j];
        }
        __syncthreads();
    }

#pragma unroll
    for (int i = 0; i < 8; i++) {
        float* crow = C + (size_t)(brow + ty * 8 + i) * N + bcol + tx * 8;
        float4 v0 = make_float4(acc[i][0], acc[i][1], acc[i][2], acc[i][3]);
        float4 v1 = make_float4(acc[i][4], acc[i][5], acc[i][6], acc[i][7]);
        reinterpret_cast<float4*>(crow)[0] = v0;
        reinterpret_cast<float4*>(crow)[1] = v1;
    }
}

// ---------------------------------------------------------------------------
// Block reduce helper
// ---------------------------------------------------------------------------
__device__ __forceinline__ float block_sum_256(float v) {
    __shared__ float red[8];
#pragma unroll
    for (int o = 16; o > 0; o >>= 1) v += __shfl_xor_sync(0xffffffffu, v, o);
    const int lane = threadIdx.x & 31, wid = threadIdx.x >> 5;
    if (lane == 0) red[wid] = v;
    __syncthreads();
    float tot = 0.f;
    if (threadIdx.x < 8) tot = red[threadIdx.x];
#pragma unroll
    for (int o = 4; o > 0; o >>= 1) tot += __shfl_xor_sync(0xffffffffu, tot, o);
    return tot;   // valid in threads 0..7 (lane 0 of warp 0 used)
}

// ---------------------------------------------------------------------------
// Q: RMSNorm over full 2048, RoPE per head, transpose to [b,h,s,d]
// grid = M_ blocks, 256 threads
// ---------------------------------------------------------------------------
__global__ __launch_bounds__(256) void q_norm_rope(
    const float* __restrict__ qraw, const float* __restrict__ qw,
    const float* __restrict__ cosb, const float* __restrict__ sinb,
    float* __restrict__ qh)
{
    const int r = blockIdx.x;
    const int b = r >> 10, s = r & 1023;
    const float* row = qraw + (size_t)r * 2048;

    float ss = 0.f;
    for (int d = threadIdx.x; d < 2048; d += 256) { float x = row[d]; ss += x * x; }
    float tot = block_sum_256(ss);
    __shared__ float s_inv;
    if (threadIdx.x == 0) s_inv = rsqrtf(tot * (1.f / 2048.f) + 1e-6f);
    __syncthreads();
    const float inv = s_inv;

    const float* cs = cosb + (size_t)r * 64;
    const float* sn = sinb + (size_t)r * 64;

    for (int d = threadIdx.x; d < 2048; d += 256) {
        const int hd = d & 63, h = d >> 6;
        float val = row[d] * inv * qw[d];
        const int pd = (hd < 32) ? d + 32 : d - 32;
        float pv = row[pd] * inv * qw[pd];
        float rot = (hd < 32) ? -pv : pv;
        float o = val * cs[hd] + rot * sn[hd];
        qh[(((size_t)(b * NH_ + h)) * S_ + s) * 64 + hd] = o;
    }
}

// ---------------------------------------------------------------------------
// K: RMSNorm over 512, RoPE, transpose; V: transpose only. grid = M_ blocks.
// ---------------------------------------------------------------------------
__global__ __launch_bounds__(256) void kv_norm_rope(
    const float* __restrict__ kraw, const float* __restrict__ vraw,
    const float* __restrict__ kw,
    const float* __restrict__ cosb, const float* __restrict__ sinb,
    float* __restrict__ kh, float* __restrict__ vh)
{
    const int r = blockIdx.x;
    const int b = r >> 10, s = r & 1023;
    const float* row = kraw + (size_t)r * 512;

    float ss = 0.f;
    for (int d = threadIdx.x; d < 512; d += 256) { float x = row[d]; ss += x * x; }
    float tot = block_sum_256(ss);
    __shared__ float s_inv;
    if (threadIdx.x == 0) s_inv = rsqrtf(tot * (1.f / 512.f) + 1e-6f);
    __syncthreads();
    const float inv = s_inv;

    const float* cs = cosb + (size_t)r * 64;
    const float* sn = sinb + (size_t)r * 64;

    for (int d = threadIdx.x; d < 512; d += 256) {
        const int hd = d & 63, h = d >> 6;
        float val = row[d] * inv * kw[d];
        const int pd = (hd < 32) ? d + 32 : d - 32;
        float pv = row[pd] * inv * kw[pd];
        float rot = (hd < 32) ? -pv : pv;
        float o = val * cs[hd] + rot * sn[hd];
        const size_t oi = (((size_t)(b * NKV_ + h)) * S_ + s) * 64 + hd;
        kh[oi] = o;
        vh[oi] = vraw[(size_t)r * 512 + d];
    }
}

// ---------------------------------------------------------------------------
// Flash attention (causal). Block: 64 queries, 64 threads (thread-per-row).
// K/V tiles of 32 rows. Probabilities staged in SMEM to avoid register-
// indexed arrays. Writes ctx[b,s, h*64+d].
// ---------------------------------------------------------------------------
__global__ __launch_bounds__(64) void flash_kernel(
    const float* __restrict__ qh, const float* __restrict__ kh,
    const float* __restrict__ vh, float* __restrict__ ctx)
{
    __shared__ float qT[64 * 64];   // swizzled [d][row]
    __shared__ float ksh[32 * 64];  // [j][d]
    __shared__ float vsh[32 * 64];  // [j][d]
    __shared__ float psh[32 * 64];  // [j][t]

    const int t = threadIdx.x;
    const int qt = blockIdx.x;       // 0..15 (64-query tile)
    const int h = blockIdx.y;        // 0..31
    const int b = blockIdx.z;        // 0..1
    const int hk = h >> 2;           // GQA group of 4

    const float* qbase = qh + (((size_t)(b * NH_ + h)) * S_ + qt * 64) * 64;
    // Load q transposed with XOR swizzle: qT[(d<<6) | (row ^ (d&31))]
    for (int c = 0; c < 64; c++)
        qT[(t << 6) | (c ^ (t & 31))] = qbase[c * 64 + t];

    float acc[64];
#pragma unroll
    for (int d = 0; d < 64; d++) acc[d] = 0.f;
    float m = -1e30f, l = 0.f;
    const int qg = qt * 64 + t;
    const int nkt = 2 * (qt + 1);

    const float* kbb = kh + (((size_t)(b * NKV_ + hk)) * S_) * 64;
    const float* vbb = vh + (((size_t)(b * NKV_ + hk)) * S_) * 64;

    for (int kt = 0; kt < nkt; kt++) {
        __syncthreads();
        const float* kb = kbb + kt * 32 * 64;
        const float* vb = vbb + kt * 32 * 64;
        for (int i = t; i < 2048; i += 64) { ksh[i] = kb[i]; vsh[i] = vb[i]; }
        __syncthreads();

        const bool diag = (kt >= 2 * qt);

        // scores: j blocked by 8 to amortize qT loads
        for (int j0 = 0; j0 < 32; j0 += 8) {
            float s[8];
#pragma unroll
            for (int jj = 0; jj < 8; jj++) s[jj] = 0.f;
#pragma unroll 8
            for (int d = 0; d < 64; d++) {
                float qv = qT[(d << 6) | (t ^ (d & 31))];
                const float* kp = &ksh[j0 * 64 + d];
#pragma unroll
                for (int jj = 0; jj < 8; jj++) s[jj] += qv * kp[jj * 64];
            }
#pragma unroll
            for (int jj = 0; jj < 8; jj++) {
                float sv = s[jj] * 0.125f;   // HD^-0.5
                if (diag && (kt * 32 + j0 + jj > qg)) sv = -1e30f;
                psh[(j0 + jj) * 64 + t] = sv;
            }
        }

        // online softmax update
        float mt = m;
        for (int j = 0; j < 32; j++) mt = fmaxf(mt, psh[j * 64 + t]);
        float scale = __expf(m - mt);
        m = mt;
        l *= scale;
#pragma unroll
        for (int d = 0; d < 64; d++) acc[d] *= scale;

        float lsum = 0.f;
        for (int j = 0; j < 32; j++) {
            float p = __expf(psh[j * 64 + t] - mt);
            psh[j * 64 + t] = p;
            lsum += p;
        }
        l += lsum;

        // acc += P @ V
        for (int j = 0; j < 32; j++) {
            float p = psh[j * 64 + t];
            const float* vr = &vsh[j * 64];
#pragma unroll
            for (int d = 0; d < 64; d++) acc[d] += p * vr[d];
        }
    }

    // Epilogue: stage into qT (reuse) for coalesced global writes
    __syncthreads();
    const float invl = 1.f / l;
#pragma unroll
    for (int d = 0; d < 64; d++)
        qT[(t << 6) | (d ^ (t & 31))] = acc[d] * invl;
    __syncthreads();

    float* crow = ctx + ((size_t)(b * S_ + qt * 64)) * (NH_ * HD_) + h * 64;
    for (int c = 0; c < 64; c++)
        crow[(size_t)c * (NH_ * HD_) + t] = qT[(c << 6) | (t ^ (c & 31))];
}

// ---------------------------------------------------------------------------
// Launch
// ---------------------------------------------------------------------------
extern "C" void kernel_launch(void* const* d_in, const int* in_sizes, int n_in,
                              void* d_out, int out_size)
{
    const float* X    = (const float*)d_in[0];  // hidden_states [B,S,H]
    const float* cosb = (const float*)d_in[1];  // [B,S,64]
    const float* sinb = (const float*)d_in[2];  // [B,S,64]
    // d_in[3] attention_mask unused (causal handled analytically; identical result)
    const float* wq = (const float*)d_in[4];
    const float* wk = (const float*)d_in[5];
    const float* wv = (const float*)d_in[6];
    const float* wo = (const float*)d_in[7];
    const float* qw = (const float*)d_in[8];
    const float* kw = (const float*)d_in[9];
    float* out = (float*)d_out;

    float *qraw, *kraw, *vraw, *qh, *kh, *vh, *ctx;
    cudaGetSymbolAddress((void**)&qraw, g_qraw);
    cudaGetSymbolAddress((void**)&kraw, g_kraw);
    cudaGetSymbolAddress((void**)&vraw, g_vraw);
    cudaGetSymbolAddress((void**)&qh,   g_qh);
    cudaGetSymbolAddress((void**)&kh,   g_kh);
    cudaGetSymbolAddress((void**)&vh,   g_vh);
    cudaGetSymbolAddress((void**)&ctx,  g_ctx);

    dim3 gq(2048 / 128, 2048 / 128);   // N=2048 GEMMs
    dim3 gkv(512 / 128, 2048 / 128);   // N=512 GEMMs

    sgemm128<<<gq,  256>>>(X, wq, qraw, M_, 2048, 2048);
    sgemm128<<<gkv, 256>>>(X, wk, kraw, M_, 512, 2048);
    sgemm128<<<gkv, 256>>>(X, wv, vraw, M_, 512, 2048);

    q_norm_rope<<<M_, 256>>>(qraw, qw, cosb, sinb, qh);
    kv_norm_rope<<<M_, 256>>>(kraw, vraw, kw, cosb, sinb, kh, vh);

    flash_kernel<<<dim3(S_ / 64, NH_, B_), 64>>>(qh, kh, vh, ctx);

    sgemm128<<<gq, 256>>>(ctx, wo, out, M_, 2048, 2048);
}

// round 3
// speedup vs baseline: 1.2776x; 1.2776x over previous
#include <cuda_runtime.h>
#include <cuda_bf16.h>
#include <cstdint>

// Problem constants
#define B_  2
#define S_  1024
#define H_  2048
#define NH_ 32
#define NKV_ 8
#define HD_ 64
#define M_  (B_ * S_)          // 2048 rows of (b,s)

// ---------------------------------------------------------------------------
// Scratch (device globals — no allocation allowed in kernel_launch)
// ---------------------------------------------------------------------------
__device__ float g_qraw[M_ * (NH_ * HD_)];   // 2048 x 2048
__device__ float g_kraw[M_ * (NKV_ * HD_)];  // 2048 x 512
__device__ float g_vraw[M_ * (NKV_ * HD_)];  // 2048 x 512
__device__ float g_qh[B_ * NH_ * S_ * HD_];  // [b,h,s,d]
__device__ float g_kh[B_ * NKV_ * S_ * HD_]; // [b,hk,s,d]
__device__ float g_vh[B_ * NKV_ * S_ * HD_]; // [b,hk,s,d]
__device__ float g_ctx[M_ * (NH_ * HD_)];    // [b,s, h*64+d]

// ---------------------------------------------------------------------------
// tf32 helpers
// ---------------------------------------------------------------------------
__device__ __forceinline__ uint32_t f2tf32(float x) {
    uint32_t r;
    asm("cvt.rna.tf32.f32 %0, %1;" : "=r"(r) : "f"(x));
    return r;
}

__device__ __forceinline__ void mma_tf32(
    float& c0, float& c1, float& c2, float& c3,
    uint32_t a0, uint32_t a1, uint32_t a2, uint32_t a3,
    uint32_t b0, uint32_t b1)
{
    asm volatile(
        "mma.sync.aligned.m16n8k8.row.col.f32.tf32.tf32.f32 "
        "{%0,%1,%2,%3}, {%4,%5,%6,%7}, {%8,%9}, {%0,%1,%2,%3};\n"
        : "+f"(c0), "+f"(c1), "+f"(c2), "+f"(c3)
        : "r"(a0), "r"(a1), "r"(a2), "r"(a3), "r"(b0), "r"(b1));
}

// ---------------------------------------------------------------------------
// Split-tf32 GEMM: C[M,N] = A[M,K] @ B[K,N], fp32-accurate via 3-term split.
// 128x128 block tile, BK=8, 256 threads (8 warps; 4x2 warp grid of 32x64).
// Correct m16n8k8 tf32 fragment maps (from CUTLASS SM80_16x8x8_F32TF32TF32F32_TN):
//   A: a0=(m=g,k=t) a1=(m=g+8,k=t) a2=(m=g,k=t+4) a3=(m=g+8,k=t+4)
//   B: b0=(k=t,n=g) b1=(k=t+4,n=g)
//   C: c0,c1=(m=g, n=2t,2t+1); c2,c3=(m=g+8, n=2t,2t+1)
// ---------------------------------------------------------------------------
#define GW 132   // padded smem width (words)

struct GemmSmem {
    uint32_t AH[2][8][GW];  // A^T hi: [k][m]
    uint32_t AL[2][8][GW];  // A^T lo
    uint32_t BH[2][8][GW];  // B hi:   [k][n]
    uint32_t BL[2][8][GW];  // B lo
};

__device__ __forceinline__ void gemm_body(
    const float* __restrict__ A, const float* __restrict__ Bm,
    float* __restrict__ C, int N, int K, int brow, int bcol)
{
    __shared__ GemmSmem sm;

    const int tid  = threadIdx.x;
    const int lane = tid & 31;
    const int warp = tid >> 5;
    const int gid  = lane >> 2;       // 0..7
    const int tig  = lane & 3;        // 0..3
    const int wm   = (warp & 3) * 32; // warp m offset
    const int wn   = (warp >> 2) * 64;// warp n offset

    // A stage mapping: thread -> (row = tid>>1 in 0..127, kq = (tid&1)*4)
    const int a_row = tid >> 1;
    const int a_kq  = (tid & 1) * 4;
    // B stage mapping: thread -> (k = warp in 0..7, n4 = lane*4)
    const int b_k  = warp;
    const int b_n4 = lane * 4;

    const float* Ag = A + (size_t)(brow + a_row) * K + a_kq;
    const float* Bg = Bm + (size_t)b_k * N + bcol + b_n4;

    float c[2][8][4];
#pragma unroll
    for (int i = 0; i < 2; i++)
#pragma unroll
        for (int j = 0; j < 8; j++)
#pragma unroll
            for (int v = 0; v < 4; v++) c[i][j][v] = 0.f;

    const int NK = K >> 3;

    auto stage_store = [&](int buf, float4 av, float4 bv) {
        float af[4] = {av.x, av.y, av.z, av.w};
#pragma unroll
        for (int i = 0; i < 4; i++) {
            uint32_t hi = f2tf32(af[i]);
            float lof = af[i] - __uint_as_float(hi);
            sm.AH[buf][a_kq + i][a_row] = hi;
            sm.AL[buf][a_kq + i][a_row] = f2tf32(lof);
        }
        float bf[4] = {bv.x, bv.y, bv.z, bv.w};
        uint32_t bh[4], bl[4];
#pragma unroll
        for (int i = 0; i < 4; i++) {
            bh[i] = f2tf32(bf[i]);
            float lof = bf[i] - __uint_as_float(bh[i]);
            bl[i] = f2tf32(lof);
        }
        *reinterpret_cast<uint4*>(&sm.BH[buf][b_k][b_n4]) =
            make_uint4(bh[0], bh[1], bh[2], bh[3]);
        *reinterpret_cast<uint4*>(&sm.BL[buf][b_k][b_n4]) =
            make_uint4(bl[0], bl[1], bl[2], bl[3]);
    };

    // prologue: stage 0
    {
        float4 av = *reinterpret_cast<const float4*>(Ag);
        float4 bv = *reinterpret_cast<const float4*>(Bg);
        stage_store(0, av, bv);
    }
    __syncthreads();

    for (int ks = 0; ks < NK; ks++) {
        const int buf = ks & 1;
        float4 av, bv;
        const bool more = (ks + 1 < NK);
        if (more) {
            av = *reinterpret_cast<const float4*>(Ag + (size_t)(ks + 1) * 8);
            bv = *reinterpret_cast<const float4*>(Bg + (size_t)(ks + 1) * 8 * N);
        }

        // fragment loads — CORRECT tf32 m16n8k8 maps
        uint32_t ah[2][4], al[2][4];
#pragma unroll
        for (int mt = 0; mt < 2; mt++) {
            const int m0 = wm + mt * 16 + gid;
            ah[mt][0] = sm.AH[buf][tig][m0];          // (m=g,   k=t)
            ah[mt][1] = sm.AH[buf][tig][m0 + 8];      // (m=g+8, k=t)
            ah[mt][2] = sm.AH[buf][tig + 4][m0];      // (m=g,   k=t+4)
            ah[mt][3] = sm.AH[buf][tig + 4][m0 + 8];  // (m=g+8, k=t+4)
            al[mt][0] = sm.AL[buf][tig][m0];
            al[mt][1] = sm.AL[buf][tig][m0 + 8];
            al[mt][2] = sm.AL[buf][tig + 4][m0];
            al[mt][3] = sm.AL[buf][tig + 4][m0 + 8];
        }
#pragma unroll
        for (int nt = 0; nt < 8; nt++) {
            const int n0 = wn + nt * 8 + gid;
            uint32_t bh0 = sm.BH[buf][tig][n0];       // (k=t,   n=g)
            uint32_t bh1 = sm.BH[buf][tig + 4][n0];   // (k=t+4, n=g)
            uint32_t bl0 = sm.BL[buf][tig][n0];
            uint32_t bl1 = sm.BL[buf][tig + 4][n0];
#pragma unroll
            for (int mt = 0; mt < 2; mt++) {
                float* cc = c[mt][nt];
                mma_tf32(cc[0], cc[1], cc[2], cc[3],
                         ah[mt][0], ah[mt][1], ah[mt][2], ah[mt][3], bh0, bh1);
                mma_tf32(cc[0], cc[1], cc[2], cc[3],
                         ah[mt][0], ah[mt][1], ah[mt][2], ah[mt][3], bl0, bl1);
                mma_tf32(cc[0], cc[1], cc[2], cc[3],
                         al[mt][0], al[mt][1], al[mt][2], al[mt][3], bh0, bh1);
            }
        }

        if (more) stage_store(buf ^ 1, av, bv);
        __syncthreads();
    }

    // epilogue
#pragma unroll
    for (int mt = 0; mt < 2; mt++) {
#pragma unroll
        for (int nt = 0; nt < 8; nt++) {
            const int row = brow + wm + mt * 16 + gid;
            const int col = bcol + wn + nt * 8 + 2 * tig;
            float* cc = c[mt][nt];
            *reinterpret_cast<float2*>(C + (size_t)row * N + col) =
                make_float2(cc[0], cc[1]);
            *reinterpret_cast<float2*>(C + (size_t)(row + 8) * N + col) =
                make_float2(cc[2], cc[3]);
        }
    }
}

__global__ __launch_bounds__(256) void gemm_tf32(
    const float* __restrict__ A, const float* __restrict__ Bm,
    float* __restrict__ C, int N, int K)
{
    gemm_body(A, Bm, C, N, K, blockIdx.y * 128, blockIdx.x * 128);
}

// Fused wk/wv GEMM: blockIdx.x 0..3 -> K proj, 4..7 -> V proj (N=512 each).
__global__ __launch_bounds__(256) void gemm_tf32_kv(
    const float* __restrict__ A,
    const float* __restrict__ Wk, const float* __restrict__ Wv,
    float* __restrict__ Ck, float* __restrict__ Cv, int K)
{
    const bool isv = blockIdx.x >= 4;
    const float* Bm = isv ? Wv : Wk;
    float* C = isv ? Cv : Ck;
    const int bx = isv ? (blockIdx.x - 4) : blockIdx.x;
    gemm_body(A, Bm, C, 512, K, blockIdx.y * 128, bx * 128);
}

// ---------------------------------------------------------------------------
// Block reduce helper
// ---------------------------------------------------------------------------
__device__ __forceinline__ float block_sum_256(float v) {
    __shared__ float red[8];
#pragma unroll
    for (int o = 16; o > 0; o >>= 1) v += __shfl_xor_sync(0xffffffffu, v, o);
    const int lane = threadIdx.x & 31, wid = threadIdx.x >> 5;
    if (lane == 0) red[wid] = v;
    __syncthreads();
    float tot = 0.f;
    if (threadIdx.x < 8) tot = red[threadIdx.x];
#pragma unroll
    for (int o = 4; o > 0; o >>= 1) tot += __shfl_xor_sync(0xffffffffu, tot, o);
    return tot;
}

// ---------------------------------------------------------------------------
// Q: RMSNorm over full 2048, RoPE per head, transpose to [b,h,s,d]
// ---------------------------------------------------------------------------
__global__ __launch_bounds__(256) void q_norm_rope(
    const float* __restrict__ qraw, const float* __restrict__ qw,
    const float* __restrict__ cosb, const float* __restrict__ sinb,
    float* __restrict__ qh)
{
    const int r = blockIdx.x;
    const int b = r >> 10, s = r & 1023;
    const float* row = qraw + (size_t)r * 2048;

    float ss = 0.f;
    for (int d = threadIdx.x; d < 2048; d += 256) { float x = row[d]; ss += x * x; }
    float tot = block_sum_256(ss);
    __shared__ float s_inv;
    if (threadIdx.x == 0) s_inv = rsqrtf(tot * (1.f / 2048.f) + 1e-6f);
    __syncthreads();
    const float inv = s_inv;

    const float* cs = cosb + (size_t)r * 64;
    const float* sn = sinb + (size_t)r * 64;

    for (int d = threadIdx.x; d < 2048; d += 256) {
        const int hd = d & 63, h = d >> 6;
        float val = row[d] * inv * qw[d];
        const int pd = (hd < 32) ? d + 32 : d - 32;
        float pv = row[pd] * inv * qw[pd];
        float rot = (hd < 32) ? -pv : pv;
        float o = val * cs[hd] + rot * sn[hd];
        qh[(((size_t)(b * NH_ + h)) * S_ + s) * 64 + hd] = o;
    }
}

// ---------------------------------------------------------------------------
// K: RMSNorm over 512, RoPE, transpose; V: transpose only.
// ---------------------------------------------------------------------------
__global__ __launch_bounds__(256) void kv_norm_rope(
    const float* __restrict__ kraw, const float* __restrict__ vraw,
    const float* __restrict__ kw,
    const float* __restrict__ cosb, const float* __restrict__ sinb,
    float* __restrict__ kh, float* __restrict__ vh)
{
    const int r = blockIdx.x;
    const int b = r >> 10, s = r & 1023;
    const float* row = kraw + (size_t)r * 512;

    float ss = 0.f;
    for (int d = threadIdx.x; d < 512; d += 256) { float x = row[d]; ss += x * x; }
    float tot = block_sum_256(ss);
    __shared__ float s_inv;
    if (threadIdx.x == 0) s_inv = rsqrtf(tot * (1.f / 512.f) + 1e-6f);
    __syncthreads();
    const float inv = s_inv;

    const float* cs = cosb + (size_t)r * 64;
    const float* sn = sinb + (size_t)r * 64;

    for (int d = threadIdx.x; d < 512; d += 256) {
        const int hd = d & 63, h = d >> 6;
        float val = row[d] * inv * kw[d];
        const int pd = (hd < 32) ? d + 32 : d - 32;
        float pv = row[pd] * inv * kw[pd];
        float rot = (hd < 32) ? -pv : pv;
        float o = val * cs[hd] + rot * sn[hd];
        const size_t oi = (((size_t)(b * NKV_ + h)) * S_ + s) * 64 + hd;
        kh[oi] = o;
        vh[oi] = vraw[(size_t)r * 512 + d];
    }
}

// ---------------------------------------------------------------------------
// Flash attention (causal). Block: 64 queries, 64 threads (thread-per-row).
// (unchanged — proven correct; rewrite is next round's lever)
// ---------------------------------------------------------------------------
__global__ __launch_bounds__(64) void flash_kernel(
    const float* __restrict__ qh, const float* __restrict__ kh,
    const float* __restrict__ vh, float* __restrict__ ctx)
{
    __shared__ float qT[64 * 64];   // swizzled [d][row]
    __shared__ float ksh[32 * 64];  // [j][d]
    __shared__ float vsh[32 * 64];  // [j][d]
    __shared__ float psh[32 * 64];  // [j][t]

    const int t = threadIdx.x;
    const int qt = blockIdx.x;
    const int h = blockIdx.y;
    const int b = blockIdx.z;
    const int hk = h >> 2;

    const float* qbase = qh + (((size_t)(b * NH_ + h)) * S_ + qt * 64) * 64;
    for (int c = 0; c < 64; c++)
        qT[(t << 6) | (c ^ (t & 31))] = qbase[c * 64 + t];

    float acc[64];
#pragma unroll
    for (int d = 0; d < 64; d++) acc[d] = 0.f;
    float m = -1e30f, l = 0.f;
    const int qg = qt * 64 + t;
    const int nkt = 2 * (qt + 1);

    const float* kbb = kh + (((size_t)(b * NKV_ + hk)) * S_) * 64;
    const float* vbb = vh + (((size_t)(b * NKV_ + hk)) * S_) * 64;

    for (int kt = 0; kt < nkt; kt++) {
        __syncthreads();
        const float* kb = kbb + kt * 32 * 64;
        const float* vb = vbb + kt * 32 * 64;
        for (int i = t; i < 2048; i += 64) { ksh[i] = kb[i]; vsh[i] = vb[i]; }
        __syncthreads();

        const bool diag = (kt >= 2 * qt);

        for (int j0 = 0; j0 < 32; j0 += 8) {
            float s[8];
#pragma unroll
            for (int jj = 0; jj < 8; jj++) s[jj] = 0.f;
#pragma unroll 8
            for (int d = 0; d < 64; d++) {
                float qv = qT[(d << 6) | (t ^ (d & 31))];
                const float* kp = &ksh[j0 * 64 + d];
#pragma unroll
                for (int jj = 0; jj < 8; jj++) s[jj] += qv * kp[jj * 64];
            }
#pragma unroll
            for (int jj = 0; jj < 8; jj++) {
                float sv = s[jj] * 0.125f;
                if (diag && (kt * 32 + j0 + jj > qg)) sv = -1e30f;
                psh[(j0 + jj) * 64 + t] = sv;
            }
        }

        float mt = m;
        for (int j = 0; j < 32; j++) mt = fmaxf(mt, psh[j * 64 + t]);
        float scale = __expf(m - mt);
        m = mt;
        l *= scale;
#pragma unroll
        for (int d = 0; d < 64; d++) acc[d] *= scale;

        float lsum = 0.f;
        for (int j = 0; j < 32; j++) {
            float p = __expf(psh[j * 64 + t] - mt);
            psh[j * 64 + t] = p;
            lsum += p;
        }
        l += lsum;

        for (int j = 0; j < 32; j++) {
            float p = psh[j * 64 + t];
            const float* vr = &vsh[j * 64];
#pragma unroll
            for (int d = 0; d < 64; d++) acc[d] += p * vr[d];
        }
    }

    __syncthreads();
    const float invl = 1.f / l;
#pragma unroll
    for (int d = 0; d < 64; d++)
        qT[(t << 6) | (d ^ (t & 31))] = acc[d] * invl;
    __syncthreads();

    float* crow = ctx + ((size_t)(b * S_ + qt * 64)) * (NH_ * HD_) + h * 64;
    for (int c = 0; c < 64; c++)
        crow[(size_t)c * (NH_ * HD_) + t] = qT[(c << 6) | (t ^ (c & 31))];
}

// ---------------------------------------------------------------------------
// Launch
// ---------------------------------------------------------------------------
extern "C" void kernel_launch(void* const* d_in, const int* in_sizes, int n_in,
                              void* d_out, int out_size)
{
    const float* X    = (const float*)d_in[0];
    const float* cosb = (const float*)d_in[1];
    const float* sinb = (const float*)d_in[2];
    // d_in[3] attention_mask unused (causal handled analytically)
    const float* wq = (const float*)d_in[4];
    const float* wk = (const float*)d_in[5];
    const float* wv = (const float*)d_in[6];
    const float* wo = (const float*)d_in[7];
    const float* qw = (const float*)d_in[8];
    const float* kw = (const float*)d_in[9];
    float* out = (float*)d_out;

    float *qraw, *kraw, *vraw, *qh, *kh, *vh, *ctx;
    cudaGetSymbolAddress((void**)&qraw, g_qraw);
    cudaGetSymbolAddress((void**)&kraw, g_kraw);
    cudaGetSymbolAddress((void**)&vraw, g_vraw);
    cudaGetSymbolAddress((void**)&qh,   g_qh);
    cudaGetSymbolAddress((void**)&kh,   g_kh);
    cudaGetSymbolAddress((void**)&vh,   g_vh);
    cudaGetSymbolAddress((void**)&ctx,  g_ctx);

    dim3 gq(16, 16);   // N=2048 GEMMs
    dim3 gkv(8, 16);   // fused wk+wv (N=512 each)

    gemm_tf32<<<gq, 256>>>(X, wq, qraw, 2048, 2048);
    gemm_tf32_kv<<<gkv, 256>>>(X, wk, wv, kraw, vraw, 2048);

    q_norm_rope<<<M_, 256>>>(qraw, qw, cosb, sinb, qh);
    kv_norm_rope<<<M_, 256>>>(kraw, vraw, kw, cosb, sinb, kh, vh);

    flash_kernel<<<dim3(S_ / 64, NH_, B_), 64>>>(qh, kh, vh, ctx);

    gemm_tf32<<<gq, 256>>>(ctx, wo, out, 2048, 2048);
}

// round 5
// speedup vs baseline: 1.6014x; 1.2535x over previous
#include <cuda_runtime.h>
#include <cuda_bf16.h>
#include <cstdint>

// Problem constants
#define B_  2
#define S_  1024
#define H_  2048
#define NH_ 32
#define NKV_ 8
#define HD_ 64
#define M_  2048

// ---------------------------------------------------------------------------
// Scratch (device globals)
// ---------------------------------------------------------------------------
__device__ float g_qraw[M_ * 2048];
__device__ float g_kraw[M_ * 512];
__device__ float g_vraw[M_ * 512];
__device__ float g_ctx[M_ * 2048];
// flash operand planes (tf32 split)
__device__ float g_qhH[M_ * 2048], g_qhL[M_ * 2048];    // [b,h,s,d]
__device__ float g_kTH[M_ * 512],  g_kTL[M_ * 512];     // [b,hk,d,s]  (transposed!)
__device__ float g_vH [M_ * 512],  g_vL [M_ * 512];     // [b,hk,s,d]

// ---------------------------------------------------------------------------
// tf32 helpers
// ---------------------------------------------------------------------------
__device__ __forceinline__ uint32_t f2tf32(float x) {
    uint32_t r;
    asm("cvt.rna.tf32.f32 %0, %1;" : "=r"(r) : "f"(x));
    return r;
}

__device__ __forceinline__ void mma_tf32(
    float& c0, float& c1, float& c2, float& c3,
    uint32_t a0, uint32_t a1, uint32_t a2, uint32_t a3,
    uint32_t b0, uint32_t b1)
{
    asm volatile(
        "mma.sync.aligned.m16n8k8.row.col.f32.tf32.tf32.f32 "
        "{%0,%1,%2,%3}, {%4,%5,%6,%7}, {%8,%9}, {%0,%1,%2,%3};\n"
        : "+f"(c0), "+f"(c1), "+f"(c2), "+f"(c3)
        : "r"(a0), "r"(a1), "r"(a2), "r"(a3), "r"(b0), "r"(b1));
}

__device__ __forceinline__ void cp16(uint32_t dst, const void* src) {
    asm volatile("cp.async.cg.shared.global [%0], [%1], 16;" :: "r"(dst), "l"(src));
}

// ---------------------------------------------------------------------------
// Split-tf32 GEMM (R3, proven): C[M,N] = A[M,K] @ B[K,N]
// ---------------------------------------------------------------------------
#define GW 132

struct GemmSmem {
    uint32_t AH[2][8][GW];
    uint32_t AL[2][8][GW];
    uint32_t BH[2][8][GW];
    uint32_t BL[2][8][GW];
};

__device__ __forceinline__ void gemm_body(
    const float* __restrict__ A, const float* __restrict__ Bm,
    float* __restrict__ C, int N, int K, int brow, int bcol)
{
    __shared__ GemmSmem sm;

    const int tid  = threadIdx.x;
    const int lane = tid & 31;
    const int warp = tid >> 5;
    const int gid  = lane >> 2;
    const int tig  = lane & 3;
    const int wm   = (warp & 3) * 32;
    const int wn   = (warp >> 2) * 64;

    const int a_row = tid >> 1;
    const int a_kq  = (tid & 1) * 4;
    const int b_k  = warp;
    const int b_n4 = lane * 4;

    const float* Ag = A + (size_t)(brow + a_row) * K + a_kq;
    const float* Bg = Bm + (size_t)b_k * N + bcol + b_n4;

    float c[2][8][4];
#pragma unroll
    for (int i = 0; i < 2; i++)
#pragma unroll
        for (int j = 0; j < 8; j++)
#pragma unroll
            for (int v = 0; v < 4; v++) c[i][j][v] = 0.f;

    const int NK = K >> 3;

    auto stage_store = [&](int buf, float4 av, float4 bv) {
        float af[4] = {av.x, av.y, av.z, av.w};
#pragma unroll
        for (int i = 0; i < 4; i++) {
            uint32_t hi = f2tf32(af[i]);
            float lof = af[i] - __uint_as_float(hi);
            sm.AH[buf][a_kq + i][a_row] = hi;
            sm.AL[buf][a_kq + i][a_row] = f2tf32(lof);
        }
        float bf[4] = {bv.x, bv.y, bv.z, bv.w};
        uint32_t bh[4], bl[4];
#pragma unroll
        for (int i = 0; i < 4; i++) {
            bh[i] = f2tf32(bf[i]);
            float lof = bf[i] - __uint_as_float(bh[i]);
            bl[i] = f2tf32(lof);
        }
        *reinterpret_cast<uint4*>(&sm.BH[buf][b_k][b_n4]) =
            make_uint4(bh[0], bh[1], bh[2], bh[3]);
        *reinterpret_cast<uint4*>(&sm.BL[buf][b_k][b_n4]) =
            make_uint4(bl[0], bl[1], bl[2], bl[3]);
    };

    {
        float4 av = *reinterpret_cast<const float4*>(Ag);
        float4 bv = *reinterpret_cast<const float4*>(Bg);
        stage_store(0, av, bv);
    }
    __syncthreads();

    for (int ks = 0; ks < NK; ks++) {
        const int buf = ks & 1;
        float4 av, bv;
        const bool more = (ks + 1 < NK);
        if (more) {
            av = *reinterpret_cast<const float4*>(Ag + (size_t)(ks + 1) * 8);
            bv = *reinterpret_cast<const float4*>(Bg + (size_t)(ks + 1) * 8 * N);
        }

        uint32_t ah[2][4], al[2][4];
#pragma unroll
        for (int mt = 0; mt < 2; mt++) {
            const int m0 = wm + mt * 16 + gid;
            ah[mt][0] = sm.AH[buf][tig][m0];
            ah[mt][1] = sm.AH[buf][tig][m0 + 8];
            ah[mt][2] = sm.AH[buf][tig + 4][m0];
            ah[mt][3] = sm.AH[buf][tig + 4][m0 + 8];
            al[mt][0] = sm.AL[buf][tig][m0];
            al[mt][1] = sm.AL[buf][tig][m0 + 8];
            al[mt][2] = sm.AL[buf][tig + 4][m0];
            al[mt][3] = sm.AL[buf][tig + 4][m0 + 8];
        }
#pragma unroll
        for (int nt = 0; nt < 8; nt++) {
            const int n0 = wn + nt * 8 + gid;
            uint32_t bh0 = sm.BH[buf][tig][n0];
            uint32_t bh1 = sm.BH[buf][tig + 4][n0];
            uint32_t bl0 = sm.BL[buf][tig][n0];
            uint32_t bl1 = sm.BL[buf][tig + 4][n0];
#pragma unroll
            for (int mt = 0; mt < 2; mt++) {
                float* cc = c[mt][nt];
                mma_tf32(cc[0], cc[1], cc[2], cc[3],
                         ah[mt][0], ah[mt][1], ah[mt][2], ah[mt][3], bh0, bh1);
                mma_tf32(cc[0], cc[1], cc[2], cc[3],
                         ah[mt][0], ah[mt][1], ah[mt][2], ah[mt][3], bl0, bl1);
                mma_tf32(cc[0], cc[1], cc[2], cc[3],
                         al[mt][0], al[mt][1], al[mt][2], al[mt][3], bh0, bh1);
            }
        }

        if (more) stage_store(buf ^ 1, av, bv);
        __syncthreads();
    }

#pragma unroll
    for (int mt = 0; mt < 2; mt++) {
#pragma unroll
        for (int nt = 0; nt < 8; nt++) {
            const int row = brow + wm + mt * 16 + gid;
            const int col = bcol + wn + nt * 8 + 2 * tig;
            float* cc = c[mt][nt];
            *reinterpret_cast<float2*>(C + (size_t)row * N + col) =
                make_float2(cc[0], cc[1]);
            *reinterpret_cast<float2*>(C + (size_t)(row + 8) * N + col) =
                make_float2(cc[2], cc[3]);
        }
    }
}

__global__ __launch_bounds__(256) void gemm_tf32(
    const float* __restrict__ A, const float* __restrict__ Bm,
    float* __restrict__ C, int N, int K)
{
    gemm_body(A, Bm, C, N, K, blockIdx.y * 128, blockIdx.x * 128);
}

__global__ __launch_bounds__(256) void gemm_tf32_kv(
    const float* __restrict__ A,
    const float* __restrict__ Wk, const float* __restrict__ Wv,
    float* __restrict__ Ck, float* __restrict__ Cv, int K)
{
    const bool isv = blockIdx.x >= 4;
    const float* Bm = isv ? Wv : Wk;
    float* C = isv ? Cv : Ck;
    const int bx = isv ? (blockIdx.x - 4) : blockIdx.x;
    gemm_body(A, Bm, C, 512, K, blockIdx.y * 128, bx * 128);
}

// ---------------------------------------------------------------------------
// Block reduce helper
// ---------------------------------------------------------------------------
__device__ __forceinline__ float block_sum_256(float v) {
    __shared__ float red[8];
#pragma unroll
    for (int o = 16; o > 0; o >>= 1) v += __shfl_xor_sync(0xffffffffu, v, o);
    const int lane = threadIdx.x & 31, wid = threadIdx.x >> 5;
    if (lane == 0) red[wid] = v;
    __syncthreads();
    float tot = 0.f;
    if (threadIdx.x < 8) tot = red[threadIdx.x];
#pragma unroll
    for (int o = 4; o > 0; o >>= 1) tot += __shfl_xor_sync(0xffffffffu, tot, o);
    return tot;
}

// ---------------------------------------------------------------------------
// Q: RMSNorm(2048) + RoPE -> split tf32 planes [b,h,s,d]
// ---------------------------------------------------------------------------
__global__ __launch_bounds__(256) void q_norm_rope(
    const float* __restrict__ qraw, const float* __restrict__ qw,
    const float* __restrict__ cosb, const float* __restrict__ sinb,
    float* __restrict__ qhH, float* __restrict__ qhL)
{
    const int r = blockIdx.x;
    const int b = r >> 10, s = r & 1023;
    const float* row = qraw + (size_t)r * 2048;

    float ss = 0.f;
    for (int d = threadIdx.x; d < 2048; d += 256) { float x = row[d]; ss += x * x; }
    float tot = block_sum_256(ss);
    __shared__ float s_inv;
    if (threadIdx.x == 0) s_inv = rsqrtf(tot * (1.f / 2048.f) + 1e-6f);
    __syncthreads();
    const float inv = s_inv;

    const float* cs = cosb + (size_t)r * 64;
    const float* sn = sinb + (size_t)r * 64;

    for (int d = threadIdx.x; d < 2048; d += 256) {
        const int hd = d & 63, h = d >> 6;
        float val = row[d] * inv * qw[d];
        const int pd = (hd < 32) ? d + 32 : d - 32;
        float pv = row[pd] * inv * qw[pd];
        float rot = (hd < 32) ? -pv : pv;
        float o = val * cs[hd] + rot * sn[hd];
        uint32_t hb = f2tf32(o);
        float lo = o - __uint_as_float(hb);
        const size_t oi = (((size_t)(b * NH_ + h)) * S_ + s) * 64 + hd;
        qhH[oi] = __uint_as_float(hb);
        qhL[oi] = __uint_as_float(f2tf32(lo));
    }
}

// ---------------------------------------------------------------------------
// K: RMSNorm(512)+RoPE -> TRANSPOSED split planes [b,hk,d,s].
// V: -> split planes [b,hk,s,d].
// ---------------------------------------------------------------------------
__global__ __launch_bounds__(256) void kv_norm_rope(
    const float* __restrict__ kraw, const float* __restrict__ vraw,
    const float* __restrict__ kw,
    const float* __restrict__ cosb, const float* __restrict__ sinb,
    float* __restrict__ kTH, float* __restrict__ kTL,
    float* __restrict__ vH, float* __restrict__ vL)
{
    const int r = blockIdx.x;
    const int b = r >> 10, s = r & 1023;
    const float* row = kraw + (size_t)r * 512;

    float ss = 0.f;
    for (int d = threadIdx.x; d < 512; d += 256) { float x = row[d]; ss += x * x; }
    float tot = block_sum_256(ss);
    __shared__ float s_inv;
    if (threadIdx.x == 0) s_inv = rsqrtf(tot * (1.f / 512.f) + 1e-6f);
    __syncthreads();
    const float inv = s_inv;

    const float* cs = cosb + (size_t)r * 64;
    const float* sn = sinb + (size_t)r * 64;

    for (int d = threadIdx.x; d < 512; d += 256) {
        const int hd = d & 63, h = d >> 6;
        float val = row[d] * inv * kw[d];
        const int pd = (hd < 32) ? d + 32 : d - 32;
        float pv = row[pd] * inv * kw[pd];
        float rot = (hd < 32) ? -pv : pv;
        float o = val * cs[hd] + rot * sn[hd];
        uint32_t hb = f2tf32(o);
        float klo = o - __uint_as_float(hb);
        // transposed: [b,hk,d,s]
        const size_t ti = (((size_t)(b * NKV_ + h)) * 64 + hd) * S_ + s;
        kTH[ti] = __uint_as_float(hb);
        kTL[ti] = __uint_as_float(f2tf32(klo));
        // v: [b,hk,s,d]
        float v = vraw[(size_t)r * 512 + d];
        uint32_t vhb = f2tf32(v);
        float vlo = v - __uint_as_float(vhb);
        const size_t vi = (((size_t)(b * NKV_ + h)) * S_ + s) * 64 + hd;
        vH[vi] = __uint_as_float(vhb);
        vL[vi] = __uint_as_float(f2tf32(vlo));
    }
}

// ---------------------------------------------------------------------------
// Flash attention on mma.sync tf32 (3-split everywhere).
// 128 threads, 64-query tile; warp w owns rows 16w..16w+15.
// K/V tiles (64 keys) double-buffered via cp.async.
// ---------------------------------------------------------------------------
#define FP 68     // pitch for A-frag smem (P planes)
#define BPP 72    // pitch for B-frag smem (kT, V planes)
#define PLANE_F (64 * BPP)                       // 4608 floats
#define STAGE_F (4 * PLANE_F)                    // 18432 floats
#define STAGE_B (STAGE_F * 4)                    // 73728 bytes
#define FLASH_SMEM (2 * STAGE_B + 2 * 64 * FP * 4)  // 182272 bytes

__global__ __launch_bounds__(128) void flash_mma(
    const float* __restrict__ qhH, const float* __restrict__ qhL,
    const float* __restrict__ kTH, const float* __restrict__ kTL,
    const float* __restrict__ vH,  const float* __restrict__ vL,
    float* __restrict__ ctx)
{
    extern __shared__ float fsm[];
    float* pH = fsm + 2 * STAGE_F;
    float* pL = pH + 64 * FP;

    const int tid = threadIdx.x, lane = tid & 31, warp = tid >> 5;
    const int g = lane >> 2, t = lane & 3;
    const int wm = warp * 16;
    const int qt = blockIdx.x, h = blockIdx.y, b = blockIdx.z, hk = h >> 2;

    uint32_t sbase;
    asm("{ .reg .u64 tt; cvta.to.shared.u64 tt, %1; cvt.u32.u64 %0, tt; }"
        : "=r"(sbase) : "l"(fsm));

    const float* kbH = kTH + ((size_t)(b * NKV_ + hk)) * 64 * S_;
    const float* kbL = kTL + ((size_t)(b * NKV_ + hk)) * 64 * S_;
    const float* vbH = vH + ((size_t)(b * NKV_ + hk)) * S_ * 64;
    const float* vbL = vL + ((size_t)(b * NKV_ + hk)) * S_ * 64;

    // Q fragments in registers for whole kernel
    uint32_t qa_h[8][4], qa_l[8][4];
    {
        const size_t qoff = (((size_t)(b * NH_ + h)) * S_ + qt * 64 + wm) * 64;
        const float* qH = qhH + qoff;
        const float* qL = qhL + qoff;
#pragma unroll
        for (int k = 0; k < 8; k++) {
            qa_h[k][0] = __float_as_uint(qH[g * 64 + 8 * k + t]);
            qa_h[k][1] = __float_as_uint(qH[(g + 8) * 64 + 8 * k + t]);
            qa_h[k][2] = __float_as_uint(qH[g * 64 + 8 * k + t + 4]);
            qa_h[k][3] = __float_as_uint(qH[(g + 8) * 64 + 8 * k + t + 4]);
            qa_l[k][0] = __float_as_uint(qL[g * 64 + 8 * k + t]);
            qa_l[k][1] = __float_as_uint(qL[(g + 8) * 64 + 8 * k + t]);
            qa_l[k][2] = __float_as_uint(qL[g * 64 + 8 * k + t + 4]);
            qa_l[k][3] = __float_as_uint(qL[(g + 8) * 64 + 8 * k + t + 4]);
        }
    }

    float o[8][4];
#pragma unroll
    for (int nt = 0; nt < 8; nt++)
#pragma unroll
        for (int c = 0; c < 4; c++) o[nt][c] = 0.f;
    float m0 = -1e30f, m1 = -1e30f, l0 = 0.f, l1 = 0.f;

    const int ntiles = qt + 1;

    // tile loader: 4096 x 16B chunks over 4 planes
    auto load_tile = [&](int kt) {
        const uint32_t st = sbase + (kt & 1) * STAGE_B;
        const int row8 = tid >> 4;      // 0..7
        const int ch = tid & 15;        // 0..15
#pragma unroll
        for (int i = 0; i < 32; i++) {
            const int plane = i >> 3;
            const int row = (i & 7) * 8 + row8;
            const uint32_t dst = st + plane * (PLANE_F * 4) + row * (BPP * 4) + ch * 16;
            const float* src;
            if (plane == 0)      src = kbH + (size_t)row * S_ + kt * 64 + ch * 4;
            else if (plane == 1) src = kbL + (size_t)row * S_ + kt * 64 + ch * 4;
            else if (plane == 2) src = vbH + (size_t)(kt * 64 + row) * 64 + ch * 4;
            else                 src = vbL + (size_t)(kt * 64 + row) * 64 + ch * 4;
            cp16(dst, src);
        }
    };

    load_tile(0);
    asm volatile("cp.async.commit_group;" ::: "memory");

    for (int kt = 0; kt < ntiles; kt++) {
        if (kt + 1 < ntiles) load_tile(kt + 1);
        asm volatile("cp.async.commit_group;" ::: "memory");
        asm volatile("cp.async.wait_group 1;" ::: "memory");
        __syncthreads();

        const float* kThs = fsm + (kt & 1) * STAGE_F;
        const float* kTls = kThs + PLANE_F;
        const float* vhs  = kThs + 2 * PLANE_F;
        const float* vls  = kThs + 3 * PLANE_F;

        // ---- S = Q K^T (3-split) ----
        float sf[8][4];
#pragma unroll
        for (int nt = 0; nt < 8; nt++)
#pragma unroll
            for (int c = 0; c < 4; c++) sf[nt][c] = 0.f;

#pragma unroll
        for (int nt = 0; nt < 8; nt++) {
#pragma unroll
            for (int k = 0; k < 8; k++) {
                uint32_t bh0 = __float_as_uint(kThs[(8 * k + t) * BPP + 8 * nt + g]);
                uint32_t bh1 = __float_as_uint(kThs[(8 * k + t + 4) * BPP + 8 * nt + g]);
                uint32_t bl0 = __float_as_uint(kTls[(8 * k + t) * BPP + 8 * nt + g]);
                uint32_t bl1 = __float_as_uint(kTls[(8 * k + t + 4) * BPP + 8 * nt + g]);
                float* cc = sf[nt];
                mma_tf32(cc[0], cc[1], cc[2], cc[3],
                         qa_h[k][0], qa_h[k][1], qa_h[k][2], qa_h[k][3], bh0, bh1);
                mma_tf32(cc[0], cc[1], cc[2], cc[3],
                         qa_h[k][0], qa_h[k][1], qa_h[k][2], qa_h[k][3], bl0, bl1);
                mma_tf32(cc[0], cc[1], cc[2], cc[3],
                         qa_l[k][0], qa_l[k][1], qa_l[k][2], qa_l[k][3], bh0, bh1);
            }
        }

        // ---- softmax (online) ----
        const bool diag = (kt == qt);
        float mn0 = m0, mn1 = m1;
#pragma unroll
        for (int nt = 0; nt < 8; nt++) {
#pragma unroll
            for (int c = 0; c < 4; c++) {
                float v = sf[nt][c] * 0.125f;
                const int colloc = nt * 8 + 2 * t + (c & 1);
                const int rowloc = wm + g + ((c >= 2) ? 8 : 0);
                if (diag && colloc > rowloc) v = -1e30f;
                sf[nt][c] = v;
                if (c < 2) mn0 = fmaxf(mn0, v);
                else       mn1 = fmaxf(mn1, v);
            }
        }
        mn0 = fmaxf(mn0, __shfl_xor_sync(0xffffffffu, mn0, 1));
        mn0 = fmaxf(mn0, __shfl_xor_sync(0xffffffffu, mn0, 2));
        mn1 = fmaxf(mn1, __shfl_xor_sync(0xffffffffu, mn1, 1));
        mn1 = fmaxf(mn1, __shfl_xor_sync(0xffffffffu, mn1, 2));

        const float sc0 = __expf(m0 - mn0);
        const float sc1 = __expf(m1 - mn1);
        m0 = mn0; m1 = mn1;
        l0 *= sc0; l1 *= sc1;
#pragma unroll
        for (int nt = 0; nt < 8; nt++) {
            o[nt][0] *= sc0; o[nt][1] *= sc0;
            o[nt][2] *= sc1; o[nt][3] *= sc1;
        }

        float ps0 = 0.f, ps1 = 0.f;
#pragma unroll
        for (int nt = 0; nt < 8; nt++) {
            float p0 = __expf(sf[nt][0] - mn0);
            float p1 = __expf(sf[nt][1] - mn0);
            float p2 = __expf(sf[nt][2] - mn1);
            float p3 = __expf(sf[nt][3] - mn1);
            ps0 += p0 + p1;
            ps1 += p2 + p3;
            uint32_t h0 = f2tf32(p0), h1 = f2tf32(p1), h2 = f2tf32(p2), h3 = f2tf32(p3);
            float e0 = p0 - __uint_as_float(h0), e1 = p1 - __uint_as_float(h1);
            float e2 = p2 - __uint_as_float(h2), e3 = p3 - __uint_as_float(h3);
            const int col = nt * 8 + 2 * t;
            *reinterpret_cast<float2*>(&pH[(wm + g) * FP + col]) =
                make_float2(__uint_as_float(h0), __uint_as_float(h1));
            *reinterpret_cast<float2*>(&pH[(wm + g + 8) * FP + col]) =
                make_float2(__uint_as_float(h2), __uint_as_float(h3));
            *reinterpret_cast<float2*>(&pL[(wm + g) * FP + col]) =
                make_float2(__uint_as_float(f2tf32(e0)), __uint_as_float(f2tf32(e1)));
            *reinterpret_cast<float2*>(&pL[(wm + g + 8) * FP + col]) =
                make_float2(__uint_as_float(f2tf32(e2)), __uint_as_float(f2tf32(e3)));
        }
        ps0 += __shfl_xor_sync(0xffffffffu, ps0, 1);
        ps0 += __shfl_xor_sync(0xffffffffu, ps0, 2);
        ps1 += __shfl_xor_sync(0xffffffffu, ps1, 1);
        ps1 += __shfl_xor_sync(0xffffffffu, ps1, 2);
        l0 += ps0; l1 += ps1;
        __syncwarp();

        // ---- O += P V (3-split) ----
#pragma unroll
        for (int k = 0; k < 8; k++) {
            uint32_t pa_h[4], pa_l[4];
            pa_h[0] = __float_as_uint(pH[(wm + g) * FP + 8 * k + t]);
            pa_h[1] = __float_as_uint(pH[(wm + g + 8) * FP + 8 * k + t]);
            pa_h[2] = __float_as_uint(pH[(wm + g) * FP + 8 * k + t + 4]);
            pa_h[3] = __float_as_uint(pH[(wm + g + 8) * FP + 8 * k + t + 4]);
            pa_l[0] = __float_as_uint(pL[(wm + g) * FP + 8 * k + t]);
            pa_l[1] = __float_as_uint(pL[(wm + g + 8) * FP + 8 * k + t]);
            pa_l[2] = __float_as_uint(pL[(wm + g) * FP + 8 * k + t + 4]);
            pa_l[3] = __float_as_uint(pL[(wm + g + 8) * FP + 8 * k + t + 4]);
#pragma unroll
            for (int nt = 0; nt < 8; nt++) {
                uint32_t bh0 = __float_as_uint(vhs[(8 * k + t) * BPP + 8 * nt + g]);
                uint32_t bh1 = __float_as_uint(vhs[(8 * k + t + 4) * BPP + 8 * nt + g]);
                uint32_t bl0 = __float_as_uint(vls[(8 * k + t) * BPP + 8 * nt + g]);
                uint32_t bl1 = __float_as_uint(vls[(8 * k + t + 4) * BPP + 8 * nt + g]);
                float* cc = o[nt];
                mma_tf32(cc[0], cc[1], cc[2], cc[3],
                         pa_h[0], pa_h[1], pa_h[2], pa_h[3], bh0, bh1);
                mma_tf32(cc[0], cc[1], cc[2], cc[3],
                         pa_l[0], pa_l[1], pa_l[2], pa_l[3], bh0, bh1);
                mma_tf32(cc[0], cc[1], cc[2], cc[3],
                         pa_h[0], pa_h[1], pa_h[2], pa_h[3], bl0, bl1);
            }
        }
        __syncthreads();   // protect stage from next cp.async overwrite
    }

    // ---- epilogue ----
    const float inv0 = 1.f / l0, inv1 = 1.f / l1;
    float* crow0 = ctx + ((size_t)(b * S_ + qt * 64 + wm + g)) * 2048 + h * 64;
    float* crow1 = crow0 + (size_t)8 * 2048;
#pragma unroll
    for (int nt = 0; nt < 8; nt++) {
        const int col = nt * 8 + 2 * t;
        *reinterpret_cast<float2*>(crow0 + col) =
            make_float2(o[nt][0] * inv0, o[nt][1] * inv0);
        *reinterpret_cast<float2*>(crow1 + col) =
            make_float2(o[nt][2] * inv1, o[nt][3] * inv1);
    }
}

// ---------------------------------------------------------------------------
// Launch
// ---------------------------------------------------------------------------
extern "C" void kernel_launch(void* const* d_in, const int* in_sizes, int n_in,
                              void* d_out, int out_size)
{
    const float* X    = (const float*)d_in[0];
    const float* cosb = (const float*)d_in[1];
    const float* sinb = (const float*)d_in[2];
    // d_in[3] attention_mask unused (causal handled analytically)
    const float* wq = (const float*)d_in[4];
    const float* wk = (const float*)d_in[5];
    const float* wv = (const float*)d_in[6];
    const float* wo = (const float*)d_in[7];
    const float* qw = (const float*)d_in[8];
    const float* kw = (const float*)d_in[9];
    float* out = (float*)d_out;

    float *qraw, *kraw, *vraw, *ctx;
    float *qhH, *qhL, *kTH, *kTL, *vH, *vL;
    cudaGetSymbolAddress((void**)&qraw, g_qraw);
    cudaGetSymbolAddress((void**)&kraw, g_kraw);
    cudaGetSymbolAddress((void**)&vraw, g_vraw);
    cudaGetSymbolAddress((void**)&ctx,  g_ctx);
    cudaGetSymbolAddress((void**)&qhH,  g_qhH);
    cudaGetSymbolAddress((void**)&qhL,  g_qhL);
    cudaGetSymbolAddress((void**)&kTH,  g_kTH);
    cudaGetSymbolAddress((void**)&kTL,  g_kTL);
    cudaGetSymbolAddress((void**)&vH,   g_vH);
    cudaGetSymbolAddress((void**)&vL,   g_vL);

    cudaFuncSetAttribute(flash_mma, cudaFuncAttributeMaxDynamicSharedMemorySize,
                         FLASH_SMEM);

    dim3 gq(16, 16);
    dim3 gkv(8, 16);

    gemm_tf32<<<gq, 256>>>(X, wq, qraw, 2048, 2048);
    gemm_tf32_kv<<<gkv, 256>>>(X, wk, wv, kraw, vraw, 2048);

    q_norm_rope<<<M_, 256>>>(qraw, qw, cosb, sinb, qhH, qhL);
    kv_norm_rope<<<M_, 256>>>(kraw, vraw, kw, cosb, sinb, kTH, kTL, vH, vL);

    flash_mma<<<dim3(16, NH_, B_), 128, FLASH_SMEM>>>(qhH, qhL, kTH, kTL, vH, vL, ctx);

    gemm_tf32<<<gq, 256>>>(ctx, wo, out, 2048, 2048);
}

// round 6
// speedup vs baseline: 2.6944x; 1.6825x over previous
#include <cuda_runtime.h>
#include <cuda_bf16.h>
#include <cstdint>

// Problem constants
#define B_  2
#define S_  1024
#define H_  2048
#define NH_ 32
#define NKV_ 8
#define HD_ 64
#define M_  2048

// ---------------------------------------------------------------------------
// Scratch (device globals)
// ---------------------------------------------------------------------------
__device__ float g_qraw[M_ * 2048];
__device__ float g_kraw[M_ * 512];
__device__ float g_vraw[M_ * 512];
__device__ float g_ctx[M_ * 2048];
// flash operand planes (tf32 split)
__device__ float g_qhH[M_ * 2048], g_qhL[M_ * 2048];    // [b,h,s,d]
__device__ float g_kTH[M_ * 512],  g_kTL[M_ * 512];     // [b,hk,d,s]  (transposed!)
__device__ float g_vH [M_ * 512],  g_vL [M_ * 512];     // [b,hk,s,d]

// ---------------------------------------------------------------------------
// helpers
// ---------------------------------------------------------------------------
__device__ __forceinline__ uint32_t f2tf32(float x) {
    uint32_t r;
    asm("cvt.rna.tf32.f32 %0, %1;" : "=r"(r) : "f"(x));
    return r;
}

__device__ __forceinline__ void mma_tf32(
    float& c0, float& c1, float& c2, float& c3,
    uint32_t a0, uint32_t a1, uint32_t a2, uint32_t a3,
    uint32_t b0, uint32_t b1)
{
    asm volatile(
        "mma.sync.aligned.m16n8k8.row.col.f32.tf32.tf32.f32 "
        "{%0,%1,%2,%3}, {%4,%5,%6,%7}, {%8,%9}, {%0,%1,%2,%3};\n"
        : "+f"(c0), "+f"(c1), "+f"(c2), "+f"(c3)
        : "r"(a0), "r"(a1), "r"(a2), "r"(a3), "r"(b0), "r"(b1));
}

__device__ __forceinline__ void mma_bf16(
    float& c0, float& c1, float& c2, float& c3,
    uint32_t a0, uint32_t a1, uint32_t a2, uint32_t a3,
    uint32_t b0, uint32_t b1)
{
    asm volatile(
        "mma.sync.aligned.m16n8k16.row.col.f32.bf16.bf16.f32 "
        "{%0,%1,%2,%3}, {%4,%5,%6,%7}, {%8,%9}, {%0,%1,%2,%3};\n"
        : "+f"(c0), "+f"(c1), "+f"(c2), "+f"(c3)
        : "r"(a0), "r"(a1), "r"(a2), "r"(a3), "r"(b0), "r"(b1));
}

__device__ __forceinline__ void cp16(uint32_t dst, const void* src) {
    asm volatile("cp.async.cg.shared.global [%0], [%1], 16;" :: "r"(dst), "l"(src));
}

// pack two floats' bf16-hi parts; compute lo remainders
__device__ __forceinline__ uint32_t pack_hi(float x, float y) {
    __nv_bfloat162 h = __floats2bfloat162_rn(x, y);
    return *reinterpret_cast<uint32_t*>(&h);
}
__device__ __forceinline__ uint32_t pack_lo(float x, float y, uint32_t hi) {
    __nv_bfloat162 h = *reinterpret_cast<__nv_bfloat162*>(&hi);
    float lx = x - __bfloat162float(h.x);
    float ly = y - __bfloat162float(h.y);
    __nv_bfloat162 l = __floats2bfloat162_rn(lx, ly);
    return *reinterpret_cast<uint32_t*>(&l);
}

// ---------------------------------------------------------------------------
// Split-bf16 GEMM: C[M,N] = A[M,K] @ B[K,N], 3-term split, m16n8k16.
// 128x128 block tile, BK=16, 256 threads (8 warps; 4x2 warp grid of 32x64).
// Smem planes: [kpair 0..7][m or n], each entry = bf16x2 (k=2kp, 2kp+1).
// ---------------------------------------------------------------------------
#define GW 132

struct GemmSmem {
    uint32_t AH[2][8][GW];
    uint32_t AL[2][8][GW];
    uint32_t BH[2][8][GW];
    uint32_t BL[2][8][GW];
};

__device__ __forceinline__ void gemm_body(
    const float* __restrict__ A, const float* __restrict__ Bm,
    float* __restrict__ C, int N, int K, int brow, int bcol)
{
    __shared__ GemmSmem sm;

    const int tid  = threadIdx.x;
    const int lane = tid & 31;
    const int warp = tid >> 5;
    const int gid  = lane >> 2;
    const int tig  = lane & 3;
    const int wm   = (warp & 3) * 32;
    const int wn   = (warp >> 2) * 64;

    // A staging: row = tid>>1 (0..127), kseg = (tid&1)*8 -> 2 float4 along k
    const int a_row = tid >> 1;
    const int a_kp0 = (tid & 1) * 4;      // first kpair plane this thread fills
    // B staging: kp = tid>>5 (0..7), n0 = lane*4 -> rows 2kp,2kp+1, 4 n's
    const int b_kp = warp;
    const int b_n0 = lane * 4;

    const float* Ag = A + (size_t)(brow + a_row) * K + a_kp0 * 2;
    const float* Bg0 = Bm + (size_t)(2 * b_kp) * N + bcol + b_n0;
    const float* Bg1 = Bg0 + N;

    float c[2][8][4];
#pragma unroll
    for (int i = 0; i < 2; i++)
#pragma unroll
        for (int j = 0; j < 8; j++)
#pragma unroll
            for (int v = 0; v < 4; v++) c[i][j][v] = 0.f;

    const int NK = K >> 4;

    auto stage_store = [&](int buf, float4 a0, float4 a1, float4 bv0, float4 bv1) {
        // A: 8 floats = 4 kpairs
        float af[8] = {a0.x, a0.y, a0.z, a0.w, a1.x, a1.y, a1.z, a1.w};
#pragma unroll
        for (int i = 0; i < 4; i++) {
            uint32_t hi = pack_hi(af[2 * i], af[2 * i + 1]);
            sm.AH[buf][a_kp0 + i][a_row] = hi;
            sm.AL[buf][a_kp0 + i][a_row] = pack_lo(af[2 * i], af[2 * i + 1], hi);
        }
        // B: 4 n's, pack (k=2kp, k=2kp+1)
        float b0f[4] = {bv0.x, bv0.y, bv0.z, bv0.w};
        float b1f[4] = {bv1.x, bv1.y, bv1.z, bv1.w};
        uint32_t bh[4], bl[4];
#pragma unroll
        for (int i = 0; i < 4; i++) {
            bh[i] = pack_hi(b0f[i], b1f[i]);
            bl[i] = pack_lo(b0f[i], b1f[i], bh[i]);
        }
        *reinterpret_cast<uint4*>(&sm.BH[buf][b_kp][b_n0]) =
            make_uint4(bh[0], bh[1], bh[2], bh[3]);
        *reinterpret_cast<uint4*>(&sm.BL[buf][b_kp][b_n0]) =
            make_uint4(bl[0], bl[1], bl[2], bl[3]);
    };

    {
        float4 a0 = *reinterpret_cast<const float4*>(Ag);
        float4 a1 = *reinterpret_cast<const float4*>(Ag + 4);
        float4 bv0 = *reinterpret_cast<const float4*>(Bg0);
        float4 bv1 = *reinterpret_cast<const float4*>(Bg1);
        stage_store(0, a0, a1, bv0, bv1);
    }
    __syncthreads();

    for (int ks = 0; ks < NK; ks++) {
        const int buf = ks & 1;
        float4 a0, a1, bv0, bv1;
        const bool more = (ks + 1 < NK);
        if (more) {
            const float* Agn = Ag + (size_t)(ks + 1) * 16;
            a0 = *reinterpret_cast<const float4*>(Agn);
            a1 = *reinterpret_cast<const float4*>(Agn + 4);
            const size_t boff = (size_t)(ks + 1) * 16 * N;
            bv0 = *reinterpret_cast<const float4*>(Bg0 + boff);
            bv1 = *reinterpret_cast<const float4*>(Bg1 + boff);
        }

        // fragment loads (m16n8k16 bf16 maps; kpair plane index = t / t+4)
        uint32_t ah[2][4], al[2][4];
#pragma unroll
        for (int mt = 0; mt < 2; mt++) {
            const int m0 = wm + mt * 16 + gid;
            ah[mt][0] = sm.AH[buf][tig][m0];          // (m=g,   k=2t:2t+1)
            ah[mt][1] = sm.AH[buf][tig][m0 + 8];      // (m=g+8, k=2t:2t+1)
            ah[mt][2] = sm.AH[buf][tig + 4][m0];      // (m=g,   k=2t+8:2t+9)
            ah[mt][3] = sm.AH[buf][tig + 4][m0 + 8];
            al[mt][0] = sm.AL[buf][tig][m0];
            al[mt][1] = sm.AL[buf][tig][m0 + 8];
            al[mt][2] = sm.AL[buf][tig + 4][m0];
            al[mt][3] = sm.AL[buf][tig + 4][m0 + 8];
        }
#pragma unroll
        for (int nt = 0; nt < 8; nt++) {
            const int n0 = wn + nt * 8 + gid;
            uint32_t bh0 = sm.BH[buf][tig][n0];       // (k=2t:2t+1,   n=g)
            uint32_t bh1 = sm.BH[buf][tig + 4][n0];   // (k=2t+8:2t+9, n=g)
            uint32_t bl0 = sm.BL[buf][tig][n0];
            uint32_t bl1 = sm.BL[buf][tig + 4][n0];
#pragma unroll
            for (int mt = 0; mt < 2; mt++) {
                float* cc = c[mt][nt];
                mma_bf16(cc[0], cc[1], cc[2], cc[3],
                         ah[mt][0], ah[mt][1], ah[mt][2], ah[mt][3], bh0, bh1);
                mma_bf16(cc[0], cc[1], cc[2], cc[3],
                         ah[mt][0], ah[mt][1], ah[mt][2], ah[mt][3], bl0, bl1);
                mma_bf16(cc[0], cc[1], cc[2], cc[3],
                         al[mt][0], al[mt][1], al[mt][2], al[mt][3], bh0, bh1);
            }
        }

        if (more) stage_store(buf ^ 1, a0, a1, bv0, bv1);
        __syncthreads();
    }

#pragma unroll
    for (int mt = 0; mt < 2; mt++) {
#pragma unroll
        for (int nt = 0; nt < 8; nt++) {
            const int row = brow + wm + mt * 16 + gid;
            const int col = bcol + wn + nt * 8 + 2 * tig;
            float* cc = c[mt][nt];
            *reinterpret_cast<float2*>(C + (size_t)row * N + col) =
                make_float2(cc[0], cc[1]);
            *reinterpret_cast<float2*>(C + (size_t)(row + 8) * N + col) =
                make_float2(cc[2], cc[3]);
        }
    }
}

__global__ __launch_bounds__(256) void gemm_bf16(
    const float* __restrict__ A, const float* __restrict__ Bm,
    float* __restrict__ C, int N, int K)
{
    gemm_body(A, Bm, C, N, K, blockIdx.y * 128, blockIdx.x * 128);
}

__global__ __launch_bounds__(256) void gemm_bf16_kv(
    const float* __restrict__ A,
    const float* __restrict__ Wk, const float* __restrict__ Wv,
    float* __restrict__ Ck, float* __restrict__ Cv, int K)
{
    const bool isv = blockIdx.x >= 4;
    const float* Bm = isv ? Wv : Wk;
    float* C = isv ? Cv : Ck;
    const int bx = isv ? (blockIdx.x - 4) : blockIdx.x;
    gemm_body(A, Bm, C, 512, K, blockIdx.y * 128, bx * 128);
}

// ---------------------------------------------------------------------------
// Block reduce helper
// ---------------------------------------------------------------------------
__device__ __forceinline__ float block_sum_256(float v) {
    __shared__ float red[8];
#pragma unroll
    for (int o = 16; o > 0; o >>= 1) v += __shfl_xor_sync(0xffffffffu, v, o);
    const int lane = threadIdx.x & 31, wid = threadIdx.x >> 5;
    if (lane == 0) red[wid] = v;
    __syncthreads();
    float tot = 0.f;
    if (threadIdx.x < 8) tot = red[threadIdx.x];
#pragma unroll
    for (int o = 4; o > 0; o >>= 1) tot += __shfl_xor_sync(0xffffffffu, tot, o);
    return tot;
}

// ---------------------------------------------------------------------------
// Q: RMSNorm(2048) + RoPE -> split tf32 planes [b,h,s,d]
// ---------------------------------------------------------------------------
__global__ __launch_bounds__(256) void q_norm_rope(
    const float* __restrict__ qraw, const float* __restrict__ qw,
    const float* __restrict__ cosb, const float* __restrict__ sinb,
    float* __restrict__ qhH, float* __restrict__ qhL)
{
    const int r = blockIdx.x;
    const int b = r >> 10, s = r & 1023;
    const float* row = qraw + (size_t)r * 2048;

    float ss = 0.f;
    for (int d = threadIdx.x; d < 2048; d += 256) { float x = row[d]; ss += x * x; }
    float tot = block_sum_256(ss);
    __shared__ float s_inv;
    if (threadIdx.x == 0) s_inv = rsqrtf(tot * (1.f / 2048.f) + 1e-6f);
    __syncthreads();
    const float inv = s_inv;

    const float* cs = cosb + (size_t)r * 64;
    const float* sn = sinb + (size_t)r * 64;

    for (int d = threadIdx.x; d < 2048; d += 256) {
        const int hd = d & 63, h = d >> 6;
        float val = row[d] * inv * qw[d];
        const int pd = (hd < 32) ? d + 32 : d - 32;
        float pv = row[pd] * inv * qw[pd];
        float rot = (hd < 32) ? -pv : pv;
        float o = val * cs[hd] + rot * sn[hd];
        uint32_t hb = f2tf32(o);
        float lo = o - __uint_as_float(hb);
        const size_t oi = (((size_t)(b * NH_ + h)) * S_ + s) * 64 + hd;
        qhH[oi] = __uint_as_float(hb);
        qhL[oi] = __uint_as_float(f2tf32(lo));
    }
}

// ---------------------------------------------------------------------------
// K: RMSNorm(512)+RoPE -> TRANSPOSED split planes [b,hk,d,s].
// V: -> split planes [b,hk,s,d].
// ---------------------------------------------------------------------------
__global__ __launch_bounds__(256) void kv_norm_rope(
    const float* __restrict__ kraw, const float* __restrict__ vraw,
    const float* __restrict__ kw,
    const float* __restrict__ cosb, const float* __restrict__ sinb,
    float* __restrict__ kTH, float* __restrict__ kTL,
    float* __restrict__ vH, float* __restrict__ vL)
{
    const int r = blockIdx.x;
    const int b = r >> 10, s = r & 1023;
    const float* row = kraw + (size_t)r * 512;

    float ss = 0.f;
    for (int d = threadIdx.x; d < 512; d += 256) { float x = row[d]; ss += x * x; }
    float tot = block_sum_256(ss);
    __shared__ float s_inv;
    if (threadIdx.x == 0) s_inv = rsqrtf(tot * (1.f / 512.f) + 1e-6f);
    __syncthreads();
    const float inv = s_inv;

    const float* cs = cosb + (size_t)r * 64;
    const float* sn = sinb + (size_t)r * 64;

    for (int d = threadIdx.x; d < 512; d += 256) {
        const int hd = d & 63, h = d >> 6;
        float val = row[d] * inv * kw[d];
        const int pd = (hd < 32) ? d + 32 : d - 32;
        float pv = row[pd] * inv * kw[pd];
        float rot = (hd < 32) ? -pv : pv;
        float o = val * cs[hd] + rot * sn[hd];
        uint32_t hb = f2tf32(o);
        float klo = o - __uint_as_float(hb);
        const size_t ti = (((size_t)(b * NKV_ + h)) * 64 + hd) * S_ + s;
        kTH[ti] = __uint_as_float(hb);
        kTL[ti] = __uint_as_float(f2tf32(klo));
        float v = vraw[(size_t)r * 512 + d];
        uint32_t vhb = f2tf32(v);
        float vlo = v - __uint_as_float(vhb);
        const size_t vi = (((size_t)(b * NKV_ + h)) * S_ + s) * 64 + hd;
        vH[vi] = __uint_as_float(vhb);
        vL[vi] = __uint_as_float(f2tf32(vlo));
    }
}

// ---------------------------------------------------------------------------
// Flash attention on mma.sync tf32 (3-split). Unchanged from R5 (proven).
// ---------------------------------------------------------------------------
#define FP 68
#define BPP 72
#define PLANE_F (64 * BPP)
#define STAGE_F (4 * PLANE_F)
#define STAGE_B (STAGE_F * 4)
#define FLASH_SMEM (2 * STAGE_B + 2 * 64 * FP * 4)

__global__ __launch_bounds__(128) void flash_mma(
    const float* __restrict__ qhH, const float* __restrict__ qhL,
    const float* __restrict__ kTH, const float* __restrict__ kTL,
    const float* __restrict__ vH,  const float* __restrict__ vL,
    float* __restrict__ ctx)
{
    extern __shared__ float fsm[];
    float* pH = fsm + 2 * STAGE_F;
    float* pL = pH + 64 * FP;

    const int tid = threadIdx.x, lane = tid & 31, warp = tid >> 5;
    const int g = lane >> 2, t = lane & 3;
    const int wm = warp * 16;
    const int qt = blockIdx.x, h = blockIdx.y, b = blockIdx.z, hk = h >> 2;

    uint32_t sbase;
    asm("{ .reg .u64 tt; cvta.to.shared.u64 tt, %1; cvt.u32.u64 %0, tt; }"
        : "=r"(sbase) : "l"(fsm));

    const float* kbH = kTH + ((size_t)(b * NKV_ + hk)) * 64 * S_;
    const float* kbL = kTL + ((size_t)(b * NKV_ + hk)) * 64 * S_;
    const float* vbH = vH + ((size_t)(b * NKV_ + hk)) * S_ * 64;
    const float* vbL = vL + ((size_t)(b * NKV_ + hk)) * S_ * 64;

    uint32_t qa_h[8][4], qa_l[8][4];
    {
        const size_t qoff = (((size_t)(b * NH_ + h)) * S_ + qt * 64 + wm) * 64;
        const float* qH = qhH + qoff;
        const float* qL = qhL + qoff;
#pragma unroll
        for (int k = 0; k < 8; k++) {
            qa_h[k][0] = __float_as_uint(qH[g * 64 + 8 * k + t]);
            qa_h[k][1] = __float_as_uint(qH[(g + 8) * 64 + 8 * k + t]);
            qa_h[k][2] = __float_as_uint(qH[g * 64 + 8 * k + t + 4]);
            qa_h[k][3] = __float_as_uint(qH[(g + 8) * 64 + 8 * k + t + 4]);
            qa_l[k][0] = __float_as_uint(qL[g * 64 + 8 * k + t]);
            qa_l[k][1] = __float_as_uint(qL[(g + 8) * 64 + 8 * k + t]);
            qa_l[k][2] = __float_as_uint(qL[g * 64 + 8 * k + t + 4]);
            qa_l[k][3] = __float_as_uint(qL[(g + 8) * 64 + 8 * k + t + 4]);
        }
    }

    float o[8][4];
#pragma unroll
    for (int nt = 0; nt < 8; nt++)
#pragma unroll
        for (int c = 0; c < 4; c++) o[nt][c] = 0.f;
    float m0 = -1e30f, m1 = -1e30f, l0 = 0.f, l1 = 0.f;

    const int ntiles = qt + 1;

    auto load_tile = [&](int kt) {
        const uint32_t st = sbase + (kt & 1) * STAGE_B;
        const int row8 = tid >> 4;
        const int ch = tid & 15;
#pragma unroll
        for (int i = 0; i < 32; i++) {
            const int plane = i >> 3;
            const int row = (i & 7) * 8 + row8;
            const uint32_t dst = st + plane * (PLANE_F * 4) + row * (BPP * 4) + ch * 16;
            const float* src;
            if (plane == 0)      src = kbH + (size_t)row * S_ + kt * 64 + ch * 4;
            else if (plane == 1) src = kbL + (size_t)row * S_ + kt * 64 + ch * 4;
            else if (plane == 2) src = vbH + (size_t)(kt * 64 + row) * 64 + ch * 4;
            else                 src = vbL + (size_t)(kt * 64 + row) * 64 + ch * 4;
            cp16(dst, src);
        }
    };

    load_tile(0);
    asm volatile("cp.async.commit_group;" ::: "memory");

    for (int kt = 0; kt < ntiles; kt++) {
        if (kt + 1 < ntiles) load_tile(kt + 1);
        asm volatile("cp.async.commit_group;" ::: "memory");
        asm volatile("cp.async.wait_group 1;" ::: "memory");
        __syncthreads();

        const float* kThs = fsm + (kt & 1) * STAGE_F;
        const float* kTls = kThs + PLANE_F;
        const float* vhs  = kThs + 2 * PLANE_F;
        const float* vls  = kThs + 3 * PLANE_F;

        float sf[8][4];
#pragma unroll
        for (int nt = 0; nt < 8; nt++)
#pragma unroll
            for (int c = 0; c < 4; c++) sf[nt][c] = 0.f;

#pragma unroll
        for (int nt = 0; nt < 8; nt++) {
#pragma unroll
            for (int k = 0; k < 8; k++) {
                uint32_t bh0 = __float_as_uint(kThs[(8 * k + t) * BPP + 8 * nt + g]);
                uint32_t bh1 = __float_as_uint(kThs[(8 * k + t + 4) * BPP + 8 * nt + g]);
                uint32_t bl0 = __float_as_uint(kTls[(8 * k + t) * BPP + 8 * nt + g]);
                uint32_t bl1 = __float_as_uint(kTls[(8 * k + t + 4) * BPP + 8 * nt + g]);
                float* cc = sf[nt];
                mma_tf32(cc[0], cc[1], cc[2], cc[3],
                         qa_h[k][0], qa_h[k][1], qa_h[k][2], qa_h[k][3], bh0, bh1);
                mma_tf32(cc[0], cc[1], cc[2], cc[3],
                         qa_h[k][0], qa_h[k][1], qa_h[k][2], qa_h[k][3], bl0, bl1);
                mma_tf32(cc[0], cc[1], cc[2], cc[3],
                         qa_l[k][0], qa_l[k][1], qa_l[k][2], qa_l[k][3], bh0, bh1);
            }
        }

        const bool diag = (kt == qt);
        float mn0 = m0, mn1 = m1;
#pragma unroll
        for (int nt = 0; nt < 8; nt++) {
#pragma unroll
            for (int c = 0; c < 4; c++) {
                float v = sf[nt][c] * 0.125f;
                const int colloc = nt * 8 + 2 * t + (c & 1);
                const int rowloc = wm + g + ((c >= 2) ? 8 : 0);
                if (diag && colloc > rowloc) v = -1e30f;
                sf[nt][c] = v;
                if (c < 2) mn0 = fmaxf(mn0, v);
                else       mn1 = fmaxf(mn1, v);
            }
        }
        mn0 = fmaxf(mn0, __shfl_xor_sync(0xffffffffu, mn0, 1));
        mn0 = fmaxf(mn0, __shfl_xor_sync(0xffffffffu, mn0, 2));
        mn1 = fmaxf(mn1, __shfl_xor_sync(0xffffffffu, mn1, 1));
        mn1 = fmaxf(mn1, __shfl_xor_sync(0xffffffffu, mn1, 2));

        const float sc0 = __expf(m0 - mn0);
        const float sc1 = __expf(m1 - mn1);
        m0 = mn0; m1 = mn1;
        l0 *= sc0; l1 *= sc1;
#pragma unroll
        for (int nt = 0; nt < 8; nt++) {
            o[nt][0] *= sc0; o[nt][1] *= sc0;
            o[nt][2] *= sc1; o[nt][3] *= sc1;
        }

        float ps0 = 0.f, ps1 = 0.f;
#pragma unroll
        for (int nt = 0; nt < 8; nt++) {
            float p0 = __expf(sf[nt][0] - mn0);
            float p1 = __expf(sf[nt][1] - mn0);
            float p2 = __expf(sf[nt][2] - mn1);
            float p3 = __expf(sf[nt][3] - mn1);
            ps0 += p0 + p1;
            ps1 += p2 + p3;
            uint32_t h0 = f2tf32(p0), h1 = f2tf32(p1), h2 = f2tf32(p2), h3 = f2tf32(p3);
            float e0 = p0 - __uint_as_float(h0), e1 = p1 - __uint_as_float(h1);
            float e2 = p2 - __uint_as_float(h2), e3 = p3 - __uint_as_float(h3);
            const int col = nt * 8 + 2 * t;
            *reinterpret_cast<float2*>(&pH[(wm + g) * FP + col]) =
                make_float2(__uint_as_float(h0), __uint_as_float(h1));
            *reinterpret_cast<float2*>(&pH[(wm + g + 8) * FP + col]) =
                make_float2(__uint_as_float(h2), __uint_as_float(h3));
            *reinterpret_cast<float2*>(&pL[(wm + g) * FP + col]) =
                make_float2(__uint_as_float(f2tf32(e0)), __uint_as_float(f2tf32(e1)));
            *reinterpret_cast<float2*>(&pL[(wm + g + 8) * FP + col]) =
                make_float2(__uint_as_float(f2tf32(e2)), __uint_as_float(f2tf32(e3)));
        }
        ps0 += __shfl_xor_sync(0xffffffffu, ps0, 1);
        ps0 += __shfl_xor_sync(0xffffffffu, ps0, 2);
        ps1 += __shfl_xor_sync(0xffffffffu, ps1, 1);
        ps1 += __shfl_xor_sync(0xffffffffu, ps1, 2);
        l0 += ps0; l1 += ps1;
        __syncwarp();

#pragma unroll
        for (int k = 0; k < 8; k++) {
            uint32_t pa_h[4], pa_l[4];
            pa_h[0] = __float_as_uint(pH[(wm + g) * FP + 8 * k + t]);
            pa_h[1] = __float_as_uint(pH[(wm + g + 8) * FP + 8 * k + t]);
            pa_h[2] = __float_as_uint(pH[(wm + g) * FP + 8 * k + t + 4]);
            pa_h[3] = __float_as_uint(pH[(wm + g + 8) * FP + 8 * k + t + 4]);
            pa_l[0] = __float_as_uint(pL[(wm + g) * FP + 8 * k + t]);
            pa_l[1] = __float_as_uint(pL[(wm + g + 8) * FP + 8 * k + t]);
            pa_l[2] = __float_as_uint(pL[(wm + g) * FP + 8 * k + t + 4]);
            pa_l[3] = __float_as_uint(pL[(wm + g + 8) * FP + 8 * k + t + 4]);
#pragma unroll
            for (int nt = 0; nt < 8; nt++) {
                uint32_t bh0 = __float_as_uint(vhs[(8 * k + t) * BPP + 8 * nt + g]);
                uint32_t bh1 = __float_as_uint(vhs[(8 * k + t + 4) * BPP + 8 * nt + g]);
                uint32_t bl0 = __float_as_uint(vls[(8 * k + t) * BPP + 8 * nt + g]);
                uint32_t bl1 = __float_as_uint(vls[(8 * k + t + 4) * BPP + 8 * nt + g]);
                float* cc = o[nt];
                mma_tf32(cc[0], cc[1], cc[2], cc[3],
                         pa_h[0], pa_h[1], pa_h[2], pa_h[3], bh0, bh1);
                mma_tf32(cc[0], cc[1], cc[2], cc[3],
                         pa_l[0], pa_l[1], pa_l[2], pa_l[3], bh0, bh1);
                mma_tf32(cc[0], cc[1], cc[2], cc[3],
                         pa_h[0], pa_h[1], pa_h[2], pa_h[3], bl0, bl1);
            }
        }
        __syncthreads();
    }

    const float inv0 = 1.f / l0, inv1 = 1.f / l1;
    float* crow0 = ctx + ((size_t)(b * S_ + qt * 64 + wm + g)) * 2048 + h * 64;
    float* crow1 = crow0 + (size_t)8 * 2048;
#pragma unroll
    for (int nt = 0; nt < 8; nt++) {
        const int col = nt * 8 + 2 * t;
        *reinterpret_cast<float2*>(crow0 + col) =
            make_float2(o[nt][0] * inv0, o[nt][1] * inv0);
        *reinterpret_cast<float2*>(crow1 + col) =
            make_float2(o[nt][2] * inv1, o[nt][3] * inv1);
    }
}

// ---------------------------------------------------------------------------
// Launch
// ---------------------------------------------------------------------------
extern "C" void kernel_launch(void* const* d_in, const int* in_sizes, int n_in,
                              void* d_out, int out_size)
{
    const float* X    = (const float*)d_in[0];
    const float* cosb = (const float*)d_in[1];
    const float* sinb = (const float*)d_in[2];
    // d_in[3] attention_mask unused (causal handled analytically)
    const float* wq = (const float*)d_in[4];
    const float* wk = (const float*)d_in[5];
    const float* wv = (const float*)d_in[6];
    const float* wo = (const float*)d_in[7];
    const float* qw = (const float*)d_in[8];
    const float* kw = (const float*)d_in[9];
    float* out = (float*)d_out;

    float *qraw, *kraw, *vraw, *ctx;
    float *qhH, *qhL, *kTH, *kTL, *vH, *vL;
    cudaGetSymbolAddress((void**)&qraw, g_qraw);
    cudaGetSymbolAddress((void**)&kraw, g_kraw);
    cudaGetSymbolAddress((void**)&vraw, g_vraw);
    cudaGetSymbolAddress((void**)&ctx,  g_ctx);
    cudaGetSymbolAddress((void**)&qhH,  g_qhH);
    cudaGetSymbolAddress((void**)&qhL,  g_qhL);
    cudaGetSymbolAddress((void**)&kTH,  g_kTH);
    cudaGetSymbolAddress((void**)&kTL,  g_kTL);
    cudaGetSymbolAddress((void**)&vH,   g_vH);
    cudaGetSymbolAddress((void**)&vL,   g_vL);

    cudaFuncSetAttribute(flash_mma, cudaFuncAttributeMaxDynamicSharedMemorySize,
                         FLASH_SMEM);

    dim3 gq(16, 16);
    dim3 gkv(8, 16);

    gemm_bf16<<<gq, 256>>>(X, wq, qraw, 2048, 2048);
    gemm_bf16_kv<<<gkv, 256>>>(X, wk, wv, kraw, vraw, 2048);

    q_norm_rope<<<M_, 256>>>(qraw, qw, cosb, sinb, qhH, qhL);
    kv_norm_rope<<<M_, 256>>>(kraw, vraw, kw, cosb, sinb, kTH, kTL, vH, vL);

    flash_mma<<<dim3(16, NH_, B_), 128, FLASH_SMEM>>>(qhH, qhL, kTH, kTL, vH, vL, ctx);

    gemm_bf16<<<gq, 256>>>(ctx, wo, out, 2048, 2048);
}

// round 7
// speedup vs baseline: 2.8721x; 1.0659x over previous
#include <cuda_runtime.h>
#include <cuda_bf16.h>
#include <cstdint>

// Problem constants
#define B_  2
#define S_  1024
#define H_  2048
#define NH_ 32
#define NKV_ 8
#define HD_ 64
#define M_  2048

// ---------------------------------------------------------------------------
// Scratch (device globals)
// ---------------------------------------------------------------------------
__device__ float g_qraw[M_ * 2048];
__device__ float g_kraw[M_ * 512];
__device__ float g_vraw[M_ * 512];
__device__ float g_ctx[M_ * 2048];
// flash operand planes (tf32 split)
__device__ float g_qhH[M_ * 2048], g_qhL[M_ * 2048];    // [b,h,s,d]
__device__ float g_kTH[M_ * 512],  g_kTL[M_ * 512];     // [b,hk,d,s]
__device__ float g_vH [M_ * 512],  g_vL [M_ * 512];     // [b,hk,s,d]
// pre-packed bf16x2 GEMM operands
__device__ uint32_t g_XAH[1024 * 2048], g_XAL[1024 * 2048];   // X^T packed [K/2][M]
__device__ uint32_t g_CAH[1024 * 2048], g_CAL[1024 * 2048];   // ctx^T packed
__device__ uint32_t g_WQH[1024 * 2048], g_WQL[1024 * 2048];   // wq [K/2][N]
__device__ uint32_t g_WKH[1024 * 512],  g_WKL[1024 * 512];
__device__ uint32_t g_WVH[1024 * 512],  g_WVL[1024 * 512];
__device__ uint32_t g_WOH[1024 * 2048], g_WOL[1024 * 2048];

// ---------------------------------------------------------------------------
// helpers
// ---------------------------------------------------------------------------
__device__ __forceinline__ uint32_t f2tf32(float x) {
    uint32_t r;
    asm("cvt.rna.tf32.f32 %0, %1;" : "=r"(r) : "f"(x));
    return r;
}

__device__ __forceinline__ void mma_tf32(
    float& c0, float& c1, float& c2, float& c3,
    uint32_t a0, uint32_t a1, uint32_t a2, uint32_t a3,
    uint32_t b0, uint32_t b1)
{
    asm volatile(
        "mma.sync.aligned.m16n8k8.row.col.f32.tf32.tf32.f32 "
        "{%0,%1,%2,%3}, {%4,%5,%6,%7}, {%8,%9}, {%0,%1,%2,%3};\n"
        : "+f"(c0), "+f"(c1), "+f"(c2), "+f"(c3)
        : "r"(a0), "r"(a1), "r"(a2), "r"(a3), "r"(b0), "r"(b1));
}

__device__ __forceinline__ void mma_bf16(
    float& c0, float& c1, float& c2, float& c3,
    uint32_t a0, uint32_t a1, uint32_t a2, uint32_t a3,
    uint32_t b0, uint32_t b1)
{
    asm volatile(
        "mma.sync.aligned.m16n8k16.row.col.f32.bf16.bf16.f32 "
        "{%0,%1,%2,%3}, {%4,%5,%6,%7}, {%8,%9}, {%0,%1,%2,%3};\n"
        : "+f"(c0), "+f"(c1), "+f"(c2), "+f"(c3)
        : "r"(a0), "r"(a1), "r"(a2), "r"(a3), "r"(b0), "r"(b1));
}

__device__ __forceinline__ void cp16(uint32_t dst, const void* src) {
    asm volatile("cp.async.cg.shared.global [%0], [%1], 16;" :: "r"(dst), "l"(src));
}

__device__ __forceinline__ uint32_t pack_hi(float x, float y) {
    __nv_bfloat162 h = __floats2bfloat162_rn(x, y);
    return *reinterpret_cast<uint32_t*>(&h);
}
__device__ __forceinline__ uint32_t pack_lo(float x, float y, uint32_t hi) {
    __nv_bfloat162 h = *reinterpret_cast<__nv_bfloat162*>(&hi);
    float lx = x - __bfloat162float(h.x);
    float ly = y - __bfloat162float(h.y);
    __nv_bfloat162 l = __floats2bfloat162_rn(lx, ly);
    return *reinterpret_cast<uint32_t*>(&l);
}

// ---------------------------------------------------------------------------
// Prep: W[K][N] f32 -> BH/BL [K/2][N] bf16x2 (pack consecutive k)
// ---------------------------------------------------------------------------
__global__ __launch_bounds__(256) void pack_rows(
    const float* __restrict__ W, uint32_t* __restrict__ BH,
    uint32_t* __restrict__ BL, int N, int total)
{
    const int i = blockIdx.x * 256 + threadIdx.x;
    if (i >= total) return;
    const int kp = i / N, n = i - kp * N;
    const float x = W[(size_t)(2 * kp) * N + n];
    const float y = W[(size_t)(2 * kp + 1) * N + n];
    const uint32_t h = pack_hi(x, y);
    BH[i] = h;
    BL[i] = pack_lo(x, y, h);
}

// ---------------------------------------------------------------------------
// Prep: X[M][K] f32 -> AH/AL [K/2][M] bf16x2 (transpose + pack)
// ---------------------------------------------------------------------------
__global__ __launch_bounds__(256) void transpose_pack(
    const float* __restrict__ X, uint32_t* __restrict__ AH,
    uint32_t* __restrict__ AL, int M, int K)
{
    __shared__ float t[64][33];
    const int m0 = blockIdx.x * 32, k0 = blockIdx.y * 64;
#pragma unroll
    for (int i = threadIdx.x; i < 32 * 64; i += 256) {
        const int ml = i >> 6, kl = i & 63;
        t[kl][ml] = X[(size_t)(m0 + ml) * K + k0 + kl];
    }
    __syncthreads();
#pragma unroll
    for (int i = threadIdx.x; i < 32 * 32; i += 256) {
        const int kpl = i >> 5, ml = i & 31;
        const float x = t[2 * kpl][ml], y = t[2 * kpl + 1][ml];
        const uint32_t h = pack_hi(x, y);
        const size_t o = (size_t)(k0 / 2 + kpl) * M + m0 + ml;
        AH[o] = h;
        AL[o] = pack_lo(x, y, h);
    }
}

// ---------------------------------------------------------------------------
// GEMM v2: C[M,N] = A @ B from pre-packed planes.
// A planes [K/2][AM], B planes [K/2][N]. 128x128 tile, BK=16 (8 kpairs),
// 4-stage cp.async pipeline, 256 threads (8 warps, 4x2 of 32x64).
// ---------------------------------------------------------------------------
#define KPT 8
#define PITCH 132
#define PLANE_W (KPT * PITCH)          // 1056 words
#define STG_W (4 * PLANE_W)            // 4224 words
#define STG_BYTES (STG_W * 4)          // 16896 B
#define NST 4
#define G2_SMEM (NST * STG_BYTES)      // 67584 B

__device__ __forceinline__ void gemm2_body(
    const uint32_t* __restrict__ AHg, const uint32_t* __restrict__ ALg,
    const uint32_t* __restrict__ BHg, const uint32_t* __restrict__ BLg,
    float* __restrict__ C, int AM, int N, int K, int brow, int bcol)
{
    extern __shared__ uint32_t sm2[];

    const int tid  = threadIdx.x;
    const int lane = tid & 31;
    const int warp = tid >> 5;
    const int gid  = lane >> 2;
    const int tig  = lane & 3;
    const int wm   = (warp & 3) * 32;
    const int wn   = (warp >> 2) * 64;

    uint32_t sbase;
    asm("{ .reg .u64 t; cvta.to.shared.u64 t, %1; cvt.u32.u64 %0, t; }"
        : "=r"(sbase) : "l"(sm2));

    const int NK = K >> 4;   // 16 k per tile
    const int l_row = tid >> 5;     // kpair row 0..7
    const int l_ch  = tid & 31;     // 16B chunk

    auto load_stage = [&](int kt) {
        const uint32_t st = sbase + (kt & 3) * STG_BYTES;
        const size_t kpg = (size_t)(kt * KPT + l_row);
        const size_t aoff = kpg * AM + brow + l_ch * 4;
        const size_t boff = kpg * N + bcol + l_ch * 4;
        const uint32_t d0 = st + l_row * (PITCH * 4) + l_ch * 16;
        cp16(d0,                       AHg + aoff);
        cp16(d0 + PLANE_W * 4,         ALg + aoff);
        cp16(d0 + 2 * (PLANE_W * 4),   BHg + boff);
        cp16(d0 + 3 * (PLANE_W * 4),   BLg + boff);
    };

    float c[2][8][4];
#pragma unroll
    for (int i = 0; i < 2; i++)
#pragma unroll
        for (int j = 0; j < 8; j++)
#pragma unroll
            for (int v = 0; v < 4; v++) c[i][j][v] = 0.f;

    load_stage(0);
    asm volatile("cp.async.commit_group;" ::: "memory");
    load_stage(1);
    asm volatile("cp.async.commit_group;" ::: "memory");
    load_stage(2);
    asm volatile("cp.async.commit_group;" ::: "memory");

    for (int kt = 0; kt < NK; kt++) {
        asm volatile("cp.async.wait_group 2;" ::: "memory");
        __syncthreads();

        const uint32_t* AH = sm2 + (kt & 3) * STG_W;
        const uint32_t* AL = AH + PLANE_W;
        const uint32_t* BH = AH + 2 * PLANE_W;
        const uint32_t* BL = AH + 3 * PLANE_W;

        uint32_t ah[2][4], al[2][4];
#pragma unroll
        for (int mt = 0; mt < 2; mt++) {
            const int m0 = wm + mt * 16 + gid;
            ah[mt][0] = AH[tig * PITCH + m0];
            ah[mt][1] = AH[tig * PITCH + m0 + 8];
            ah[mt][2] = AH[(tig + 4) * PITCH + m0];
            ah[mt][3] = AH[(tig + 4) * PITCH + m0 + 8];
            al[mt][0] = AL[tig * PITCH + m0];
            al[mt][1] = AL[tig * PITCH + m0 + 8];
            al[mt][2] = AL[(tig + 4) * PITCH + m0];
            al[mt][3] = AL[(tig + 4) * PITCH + m0 + 8];
        }
#pragma unroll
        for (int nt = 0; nt < 8; nt++) {
            const int n0 = wn + nt * 8 + gid;
            const uint32_t bh0 = BH[tig * PITCH + n0];
            const uint32_t bh1 = BH[(tig + 4) * PITCH + n0];
            const uint32_t bl0 = BL[tig * PITCH + n0];
            const uint32_t bl1 = BL[(tig + 4) * PITCH + n0];
#pragma unroll
            for (int mt = 0; mt < 2; mt++) {
                float* cc = c[mt][nt];
                mma_bf16(cc[0], cc[1], cc[2], cc[3],
                         ah[mt][0], ah[mt][1], ah[mt][2], ah[mt][3], bh0, bh1);
                mma_bf16(cc[0], cc[1], cc[2], cc[3],
                         ah[mt][0], ah[mt][1], ah[mt][2], ah[mt][3], bl0, bl1);
                mma_bf16(cc[0], cc[1], cc[2], cc[3],
                         al[mt][0], al[mt][1], al[mt][2], al[mt][3], bh0, bh1);
            }
        }

        __syncthreads();
        if (kt + 3 < NK) load_stage(kt + 3);
        asm volatile("cp.async.commit_group;" ::: "memory");
    }

#pragma unroll
    for (int mt = 0; mt < 2; mt++) {
#pragma unroll
        for (int nt = 0; nt < 8; nt++) {
            const int row = brow + wm + mt * 16 + gid;
            const int col = bcol + wn + nt * 8 + 2 * tig;
            float* cc = c[mt][nt];
            *reinterpret_cast<float2*>(C + (size_t)row * N + col) =
                make_float2(cc[0], cc[1]);
            *reinterpret_cast<float2*>(C + (size_t)(row + 8) * N + col) =
                make_float2(cc[2], cc[3]);
        }
    }
}

__global__ __launch_bounds__(256, 2) void gemm2(
    const uint32_t* __restrict__ AHg, const uint32_t* __restrict__ ALg,
    const uint32_t* __restrict__ BHg, const uint32_t* __restrict__ BLg,
    float* __restrict__ C, int AM, int N, int K)
{
    gemm2_body(AHg, ALg, BHg, BLg, C, AM, N, K, blockIdx.y * 128, blockIdx.x * 128);
}

__global__ __launch_bounds__(256, 2) void gemm2_kv(
    const uint32_t* __restrict__ AHg, const uint32_t* __restrict__ ALg,
    const uint32_t* __restrict__ KHg, const uint32_t* __restrict__ KLg,
    const uint32_t* __restrict__ VHg, const uint32_t* __restrict__ VLg,
    float* __restrict__ Ck, float* __restrict__ Cv, int AM, int K)
{
    const bool isv = blockIdx.x >= 4;
    const int bx = isv ? (int)blockIdx.x - 4 : (int)blockIdx.x;
    gemm2_body(AHg, ALg, isv ? VHg : KHg, isv ? VLg : KLg,
               isv ? Cv : Ck, AM, 512, K, blockIdx.y * 128, bx * 128);
}

// ---------------------------------------------------------------------------
// Block reduce helper
// ---------------------------------------------------------------------------
__device__ __forceinline__ float block_sum_256(float v) {
    __shared__ float red[8];
#pragma unroll
    for (int o = 16; o > 0; o >>= 1) v += __shfl_xor_sync(0xffffffffu, v, o);
    const int lane = threadIdx.x & 31, wid = threadIdx.x >> 5;
    if (lane == 0) red[wid] = v;
    __syncthreads();
    float tot = 0.f;
    if (threadIdx.x < 8) tot = red[threadIdx.x];
#pragma unroll
    for (int o = 4; o > 0; o >>= 1) tot += __shfl_xor_sync(0xffffffffu, tot, o);
    return tot;
}

// ---------------------------------------------------------------------------
// Q: RMSNorm(2048) + RoPE -> split tf32 planes [b,h,s,d]
// ---------------------------------------------------------------------------
__global__ __launch_bounds__(256) void q_norm_rope(
    const float* __restrict__ qraw, const float* __restrict__ qw,
    const float* __restrict__ cosb, const float* __restrict__ sinb,
    float* __restrict__ qhH, float* __restrict__ qhL)
{
    const int r = blockIdx.x;
    const int b = r >> 10, s = r & 1023;
    const float* row = qraw + (size_t)r * 2048;

    float ss = 0.f;
    for (int d = threadIdx.x; d < 2048; d += 256) { float x = row[d]; ss += x * x; }
    float tot = block_sum_256(ss);
    __shared__ float s_inv;
    if (threadIdx.x == 0) s_inv = rsqrtf(tot * (1.f / 2048.f) + 1e-6f);
    __syncthreads();
    const float inv = s_inv;

    const float* cs = cosb + (size_t)r * 64;
    const float* sn = sinb + (size_t)r * 64;

    for (int d = threadIdx.x; d < 2048; d += 256) {
        const int hd = d & 63, h = d >> 6;
        float val = row[d] * inv * qw[d];
        const int pd = (hd < 32) ? d + 32 : d - 32;
        float pv = row[pd] * inv * qw[pd];
        float rot = (hd < 32) ? -pv : pv;
        float o = val * cs[hd] + rot * sn[hd];
        uint32_t hb = f2tf32(o);
        float lo = o - __uint_as_float(hb);
        const size_t oi = (((size_t)(b * NH_ + h)) * S_ + s) * 64 + hd;
        qhH[oi] = __uint_as_float(hb);
        qhL[oi] = __uint_as_float(f2tf32(lo));
    }
}

// ---------------------------------------------------------------------------
// K: RMSNorm(512)+RoPE -> TRANSPOSED split planes [b,hk,d,s]; V split [b,hk,s,d]
// ---------------------------------------------------------------------------
__global__ __launch_bounds__(256) void kv_norm_rope(
    const float* __restrict__ kraw, const float* __restrict__ vraw,
    const float* __restrict__ kw,
    const float* __restrict__ cosb, const float* __restrict__ sinb,
    float* __restrict__ kTH, float* __restrict__ kTL,
    float* __restrict__ vH, float* __restrict__ vL)
{
    const int r = blockIdx.x;
    const int b = r >> 10, s = r & 1023;
    const float* row = kraw + (size_t)r * 512;

    float ss = 0.f;
    for (int d = threadIdx.x; d < 512; d += 256) { float x = row[d]; ss += x * x; }
    float tot = block_sum_256(ss);
    __shared__ float s_inv;
    if (threadIdx.x == 0) s_inv = rsqrtf(tot * (1.f / 512.f) + 1e-6f);
    __syncthreads();
    const float inv = s_inv;

    const float* cs = cosb + (size_t)r * 64;
    const float* sn = sinb + (size_t)r * 64;

    for (int d = threadIdx.x; d < 512; d += 256) {
        const int hd = d & 63, h = d >> 6;
        float val = row[d] * inv * kw[d];
        const int pd = (hd < 32) ? d + 32 : d - 32;
        float pv = row[pd] * inv * kw[pd];
        float rot = (hd < 32) ? -pv : pv;
        float o = val * cs[hd] + rot * sn[hd];
        uint32_t hb = f2tf32(o);
        float klo = o - __uint_as_float(hb);
        const size_t ti = (((size_t)(b * NKV_ + h)) * 64 + hd) * S_ + s;
        kTH[ti] = __uint_as_float(hb);
        kTL[ti] = __uint_as_float(f2tf32(klo));
        float v = vraw[(size_t)r * 512 + d];
        uint32_t vhb = f2tf32(v);
        float vlo = v - __uint_as_float(vhb);
        const size_t vi = (((size_t)(b * NKV_ + h)) * S_ + s) * 64 + hd;
        vH[vi] = __uint_as_float(vhb);
        vL[vi] = __uint_as_float(f2tf32(vlo));
    }
}

// ---------------------------------------------------------------------------
// Flash attention on mma.sync tf32 (3-split). Unchanged from R5/R6 (proven).
// ---------------------------------------------------------------------------
#define FP 68
#define BPP 72
#define PLANE_F (64 * BPP)
#define STAGE_F (4 * PLANE_F)
#define STAGE_B (STAGE_F * 4)
#define FLASH_SMEM (2 * STAGE_B + 2 * 64 * FP * 4)

__global__ __launch_bounds__(128) void flash_mma(
    const float* __restrict__ qhH, const float* __restrict__ qhL,
    const float* __restrict__ kTH, const float* __restrict__ kTL,
    const float* __restrict__ vH,  const float* __restrict__ vL,
    float* __restrict__ ctx)
{
    extern __shared__ float fsm[];
    float* pH = fsm + 2 * STAGE_F;
    float* pL = pH + 64 * FP;

    const int tid = threadIdx.x, lane = tid & 31, warp = tid >> 5;
    const int g = lane >> 2, t = lane & 3;
    const int wm = warp * 16;
    const int qt = blockIdx.x, h = blockIdx.y, b = blockIdx.z, hk = h >> 2;

    uint32_t sbase;
    asm("{ .reg .u64 tt; cvta.to.shared.u64 tt, %1; cvt.u32.u64 %0, tt; }"
        : "=r"(sbase) : "l"(fsm));

    const float* kbH = kTH + ((size_t)(b * NKV_ + hk)) * 64 * S_;
    const float* kbL = kTL + ((size_t)(b * NKV_ + hk)) * 64 * S_;
    const float* vbH = vH + ((size_t)(b * NKV_ + hk)) * S_ * 64;
    const float* vbL = vL + ((size_t)(b * NKV_ + hk)) * S_ * 64;

    uint32_t qa_h[8][4], qa_l[8][4];
    {
        const size_t qoff = (((size_t)(b * NH_ + h)) * S_ + qt * 64 + wm) * 64;
        const float* qH = qhH + qoff;
        const float* qL = qhL + qoff;
#pragma unroll
        for (int k = 0; k < 8; k++) {
            qa_h[k][0] = __float_as_uint(qH[g * 64 + 8 * k + t]);
            qa_h[k][1] = __float_as_uint(qH[(g + 8) * 64 + 8 * k + t]);
            qa_h[k][2] = __float_as_uint(qH[g * 64 + 8 * k + t + 4]);
            qa_h[k][3] = __float_as_uint(qH[(g + 8) * 64 + 8 * k + t + 4]);
            qa_l[k][0] = __float_as_uint(qL[g * 64 + 8 * k + t]);
            qa_l[k][1] = __float_as_uint(qL[(g + 8) * 64 + 8 * k + t]);
            qa_l[k][2] = __float_as_uint(qL[g * 64 + 8 * k + t + 4]);
            qa_l[k][3] = __float_as_uint(qL[(g + 8) * 64 + 8 * k + t + 4]);
        }
    }

    float o[8][4];
#pragma unroll
    for (int nt = 0; nt < 8; nt++)
#pragma unroll
        for (int c = 0; c < 4; c++) o[nt][c] = 0.f;
    float m0 = -1e30f, m1 = -1e30f, l0 = 0.f, l1 = 0.f;

    const int ntiles = qt + 1;

    auto load_tile = [&](int kt) {
        const uint32_t st = sbase + (kt & 1) * STAGE_B;
        const int row8 = tid >> 4;
        const int ch = tid & 15;
#pragma unroll
        for (int i = 0; i < 32; i++) {
            const int plane = i >> 3;
            const int row = (i & 7) * 8 + row8;
            const uint32_t dst = st + plane * (PLANE_F * 4) + row * (BPP * 4) + ch * 16;
            const float* src;
            if (plane == 0)      src = kbH + (size_t)row * S_ + kt * 64 + ch * 4;
            else if (plane == 1) src = kbL + (size_t)row * S_ + kt * 64 + ch * 4;
            else if (plane == 2) src = vbH + (size_t)(kt * 64 + row) * 64 + ch * 4;
            else                 src = vbL + (size_t)(kt * 64 + row) * 64 + ch * 4;
            cp16(dst, src);
        }
    };

    load_tile(0);
    asm volatile("cp.async.commit_group;" ::: "memory");

    for (int kt = 0; kt < ntiles; kt++) {
        if (kt + 1 < ntiles) load_tile(kt + 1);
        asm volatile("cp.async.commit_group;" ::: "memory");
        asm volatile("cp.async.wait_group 1;" ::: "memory");
        __syncthreads();

        const float* kThs = fsm + (kt & 1) * STAGE_F;
        const float* kTls = kThs + PLANE_F;
        const float* vhs  = kThs + 2 * PLANE_F;
        const float* vls  = kThs + 3 * PLANE_F;

        float sf[8][4];
#pragma unroll
        for (int nt = 0; nt < 8; nt++)
#pragma unroll
            for (int c = 0; c < 4; c++) sf[nt][c] = 0.f;

#pragma unroll
        for (int nt = 0; nt < 8; nt++) {
#pragma unroll
            for (int k = 0; k < 8; k++) {
                uint32_t bh0 = __float_as_uint(kThs[(8 * k + t) * BPP + 8 * nt + g]);
                uint32_t bh1 = __float_as_uint(kThs[(8 * k + t + 4) * BPP + 8 * nt + g]);
                uint32_t bl0 = __float_as_uint(kTls[(8 * k + t) * BPP + 8 * nt + g]);
                uint32_t bl1 = __float_as_uint(kTls[(8 * k + t + 4) * BPP + 8 * nt + g]);
                float* cc = sf[nt];
                mma_tf32(cc[0], cc[1], cc[2], cc[3],
                         qa_h[k][0], qa_h[k][1], qa_h[k][2], qa_h[k][3], bh0, bh1);
                mma_tf32(cc[0], cc[1], cc[2], cc[3],
                         qa_h[k][0], qa_h[k][1], qa_h[k][2], qa_h[k][3], bl0, bl1);
                mma_tf32(cc[0], cc[1], cc[2], cc[3],
                         qa_l[k][0], qa_l[k][1], qa_l[k][2], qa_l[k][3], bh0, bh1);
            }
        }

        const bool diag = (kt == qt);
        float mn0 = m0, mn1 = m1;
#pragma unroll
        for (int nt = 0; nt < 8; nt++) {
#pragma unroll
            for (int c = 0; c < 4; c++) {
                float v = sf[nt][c] * 0.125f;
                const int colloc = nt * 8 + 2 * t + (c & 1);
                const int rowloc = wm + g + ((c >= 2) ? 8 : 0);
                if (diag && colloc > rowloc) v = -1e30f;
                sf[nt][c] = v;
                if (c < 2) mn0 = fmaxf(mn0, v);
                else       mn1 = fmaxf(mn1, v);
            }
        }
        mn0 = fmaxf(mn0, __shfl_xor_sync(0xffffffffu, mn0, 1));
        mn0 = fmaxf(mn0, __shfl_xor_sync(0xffffffffu, mn0, 2));
        mn1 = fmaxf(mn1, __shfl_xor_sync(0xffffffffu, mn1, 1));
        mn1 = fmaxf(mn1, __shfl_xor_sync(0xffffffffu, mn1, 2));

        const float sc0 = __expf(m0 - mn0);
        const float sc1 = __expf(m1 - mn1);
        m0 = mn0; m1 = mn1;
        l0 *= sc0; l1 *= sc1;
#pragma unroll
        for (int nt = 0; nt < 8; nt++) {
            o[nt][0] *= sc0; o[nt][1] *= sc0;
            o[nt][2] *= sc1; o[nt][3] *= sc1;
        }

        float ps0 = 0.f, ps1 = 0.f;
#pragma unroll
        for (int nt = 0; nt < 8; nt++) {
            float p0 = __expf(sf[nt][0] - mn0);
            float p1 = __expf(sf[nt][1] - mn0);
            float p2 = __expf(sf[nt][2] - mn1);
            float p3 = __expf(sf[nt][3] - mn1);
            ps0 += p0 + p1;
            ps1 += p2 + p3;
            uint32_t h0 = f2tf32(p0), h1 = f2tf32(p1), h2 = f2tf32(p2), h3 = f2tf32(p3);
            float e0 = p0 - __uint_as_float(h0), e1 = p1 - __uint_as_float(h1);
            float e2 = p2 - __uint_as_float(h2), e3 = p3 - __uint_as_float(h3);
            const int col = nt * 8 + 2 * t;
            *reinterpret_cast<float2*>(&pH[(wm + g) * FP + col]) =
                make_float2(__uint_as_float(h0), __uint_as_float(h1));
            *reinterpret_cast<float2*>(&pH[(wm + g + 8) * FP + col]) =
                make_float2(__uint_as_float(h2), __uint_as_float(h3));
            *reinterpret_cast<float2*>(&pL[(wm + g) * FP + col]) =
                make_float2(__uint_as_float(f2tf32(e0)), __uint_as_float(f2tf32(e1)));
            *reinterpret_cast<float2*>(&pL[(wm + g + 8) * FP + col]) =
                make_float2(__uint_as_float(f2tf32(e2)), __uint_as_float(f2tf32(e3)));
        }
        ps0 += __shfl_xor_sync(0xffffffffu, ps0, 1);
        ps0 += __shfl_xor_sync(0xffffffffu, ps0, 2);
        ps1 += __shfl_xor_sync(0xffffffffu, ps1, 1);
        ps1 += __shfl_xor_sync(0xffffffffu, ps1, 2);
        l0 += ps0; l1 += ps1;
        __syncwarp();

#pragma unroll
        for (int k = 0; k < 8; k++) {
            uint32_t pa_h[4], pa_l[4];
            pa_h[0] = __float_as_uint(pH[(wm + g) * FP + 8 * k + t]);
            pa_h[1] = __float_as_uint(pH[(wm + g + 8) * FP + 8 * k + t]);
            pa_h[2] = __float_as_uint(pH[(wm + g) * FP + 8 * k + t + 4]);
            pa_h[3] = __float_as_uint(pH[(wm + g + 8) * FP + 8 * k + t + 4]);
            pa_l[0] = __float_as_uint(pL[(wm + g) * FP + 8 * k + t]);
            pa_l[1] = __float_as_uint(pL[(wm + g + 8) * FP + 8 * k + t]);
            pa_l[2] = __float_as_uint(pL[(wm + g) * FP + 8 * k + t + 4]);
            pa_l[3] = __float_as_uint(pL[(wm + g + 8) * FP + 8 * k + t + 4]);
#pragma unroll
            for (int nt = 0; nt < 8; nt++) {
                uint32_t bh0 = __float_as_uint(vhs[(8 * k + t) * BPP + 8 * nt + g]);
                uint32_t bh1 = __float_as_uint(vhs[(8 * k + t + 4) * BPP + 8 * nt + g]);
                uint32_t bl0 = __float_as_uint(vls[(8 * k + t) * BPP + 8 * nt + g]);
                uint32_t bl1 = __float_as_uint(vls[(8 * k + t + 4) * BPP + 8 * nt + g]);
                float* cc = o[nt];
                mma_tf32(cc[0], cc[1], cc[2], cc[3],
                         pa_h[0], pa_h[1], pa_h[2], pa_h[3], bh0, bh1);
                mma_tf32(cc[0], cc[1], cc[2], cc[3],
                         pa_l[0], pa_l[1], pa_l[2], pa_l[3], bh0, bh1);
                mma_tf32(cc[0], cc[1], cc[2], cc[3],
                         pa_h[0], pa_h[1], pa_h[2], pa_h[3], bl0, bl1);
            }
        }
        __syncthreads();
    }

    const float inv0 = 1.f / l0, inv1 = 1.f / l1;
    float* crow0 = ctx + ((size_t)(b * S_ + qt * 64 + wm + g)) * 2048 + h * 64;
    float* crow1 = crow0 + (size_t)8 * 2048;
#pragma unroll
    for (int nt = 0; nt < 8; nt++) {
        const int col = nt * 8 + 2 * t;
        *reinterpret_cast<float2*>(crow0 + col) =
            make_float2(o[nt][0] * inv0, o[nt][1] * inv0);
        *reinterpret_cast<float2*>(crow1 + col) =
            make_float2(o[nt][2] * inv1, o[nt][3] * inv1);
    }
}

// ---------------------------------------------------------------------------
// Launch
// ---------------------------------------------------------------------------
extern "C" void kernel_launch(void* const* d_in, const int* in_sizes, int n_in,
                              void* d_out, int out_size)
{
    const float* X    = (const float*)d_in[0];
    const float* cosb = (const float*)d_in[1];
    const float* sinb = (const float*)d_in[2];
    // d_in[3] attention_mask unused (causal handled analytically)
    const float* wq = (const float*)d_in[4];
    const float* wk = (const float*)d_in[5];
    const float* wv = (const float*)d_in[6];
    const float* wo = (const float*)d_in[7];
    const float* qw = (const float*)d_in[8];
    const float* kw = (const float*)d_in[9];
    float* out = (float*)d_out;

    float *qraw, *kraw, *vraw, *ctx;
    float *qhH, *qhL, *kTH, *kTL, *vH, *vL;
    uint32_t *XAH, *XAL, *CAH, *CAL;
    uint32_t *WQH, *WQL, *WKH, *WKL, *WVH, *WVL, *WOH, *WOL;
    cudaGetSymbolAddress((void**)&qraw, g_qraw);
    cudaGetSymbolAddress((void**)&kraw, g_kraw);
    cudaGetSymbolAddress((void**)&vraw, g_vraw);
    cudaGetSymbolAddress((void**)&ctx,  g_ctx);
    cudaGetSymbolAddress((void**)&qhH,  g_qhH);
    cudaGetSymbolAddress((void**)&qhL,  g_qhL);
    cudaGetSymbolAddress((void**)&kTH,  g_kTH);
    cudaGetSymbolAddress((void**)&kTL,  g_kTL);
    cudaGetSymbolAddress((void**)&vH,   g_vH);
    cudaGetSymbolAddress((void**)&vL,   g_vL);
    cudaGetSymbolAddress((void**)&XAH,  g_XAH);
    cudaGetSymbolAddress((void**)&XAL,  g_XAL);
    cudaGetSymbolAddress((void**)&CAH,  g_CAH);
    cudaGetSymbolAddress((void**)&CAL,  g_CAL);
    cudaGetSymbolAddress((void**)&WQH,  g_WQH);
    cudaGetSymbolAddress((void**)&WQL,  g_WQL);
    cudaGetSymbolAddress((void**)&WKH,  g_WKH);
    cudaGetSymbolAddress((void**)&WKL,  g_WKL);
    cudaGetSymbolAddress((void**)&WVH,  g_WVH);
    cudaGetSymbolAddress((void**)&WVL,  g_WVL);
    cudaGetSymbolAddress((void**)&WOH,  g_WOH);
    cudaGetSymbolAddress((void**)&WOL,  g_WOL);

    cudaFuncSetAttribute(flash_mma, cudaFuncAttributeMaxDynamicSharedMemorySize,
                         FLASH_SMEM);
    cudaFuncSetAttribute(gemm2, cudaFuncAttributeMaxDynamicSharedMemorySize, G2_SMEM);
    cudaFuncSetAttribute(gemm2_kv, cudaFuncAttributeMaxDynamicSharedMemorySize, G2_SMEM);

    // prep: pack operands
    transpose_pack<<<dim3(64, 32), 256>>>(X, XAH, XAL, 2048, 2048);
    pack_rows<<<8192, 256>>>(wq, WQH, WQL, 2048, 1024 * 2048);
    pack_rows<<<2048, 256>>>(wk, WKH, WKL, 512, 1024 * 512);
    pack_rows<<<2048, 256>>>(wv, WVH, WVL, 512, 1024 * 512);
    pack_rows<<<8192, 256>>>(wo, WOH, WOL, 2048, 1024 * 2048);

    // projections
    gemm2<<<dim3(16, 16), 256, G2_SMEM>>>(XAH, XAL, WQH, WQL, qraw, 2048, 2048, 2048);
    gemm2_kv<<<dim3(8, 16), 256, G2_SMEM>>>(XAH, XAL, WKH, WKL, WVH, WVL,
                                            kraw, vraw, 2048, 2048);

    q_norm_rope<<<M_, 256>>>(qraw, qw, cosb, sinb, qhH, qhL);
    kv_norm_rope<<<M_, 256>>>(kraw, vraw, kw, cosb, sinb, kTH, kTL, vH, vL);

    flash_mma<<<dim3(16, NH_, B_), 128, FLASH_SMEM>>>(qhH, qhL, kTH, kTL, vH, vL, ctx);

    // output projection
    transpose_pack<<<dim3(64, 32), 256>>>(ctx, CAH, CAL, 2048, 2048);
    gemm2<<<dim3(16, 16), 256, G2_SMEM>>>(CAH, CAL, WOH, WOL, out, 2048, 2048, 2048);
}

// round 8
// speedup vs baseline: 3.4184x; 1.1902x over previous
#include <cuda_runtime.h>
#include <cuda_bf16.h>
#include <cstdint>

// Problem constants
#define B_  2
#define S_  1024
#define H_  2048
#define NH_ 32
#define NKV_ 8
#define HD_ 64
#define M_  2048

// ---------------------------------------------------------------------------
// Scratch (device globals)
// ---------------------------------------------------------------------------
__device__ float g_qraw[M_ * 2048];
__device__ float g_kraw[M_ * 512];
__device__ float g_vraw[M_ * 512];
__device__ float g_ctx[M_ * 2048];
// flash packed bf16x2 operands
__device__ uint32_t g_QH[M_ * 1024], g_QL[M_ * 1024];   // [b,h,s,dpair32]
__device__ uint32_t g_KH[524288],    g_KL[524288];      // [b,hk,dpair32,s1024]
__device__ uint32_t g_VH[524288],    g_VL[524288];      // [b,hk,spair512,d64]
// pre-packed bf16x2 GEMM operands
__device__ uint32_t g_XAH[1024 * 2048], g_XAL[1024 * 2048];   // X^T packed [K/2][M]
__device__ uint32_t g_CAH[1024 * 2048], g_CAL[1024 * 2048];   // ctx^T packed
__device__ uint32_t g_WQH[1024 * 2048], g_WQL[1024 * 2048];   // wq [K/2][N]
__device__ uint32_t g_WKH[1024 * 512],  g_WKL[1024 * 512];
__device__ uint32_t g_WVH[1024 * 512],  g_WVL[1024 * 512];
__device__ uint32_t g_WOH[1024 * 2048], g_WOL[1024 * 2048];

// ---------------------------------------------------------------------------
// helpers
// ---------------------------------------------------------------------------
__device__ __forceinline__ void mma_bf16(
    float& c0, float& c1, float& c2, float& c3,
    uint32_t a0, uint32_t a1, uint32_t a2, uint32_t a3,
    uint32_t b0, uint32_t b1)
{
    asm volatile(
        "mma.sync.aligned.m16n8k16.row.col.f32.bf16.bf16.f32 "
        "{%0,%1,%2,%3}, {%4,%5,%6,%7}, {%8,%9}, {%0,%1,%2,%3};\n"
        : "+f"(c0), "+f"(c1), "+f"(c2), "+f"(c3)
        : "r"(a0), "r"(a1), "r"(a2), "r"(a3), "r"(b0), "r"(b1));
}

__device__ __forceinline__ void cp16(uint32_t dst, const void* src) {
    asm volatile("cp.async.cg.shared.global [%0], [%1], 16;" :: "r"(dst), "l"(src));
}

__device__ __forceinline__ uint32_t pack_hi(float x, float y) {
    __nv_bfloat162 h = __floats2bfloat162_rn(x, y);
    return *reinterpret_cast<uint32_t*>(&h);
}
__device__ __forceinline__ uint32_t pack_lo(float x, float y, uint32_t hi) {
    __nv_bfloat162 h = *reinterpret_cast<__nv_bfloat162*>(&hi);
    float lx = x - __bfloat162float(h.x);
    float ly = y - __bfloat162float(h.y);
    __nv_bfloat162 l = __floats2bfloat162_rn(lx, ly);
    return *reinterpret_cast<uint32_t*>(&l);
}

// ---------------------------------------------------------------------------
// Prep: W[K][N] f32 -> BH/BL [K/2][N] bf16x2
// ---------------------------------------------------------------------------
__global__ __launch_bounds__(256) void pack_rows(
    const float* __restrict__ W, uint32_t* __restrict__ BH,
    uint32_t* __restrict__ BL, int N, int total)
{
    const int i = blockIdx.x * 256 + threadIdx.x;
    if (i >= total) return;
    const int kp = i / N, n = i - kp * N;
    const float x = W[(size_t)(2 * kp) * N + n];
    const float y = W[(size_t)(2 * kp + 1) * N + n];
    const uint32_t h = pack_hi(x, y);
    BH[i] = h;
    BL[i] = pack_lo(x, y, h);
}

// ---------------------------------------------------------------------------
// Prep: X[M][K] f32 -> AH/AL [K/2][M] bf16x2 (transpose + pack)
// ---------------------------------------------------------------------------
__global__ __launch_bounds__(256) void transpose_pack(
    const float* __restrict__ X, uint32_t* __restrict__ AH,
    uint32_t* __restrict__ AL, int M, int K)
{
    __shared__ float t[64][33];
    const int m0 = blockIdx.x * 32, k0 = blockIdx.y * 64;
#pragma unroll
    for (int i = threadIdx.x; i < 32 * 64; i += 256) {
        const int ml = i >> 6, kl = i & 63;
        t[kl][ml] = X[(size_t)(m0 + ml) * K + k0 + kl];
    }
    __syncthreads();
#pragma unroll
    for (int i = threadIdx.x; i < 32 * 32; i += 256) {
        const int kpl = i >> 5, ml = i & 31;
        const float x = t[2 * kpl][ml], y = t[2 * kpl + 1][ml];
        const uint32_t h = pack_hi(x, y);
        const size_t o = (size_t)(k0 / 2 + kpl) * M + m0 + ml;
        AH[o] = h;
        AL[o] = pack_lo(x, y, h);
    }
}

// ---------------------------------------------------------------------------
// GEMM v2 (R7, proven): C = A @ B from pre-packed planes.
// ---------------------------------------------------------------------------
#define KPT 8
#define PITCH 132
#define PLANE_W (KPT * PITCH)
#define STG_W (4 * PLANE_W)
#define STG_BYTES (STG_W * 4)
#define NST 4
#define G2_SMEM (NST * STG_BYTES)

__device__ __forceinline__ void gemm2_body(
    const uint32_t* __restrict__ AHg, const uint32_t* __restrict__ ALg,
    const uint32_t* __restrict__ BHg, const uint32_t* __restrict__ BLg,
    float* __restrict__ C, int AM, int N, int K, int brow, int bcol)
{
    extern __shared__ uint32_t sm2[];

    const int tid  = threadIdx.x;
    const int lane = tid & 31;
    const int warp = tid >> 5;
    const int gid  = lane >> 2;
    const int tig  = lane & 3;
    const int wm   = (warp & 3) * 32;
    const int wn   = (warp >> 2) * 64;

    uint32_t sbase;
    asm("{ .reg .u64 t; cvta.to.shared.u64 t, %1; cvt.u32.u64 %0, t; }"
        : "=r"(sbase) : "l"(sm2));

    const int NK = K >> 4;
    const int l_row = tid >> 5;
    const int l_ch  = tid & 31;

    auto load_stage = [&](int kt) {
        const uint32_t st = sbase + (kt & 3) * STG_BYTES;
        const size_t kpg = (size_t)(kt * KPT + l_row);
        const size_t aoff = kpg * AM + brow + l_ch * 4;
        const size_t boff = kpg * N + bcol + l_ch * 4;
        const uint32_t d0 = st + l_row * (PITCH * 4) + l_ch * 16;
        cp16(d0,                       AHg + aoff);
        cp16(d0 + PLANE_W * 4,         ALg + aoff);
        cp16(d0 + 2 * (PLANE_W * 4),   BHg + boff);
        cp16(d0 + 3 * (PLANE_W * 4),   BLg + boff);
    };

    float c[2][8][4];
#pragma unroll
    for (int i = 0; i < 2; i++)
#pragma unroll
        for (int j = 0; j < 8; j++)
#pragma unroll
            for (int v = 0; v < 4; v++) c[i][j][v] = 0.f;

    load_stage(0);
    asm volatile("cp.async.commit_group;" ::: "memory");
    load_stage(1);
    asm volatile("cp.async.commit_group;" ::: "memory");
    load_stage(2);
    asm volatile("cp.async.commit_group;" ::: "memory");

    for (int kt = 0; kt < NK; kt++) {
        asm volatile("cp.async.wait_group 2;" ::: "memory");
        __syncthreads();

        const uint32_t* AH = sm2 + (kt & 3) * STG_W;
        const uint32_t* AL = AH + PLANE_W;
        const uint32_t* BH = AH + 2 * PLANE_W;
        const uint32_t* BL = AH + 3 * PLANE_W;

        uint32_t ah[2][4], al[2][4];
#pragma unroll
        for (int mt = 0; mt < 2; mt++) {
            const int m0 = wm + mt * 16 + gid;
            ah[mt][0] = AH[tig * PITCH + m0];
            ah[mt][1] = AH[tig * PITCH + m0 + 8];
            ah[mt][2] = AH[(tig + 4) * PITCH + m0];
            ah[mt][3] = AH[(tig + 4) * PITCH + m0 + 8];
            al[mt][0] = AL[tig * PITCH + m0];
            al[mt][1] = AL[tig * PITCH + m0 + 8];
            al[mt][2] = AL[(tig + 4) * PITCH + m0];
            al[mt][3] = AL[(tig + 4) * PITCH + m0 + 8];
        }
#pragma unroll
        for (int nt = 0; nt < 8; nt++) {
            const int n0 = wn + nt * 8 + gid;
            const uint32_t bh0 = BH[tig * PITCH + n0];
            const uint32_t bh1 = BH[(tig + 4) * PITCH + n0];
            const uint32_t bl0 = BL[tig * PITCH + n0];
            const uint32_t bl1 = BL[(tig + 4) * PITCH + n0];
#pragma unroll
            for (int mt = 0; mt < 2; mt++) {
                float* cc = c[mt][nt];
                mma_bf16(cc[0], cc[1], cc[2], cc[3],
                         ah[mt][0], ah[mt][1], ah[mt][2], ah[mt][3], bh0, bh1);
                mma_bf16(cc[0], cc[1], cc[2], cc[3],
                         ah[mt][0], ah[mt][1], ah[mt][2], ah[mt][3], bl0, bl1);
                mma_bf16(cc[0], cc[1], cc[2], cc[3],
                         al[mt][0], al[mt][1], al[mt][2], al[mt][3], bh0, bh1);
            }
        }

        __syncthreads();
        if (kt + 3 < NK) load_stage(kt + 3);
        asm volatile("cp.async.commit_group;" ::: "memory");
    }

#pragma unroll
    for (int mt = 0; mt < 2; mt++) {
#pragma unroll
        for (int nt = 0; nt < 8; nt++) {
            const int row = brow + wm + mt * 16 + gid;
            const int col = bcol + wn + nt * 8 + 2 * tig;
            float* cc = c[mt][nt];
            *reinterpret_cast<float2*>(C + (size_t)row * N + col) =
                make_float2(cc[0], cc[1]);
            *reinterpret_cast<float2*>(C + (size_t)(row + 8) * N + col) =
                make_float2(cc[2], cc[3]);
        }
    }
}

__global__ __launch_bounds__(256, 2) void gemm2(
    const uint32_t* __restrict__ AHg, const uint32_t* __restrict__ ALg,
    const uint32_t* __restrict__ BHg, const uint32_t* __restrict__ BLg,
    float* __restrict__ C, int AM, int N, int K)
{
    gemm2_body(AHg, ALg, BHg, BLg, C, AM, N, K, blockIdx.y * 128, blockIdx.x * 128);
}

__global__ __launch_bounds__(256, 2) void gemm2_kv(
    const uint32_t* __restrict__ AHg, const uint32_t* __restrict__ ALg,
    const uint32_t* __restrict__ KHg, const uint32_t* __restrict__ KLg,
    const uint32_t* __restrict__ VHg, const uint32_t* __restrict__ VLg,
    float* __restrict__ Ck, float* __restrict__ Cv, int AM, int K)
{
    const bool isv = blockIdx.x >= 4;
    const int bx = isv ? (int)blockIdx.x - 4 : (int)blockIdx.x;
    gemm2_body(AHg, ALg, isv ? VHg : KHg, isv ? VLg : KLg,
               isv ? Cv : Ck, AM, 512, K, blockIdx.y * 128, bx * 128);
}

// ---------------------------------------------------------------------------
// Block reduce helper
// ---------------------------------------------------------------------------
__device__ __forceinline__ float block_sum_256(float v) {
    __shared__ float red[8];
#pragma unroll
    for (int o = 16; o > 0; o >>= 1) v += __shfl_xor_sync(0xffffffffu, v, o);
    const int lane = threadIdx.x & 31, wid = threadIdx.x >> 5;
    if (lane == 0) red[wid] = v;
    __syncthreads();
    float tot = 0.f;
    if (threadIdx.x < 8) tot = red[threadIdx.x];
#pragma unroll
    for (int o = 4; o > 0; o >>= 1) tot += __shfl_xor_sync(0xffffffffu, tot, o);
    return tot;
}

// ---------------------------------------------------------------------------
// Q: RMSNorm(2048)+RoPE -> packed bf16x2 planes [b,h,s,dpair]
// ---------------------------------------------------------------------------
__global__ __launch_bounds__(256) void q_norm_rope(
    const float* __restrict__ qraw, const float* __restrict__ qw,
    const float* __restrict__ cosb, const float* __restrict__ sinb,
    uint32_t* __restrict__ QH, uint32_t* __restrict__ QL)
{
    const int r = blockIdx.x;
    const int b = r >> 10, s = r & 1023;
    const float* row = qraw + (size_t)r * 2048;

    float ss = 0.f;
    for (int d = threadIdx.x; d < 2048; d += 256) { float x = row[d]; ss += x * x; }
    float tot = block_sum_256(ss);
    __shared__ float s_inv;
    if (threadIdx.x == 0) s_inv = rsqrtf(tot * (1.f / 2048.f) + 1e-6f);
    __syncthreads();
    const float inv = s_inv;

    const float* cs = cosb + (size_t)r * 64;
    const float* sn = sinb + (size_t)r * 64;

    for (int p = threadIdx.x; p < 1024; p += 256) {
        const int h = p >> 5, hdp = p & 31;
        float o2[2];
#pragma unroll
        for (int j = 0; j < 2; j++) {
            const int hd = 2 * hdp + j, d = h * 64 + hd;
            float val = row[d] * inv * qw[d];
            const int pd = (hd < 32) ? d + 32 : d - 32;
            float pv = row[pd] * inv * qw[pd];
            float rot = (hd < 32) ? -pv : pv;
            o2[j] = val * cs[hd] + rot * sn[hd];
        }
        const uint32_t hb = pack_hi(o2[0], o2[1]);
        const size_t oi = (((size_t)(b * NH_ + h)) * S_ + s) * 32 + hdp;
        QH[oi] = hb;
        QL[oi] = pack_lo(o2[0], o2[1], hb);
    }
}

// ---------------------------------------------------------------------------
// K: RMSNorm(512)+RoPE -> packed TRANSPOSED [b,hk,dpair,s]
// ---------------------------------------------------------------------------
__global__ __launch_bounds__(256) void k_norm_rope(
    const float* __restrict__ kraw, const float* __restrict__ kw,
    const float* __restrict__ cosb, const float* __restrict__ sinb,
    uint32_t* __restrict__ KH, uint32_t* __restrict__ KL)
{
    const int r = blockIdx.x;
    const int b = r >> 10, s = r & 1023;
    const float* row = kraw + (size_t)r * 512;

    float ss = 0.f;
    for (int d = threadIdx.x; d < 512; d += 256) { float x = row[d]; ss += x * x; }
    float tot = block_sum_256(ss);
    __shared__ float s_inv;
    if (threadIdx.x == 0) s_inv = rsqrtf(tot * (1.f / 512.f) + 1e-6f);
    __syncthreads();
    const float inv = s_inv;

    const float* cs = cosb + (size_t)r * 64;
    const float* sn = sinb + (size_t)r * 64;

    const int p = threadIdx.x;          // 256 pairs exactly
    const int h = p >> 5, hdp = p & 31;
    float o2[2];
#pragma unroll
    for (int j = 0; j < 2; j++) {
        const int hd = 2 * hdp + j, d = h * 64 + hd;
        float val = row[d] * inv * kw[d];
        const int pd = (hd < 32) ? d + 32 : d - 32;
        float pv = row[pd] * inv * kw[pd];
        float rot = (hd < 32) ? -pv : pv;
        o2[j] = val * cs[hd] + rot * sn[hd];
    }
    const uint32_t hb = pack_hi(o2[0], o2[1]);
    const size_t oi = (((size_t)(b * NKV_ + h)) * 32 + hdp) * S_ + s;
    KH[oi] = hb;
    KL[oi] = pack_lo(o2[0], o2[1], hb);
}

// ---------------------------------------------------------------------------
// V: pack along s-pairs -> [b,hk,spair,d]
// ---------------------------------------------------------------------------
__global__ __launch_bounds__(256) void pack_v(
    const float* __restrict__ vraw,
    uint32_t* __restrict__ VH, uint32_t* __restrict__ VL)
{
    const int i = blockIdx.x * 256 + threadIdx.x;   // < 524288
    const int d  = i & 63;
    const int sp = (i >> 6) & 511;
    const int hk = (i >> 15) & 7;
    const int b  = i >> 18;
    const float x = vraw[((size_t)(b * 1024 + 2 * sp)) * 512 + hk * 64 + d];
    const float y = vraw[((size_t)(b * 1024 + 2 * sp + 1)) * 512 + hk * 64 + d];
    const uint32_t h = pack_hi(x, y);
    VH[i] = h;
    VL[i] = pack_lo(x, y, h);
}

// ---------------------------------------------------------------------------
// Flash attention, bf16 m16n8k16 3-split.
// 128 threads, 64-query tile; warp w owns rows 16w..16w+15.
// K planes [dpair32][s64], V planes [spair32][d64], P packed [row64][kpair32].
// ---------------------------------------------------------------------------
#define PP 36
#define BPP 72
#define KPLANE_W (32 * BPP)            // 2304 words
#define FSTAGE_W (4 * KPLANE_W)        // 9216 words
#define FSTAGE_B (FSTAGE_W * 4)        // 36864 B
#define FLASH_SMEM (2 * FSTAGE_B + 2 * 64 * PP * 4)   // 92160 B

__global__ __launch_bounds__(128) void flash_bf16(
    const uint32_t* __restrict__ QH, const uint32_t* __restrict__ QL,
    const uint32_t* __restrict__ KH, const uint32_t* __restrict__ KL,
    const uint32_t* __restrict__ VH, const uint32_t* __restrict__ VL,
    float* __restrict__ ctx)
{
    extern __shared__ uint32_t fsm[];
    uint32_t* pH = fsm + 2 * FSTAGE_W;
    uint32_t* pL = pH + 64 * PP;

    const int tid = threadIdx.x, lane = tid & 31, warp = tid >> 5;
    const int g = lane >> 2, t = lane & 3;
    const int wm = warp * 16;
    const int qt = blockIdx.x, h = blockIdx.y, b = blockIdx.z, hk = h >> 2;

    uint32_t sbase;
    asm("{ .reg .u64 tt; cvta.to.shared.u64 tt, %1; cvt.u32.u64 %0, tt; }"
        : "=r"(sbase) : "l"(fsm));

    const uint32_t* kbH = KH + ((size_t)(b * NKV_ + hk)) * 32 * S_;   // [dpair][s]
    const uint32_t* kbL = KL + ((size_t)(b * NKV_ + hk)) * 32 * S_;
    const uint32_t* vbH = VH + ((size_t)(b * NKV_ + hk)) * 512 * 64;  // [spair][d]
    const uint32_t* vbL = VL + ((size_t)(b * NKV_ + hk)) * 512 * 64;

    // Q fragments (packed d-pairs) in registers
    uint32_t qa_h[4][4], qa_l[4][4];
    {
        const size_t qoff = (((size_t)(b * NH_ + h)) * S_ + qt * 64 + wm) * 32;
#pragma unroll
        for (int ks = 0; ks < 4; ks++) {
            qa_h[ks][0] = QH[qoff + g * 32 + ks * 8 + t];
            qa_h[ks][1] = QH[qoff + (g + 8) * 32 + ks * 8 + t];
            qa_h[ks][2] = QH[qoff + g * 32 + ks * 8 + t + 4];
            qa_h[ks][3] = QH[qoff + (g + 8) * 32 + ks * 8 + t + 4];
            qa_l[ks][0] = QL[qoff + g * 32 + ks * 8 + t];
            qa_l[ks][1] = QL[qoff + (g + 8) * 32 + ks * 8 + t];
            qa_l[ks][2] = QL[qoff + g * 32 + ks * 8 + t + 4];
            qa_l[ks][3] = QL[qoff + (g + 8) * 32 + ks * 8 + t + 4];
        }
    }

    float o[8][4];
#pragma unroll
    for (int nt = 0; nt < 8; nt++)
#pragma unroll
        for (int c = 0; c < 4; c++) o[nt][c] = 0.f;
    float m0 = -1e30f, m1 = -1e30f, l0 = 0.f, l1 = 0.f;

    const int ntiles = qt + 1;

    // tile loader: 2048 16B chunks over 4 planes, 16/thread
    auto load_tile = [&](int kt) {
        const uint32_t st = sbase + (kt & 1) * FSTAGE_B;
#pragma unroll
        for (int i = 0; i < 16; i++) {
            const int plane = i >> 2;
            const int chunk = (i & 3) * 128 + tid;   // 0..511
            const int row = chunk >> 4;              // 0..31
            const int ch = chunk & 15;
            const uint32_t dst = st + plane * (KPLANE_W * 4) + row * (BPP * 4) + ch * 16;
            const uint32_t* src;
            if (plane == 0)      src = kbH + (size_t)row * S_ + kt * 64 + ch * 4;
            else if (plane == 1) src = kbL + (size_t)row * S_ + kt * 64 + ch * 4;
            else if (plane == 2) src = vbH + (size_t)(kt * 32 + row) * 64 + ch * 4;
            else                 src = vbL + (size_t)(kt * 32 + row) * 64 + ch * 4;
            cp16(dst, src);
        }
    };

    load_tile(0);
    asm volatile("cp.async.commit_group;" ::: "memory");

    for (int kt = 0; kt < ntiles; kt++) {
        if (kt + 1 < ntiles) load_tile(kt + 1);
        asm volatile("cp.async.commit_group;" ::: "memory");
        asm volatile("cp.async.wait_group 1;" ::: "memory");
        __syncthreads();

        const uint32_t* kThs = fsm + (kt & 1) * FSTAGE_W;
        const uint32_t* kTls = kThs + KPLANE_W;
        const uint32_t* vhs  = kThs + 2 * KPLANE_W;
        const uint32_t* vls  = kThs + 3 * KPLANE_W;

        // ---- S = Q K^T (bf16 3-split, 4 ksteps of 16 d) ----
        float sf[8][4];
#pragma unroll
        for (int nt = 0; nt < 8; nt++)
#pragma unroll
            for (int c = 0; c < 4; c++) sf[nt][c] = 0.f;

#pragma unroll
        for (int nt = 0; nt < 8; nt++) {
#pragma unroll
            for (int ks = 0; ks < 4; ks++) {
                const uint32_t bh0 = kThs[(ks * 8 + t) * BPP + 8 * nt + g];
                const uint32_t bh1 = kThs[(ks * 8 + t + 4) * BPP + 8 * nt + g];
                const uint32_t bl0 = kTls[(ks * 8 + t) * BPP + 8 * nt + g];
                const uint32_t bl1 = kTls[(ks * 8 + t + 4) * BPP + 8 * nt + g];
                float* cc = sf[nt];
                mma_bf16(cc[0], cc[1], cc[2], cc[3],
                         qa_h[ks][0], qa_h[ks][1], qa_h[ks][2], qa_h[ks][3], bh0, bh1);
                mma_bf16(cc[0], cc[1], cc[2], cc[3],
                         qa_h[ks][0], qa_h[ks][1], qa_h[ks][2], qa_h[ks][3], bl0, bl1);
                mma_bf16(cc[0], cc[1], cc[2], cc[3],
                         qa_l[ks][0], qa_l[ks][1], qa_l[ks][2], qa_l[ks][3], bh0, bh1);
            }
        }

        // ---- online softmax ----
        const bool diag = (kt == qt);
        float mn0 = m0, mn1 = m1;
#pragma unroll
        for (int nt = 0; nt < 8; nt++) {
#pragma unroll
            for (int c = 0; c < 4; c++) {
                float v = sf[nt][c] * 0.125f;
                const int colloc = nt * 8 + 2 * t + (c & 1);
                const int rowloc = wm + g + ((c >= 2) ? 8 : 0);
                if (diag && colloc > rowloc) v = -1e30f;
                sf[nt][c] = v;
                if (c < 2) mn0 = fmaxf(mn0, v);
                else       mn1 = fmaxf(mn1, v);
            }
        }
        mn0 = fmaxf(mn0, __shfl_xor_sync(0xffffffffu, mn0, 1));
        mn0 = fmaxf(mn0, __shfl_xor_sync(0xffffffffu, mn0, 2));
        mn1 = fmaxf(mn1, __shfl_xor_sync(0xffffffffu, mn1, 1));
        mn1 = fmaxf(mn1, __shfl_xor_sync(0xffffffffu, mn1, 2));

        const float sc0 = __expf(m0 - mn0);
        const float sc1 = __expf(m1 - mn1);
        m0 = mn0; m1 = mn1;
        l0 *= sc0; l1 *= sc1;
#pragma unroll
        for (int nt = 0; nt < 8; nt++) {
            o[nt][0] *= sc0; o[nt][1] *= sc0;
            o[nt][2] *= sc1; o[nt][3] *= sc1;
        }

        // P = exp(S - m); pack bf16x2 (cols 2t,2t+1) to smem
        float ps0 = 0.f, ps1 = 0.f;
#pragma unroll
        for (int nt = 0; nt < 8; nt++) {
            float p0 = __expf(sf[nt][0] - mn0);
            float p1 = __expf(sf[nt][1] - mn0);
            float p2 = __expf(sf[nt][2] - mn1);
            float p3 = __expf(sf[nt][3] - mn1);
            ps0 += p0 + p1;
            ps1 += p2 + p3;
            const uint32_t h01 = pack_hi(p0, p1);
            const uint32_t h23 = pack_hi(p2, p3);
            const int kp = nt * 4 + t;
            pH[(wm + g) * PP + kp] = h01;
            pH[(wm + g + 8) * PP + kp] = h23;
            pL[(wm + g) * PP + kp] = pack_lo(p0, p1, h01);
            pL[(wm + g + 8) * PP + kp] = pack_lo(p2, p3, h23);
        }
        ps0 += __shfl_xor_sync(0xffffffffu, ps0, 1);
        ps0 += __shfl_xor_sync(0xffffffffu, ps0, 2);
        ps1 += __shfl_xor_sync(0xffffffffu, ps1, 1);
        ps1 += __shfl_xor_sync(0xffffffffu, ps1, 2);
        l0 += ps0; l1 += ps1;
        __syncwarp();

        // ---- O += P V (bf16 3-split, 4 ksteps of 16 s) ----
#pragma unroll
        for (int ks = 0; ks < 4; ks++) {
            uint32_t pa_h[4], pa_l[4];
            pa_h[0] = pH[(wm + g) * PP + ks * 8 + t];
            pa_h[1] = pH[(wm + g + 8) * PP + ks * 8 + t];
            pa_h[2] = pH[(wm + g) * PP + ks * 8 + t + 4];
            pa_h[3] = pH[(wm + g + 8) * PP + ks * 8 + t + 4];
            pa_l[0] = pL[(wm + g) * PP + ks * 8 + t];
            pa_l[1] = pL[(wm + g + 8) * PP + ks * 8 + t];
            pa_l[2] = pL[(wm + g) * PP + ks * 8 + t + 4];
            pa_l[3] = pL[(wm + g + 8) * PP + ks * 8 + t + 4];
#pragma unroll
            for (int nt = 0; nt < 8; nt++) {
                const uint32_t bh0 = vhs[(ks * 8 + t) * BPP + 8 * nt + g];
                const uint32_t bh1 = vhs[(ks * 8 + t + 4) * BPP + 8 * nt + g];
                const uint32_t bl0 = vls[(ks * 8 + t) * BPP + 8 * nt + g];
                const uint32_t bl1 = vls[(ks * 8 + t + 4) * BPP + 8 * nt + g];
                float* cc = o[nt];
                mma_bf16(cc[0], cc[1], cc[2], cc[3],
                         pa_h[0], pa_h[1], pa_h[2], pa_h[3], bh0, bh1);
                mma_bf16(cc[0], cc[1], cc[2], cc[3],
                         pa_l[0], pa_l[1], pa_l[2], pa_l[3], bh0, bh1);
                mma_bf16(cc[0], cc[1], cc[2], cc[3],
                         pa_h[0], pa_h[1], pa_h[2], pa_h[3], bl0, bl1);
            }
        }
        __syncthreads();   // protect stage before next cp.async overwrite
    }

    // ---- epilogue ----
    const float inv0 = 1.f / l0, inv1 = 1.f / l1;
    float* crow0 = ctx + ((size_t)(b * S_ + qt * 64 + wm + g)) * 2048 + h * 64;
    float* crow1 = crow0 + (size_t)8 * 2048;
#pragma unroll
    for (int nt = 0; nt < 8; nt++) {
        const int col = nt * 8 + 2 * t;
        *reinterpret_cast<float2*>(crow0 + col) =
            make_float2(o[nt][0] * inv0, o[nt][1] * inv0);
        *reinterpret_cast<float2*>(crow1 + col) =
            make_float2(o[nt][2] * inv1, o[nt][3] * inv1);
    }
}

// ---------------------------------------------------------------------------
// Launch
// ---------------------------------------------------------------------------
extern "C" void kernel_launch(void* const* d_in, const int* in_sizes, int n_in,
                              void* d_out, int out_size)
{
    const float* X    = (const float*)d_in[0];
    const float* cosb = (const float*)d_in[1];
    const float* sinb = (const float*)d_in[2];
    // d_in[3] attention_mask unused (causal handled analytically)
    const float* wq = (const float*)d_in[4];
    const float* wk = (const float*)d_in[5];
    const float* wv = (const float*)d_in[6];
    const float* wo = (const float*)d_in[7];
    const float* qw = (const float*)d_in[8];
    const float* kw = (const float*)d_in[9];
    float* out = (float*)d_out;

    float *qraw, *kraw, *vraw, *ctx;
    uint32_t *QH, *QL, *KHp, *KLp, *VHp, *VLp;
    uint32_t *XAH, *XAL, *CAH, *CAL;
    uint32_t *WQH, *WQL, *WKH, *WKL, *WVH, *WVL, *WOH, *WOL;
    cudaGetSymbolAddress((void**)&qraw, g_qraw);
    cudaGetSymbolAddress((void**)&kraw, g_kraw);
    cudaGetSymbolAddress((void**)&vraw, g_vraw);
    cudaGetSymbolAddress((void**)&ctx,  g_ctx);
    cudaGetSymbolAddress((void**)&QH,   g_QH);
    cudaGetSymbolAddress((void**)&QL,   g_QL);
    cudaGetSymbolAddress((void**)&KHp,  g_KH);
    cudaGetSymbolAddress((void**)&KLp,  g_KL);
    cudaGetSymbolAddress((void**)&VHp,  g_VH);
    cudaGetSymbolAddress((void**)&VLp,  g_VL);
    cudaGetSymbolAddress((void**)&XAH,  g_XAH);
    cudaGetSymbolAddress((void**)&XAL,  g_XAL);
    cudaGetSymbolAddress((void**)&CAH,  g_CAH);
    cudaGetSymbolAddress((void**)&CAL,  g_CAL);
    cudaGetSymbolAddress((void**)&WQH,  g_WQH);
    cudaGetSymbolAddress((void**)&WQL,  g_WQL);
    cudaGetSymbolAddress((void**)&WKH,  g_WKH);
    cudaGetSymbolAddress((void**)&WKL,  g_WKL);
    cudaGetSymbolAddress((void**)&WVH,  g_WVH);
    cudaGetSymbolAddress((void**)&WVL,  g_WVL);
    cudaGetSymbolAddress((void**)&WOH,  g_WOH);
    cudaGetSymbolAddress((void**)&WOL,  g_WOL);

    cudaFuncSetAttribute(flash_bf16, cudaFuncAttributeMaxDynamicSharedMemorySize,
                         FLASH_SMEM);
    cudaFuncSetAttribute(gemm2, cudaFuncAttributeMaxDynamicSharedMemorySize, G2_SMEM);
    cudaFuncSetAttribute(gemm2_kv, cudaFuncAttributeMaxDynamicSharedMemorySize, G2_SMEM);

    // prep: pack operands
    transpose_pack<<<dim3(64, 32), 256>>>(X, XAH, XAL, 2048, 2048);
    pack_rows<<<8192, 256>>>(wq, WQH, WQL, 2048, 1024 * 2048);
    pack_rows<<<2048, 256>>>(wk, WKH, WKL, 512, 1024 * 512);
    pack_rows<<<2048, 256>>>(wv, WVH, WVL, 512, 1024 * 512);
    pack_rows<<<8192, 256>>>(wo, WOH, WOL, 2048, 1024 * 2048);

    // projections
    gemm2<<<dim3(16, 16), 256, G2_SMEM>>>(XAH, XAL, WQH, WQL, qraw, 2048, 2048, 2048);
    gemm2_kv<<<dim3(8, 16), 256, G2_SMEM>>>(XAH, XAL, WKH, WKL, WVH, WVL,
                                            kraw, vraw, 2048, 2048);

    q_norm_rope<<<M_, 256>>>(qraw, qw, cosb, sinb, QH, QL);
    k_norm_rope<<<M_, 256>>>(kraw, kw, cosb, sinb, KHp, KLp);
    pack_v<<<2048, 256>>>(vraw, VHp, VLp);

    flash_bf16<<<dim3(16, NH_, B_), 128, FLASH_SMEM>>>(QH, QL, KHp, KLp, VHp, VLp, ctx);

    // output projection
    transpose_pack<<<dim3(64, 32), 256>>>(ctx, CAH, CAL, 2048, 2048);
    gemm2<<<dim3(16, 16), 256, G2_SMEM>>>(CAH, CAL, WOH, WOL, out, 2048, 2048, 2048);
}

// round 9
// speedup vs baseline: 4.5350x; 1.3267x over previous
#include <cuda_runtime.h>
#include <cuda_bf16.h>
#include <cstdint>

// Problem constants
#define B_  2
#define S_  1024
#define H_  2048
#define NH_ 32
#define NKV_ 8
#define HD_ 64
#define M_  2048

// ---------------------------------------------------------------------------
// Scratch (device globals)
// ---------------------------------------------------------------------------
__device__ float g_qraw[M_ * 2048];
__device__ float g_kraw[M_ * 512];
__device__ float g_vraw[M_ * 512];
__device__ float g_ctx[M_ * 2048];
// flash packed bf16x2 operands
__device__ uint32_t g_QH[M_ * 1024], g_QL[M_ * 1024];   // [b,h,s,dpair32]
__device__ uint32_t g_KHp[524288],   g_KLp[524288];     // [b,hk,dpair32,s1024]
__device__ uint32_t g_VHp[524288],   g_VLp[524288];     // [b,hk,spair512,d64]
// int8 GEMM operands: A planes [K/4][M] int8x4, W planes [K/4][N]
__device__ uint32_t g_A1[512 * 2048], g_A2[512 * 2048];   // X^T / ctx^T (reused)
__device__ uint32_t g_WQ1[512 * 2048], g_WQ2[512 * 2048];
__device__ uint32_t g_WK1[512 * 512],  g_WK2[512 * 512];
__device__ uint32_t g_WV1[512 * 512],  g_WV2[512 * 512];
__device__ uint32_t g_WO1[512 * 2048], g_WO2[512 * 2048];
// abs-max arrays (float; col maxes written via atomicMax on bits)
__device__ float g_mxA[2048];   // rows of X, then rows of ctx (reused)
__device__ float g_mxQ[2048], g_mxK[512], g_mxV[512], g_mxO[2048];

// ---------------------------------------------------------------------------
// helpers
// ---------------------------------------------------------------------------
__device__ __forceinline__ void mma_bf16(
    float& c0, float& c1, float& c2, float& c3,
    uint32_t a0, uint32_t a1, uint32_t a2, uint32_t a3,
    uint32_t b0, uint32_t b1)
{
    asm volatile(
        "mma.sync.aligned.m16n8k16.row.col.f32.bf16.bf16.f32 "
        "{%0,%1,%2,%3}, {%4,%5,%6,%7}, {%8,%9}, {%0,%1,%2,%3};\n"
        : "+f"(c0), "+f"(c1), "+f"(c2), "+f"(c3)
        : "r"(a0), "r"(a1), "r"(a2), "r"(a3), "r"(b0), "r"(b1));
}

__device__ __forceinline__ void mma_s8(
    int& c0, int& c1, int& c2, int& c3,
    uint32_t a0, uint32_t a1, uint32_t a2, uint32_t a3,
    uint32_t b0, uint32_t b1)
{
    asm volatile(
        "mma.sync.aligned.m16n8k32.row.col.s32.s8.s8.s32 "
        "{%0,%1,%2,%3}, {%4,%5,%6,%7}, {%8,%9}, {%0,%1,%2,%3};\n"
        : "+r"(c0), "+r"(c1), "+r"(c2), "+r"(c3)
        : "r"(a0), "r"(a1), "r"(a2), "r"(a3), "r"(b0), "r"(b1));
}

__device__ __forceinline__ void cp16(uint32_t dst, const void* src) {
    asm volatile("cp.async.cg.shared.global [%0], [%1], 16;" :: "r"(dst), "l"(src));
}

__device__ __forceinline__ uint32_t pack_hi(float x, float y) {
    __nv_bfloat162 h = __floats2bfloat162_rn(x, y);
    return *reinterpret_cast<uint32_t*>(&h);
}
__device__ __forceinline__ uint32_t pack_lo(float x, float y, uint32_t hi) {
    __nv_bfloat162 h = *reinterpret_cast<__nv_bfloat162*>(&hi);
    float lx = x - __bfloat162float(h.x);
    float ly = y - __bfloat162float(h.y);
    __nv_bfloat162 l = __floats2bfloat162_rn(lx, ly);
    return *reinterpret_cast<uint32_t*>(&l);
}

// int8 quant helpers: scale S = 2^e with mx = f*2^e, f in [0.5,1)
__device__ __forceinline__ float quant_r127(float mx) {
    int e; frexpf(mx, &e);
    return 127.f * exp2f((float)(-e));
}
__device__ __forceinline__ float scl(float mx) {
    int e; frexpf(mx, &e);
    return exp2f((float)e) * (1.f / 127.f);
}
__device__ __forceinline__ void quant2(float x, float r127, int& q1, int& q2) {
    float a1 = rintf(x * r127);
    float r = fmaf(x, r127, -a1);
    float a2 = rintf(r * 256.f);
    a2 = fminf(fmaxf(a2, -127.f), 127.f);
    q1 = (int)a1; q2 = (int)a2;
}
__device__ __forceinline__ uint32_t pack4(int a, int b, int c, int d) {
    return (uint32_t)(a & 0xff) | ((uint32_t)(b & 0xff) << 8) |
           ((uint32_t)(c & 0xff) << 16) | ((uint32_t)(d & 0xff) << 24);
}

// ---------------------------------------------------------------------------
// reductions
// ---------------------------------------------------------------------------
__device__ __forceinline__ float block_sum_256(float v) {
    __shared__ float red[8];
#pragma unroll
    for (int o = 16; o > 0; o >>= 1) v += __shfl_xor_sync(0xffffffffu, v, o);
    const int lane = threadIdx.x & 31, wid = threadIdx.x >> 5;
    if (lane == 0) red[wid] = v;
    __syncthreads();
    float tot = 0.f;
    if (threadIdx.x < 8) tot = red[threadIdx.x];
#pragma unroll
    for (int o = 4; o > 0; o >>= 1) tot += __shfl_xor_sync(0xffffffffu, tot, o);
    return tot;
}

__device__ __forceinline__ float block_max_256(float v) {
    __shared__ float red[8];
#pragma unroll
    for (int o = 16; o > 0; o >>= 1) v = fmaxf(v, __shfl_xor_sync(0xffffffffu, v, o));
    const int lane = threadIdx.x & 31, wid = threadIdx.x >> 5;
    if (lane == 0) red[wid] = v;
    __syncthreads();
    float tot = 0.f;
    if (threadIdx.x < 8) tot = red[threadIdx.x];
#pragma unroll
    for (int o = 4; o > 0; o >>= 1) tot = fmaxf(tot, __shfl_xor_sync(0xffffffffu, tot, o));
    return tot;
}

// ---------------------------------------------------------------------------
// scale prep
// ---------------------------------------------------------------------------
__global__ __launch_bounds__(256) void zero_f(float* p, int n) {
    const int i = blockIdx.x * 256 + threadIdx.x;
    if (i < n) p[i] = 0.f;
}

// per-row abs max of X[M][K]
__global__ __launch_bounds__(256) void rowmax(
    const float* __restrict__ X, float* __restrict__ mx, int K)
{
    const int r = blockIdx.x;
    float v = 0.f;
    for (int k = threadIdx.x; k < K; k += 256)
        v = fmaxf(v, fabsf(X[(size_t)r * K + k]));
    float tot = block_max_256(v);
    if (threadIdx.x == 0) mx[r] = tot;
}

// per-col abs max of W[K][N]; atomicMax on float bits (values >= 0)
__global__ __launch_bounds__(256) void colmax(
    const float* __restrict__ W, float* __restrict__ mx, int N)
{
    __shared__ float s[4][64];
    const int n0 = blockIdx.x * 64, k0 = blockIdx.y * 256;
    const int c = threadIdx.x & 63, r = threadIdx.x >> 6;
    float v = 0.f;
#pragma unroll 8
    for (int j = 0; j < 64; j++)
        v = fmaxf(v, fabsf(W[(size_t)(k0 + 4 * j + r) * N + n0 + c]));
    s[r][c] = v;
    __syncthreads();
    if (r == 0) {
        float m = fmaxf(fmaxf(s[0][c], s[1][c]), fmaxf(s[2][c], s[3][c]));
        atomicMax((unsigned int*)&mx[n0 + c], __float_as_uint(m));
    }
}

// ---------------------------------------------------------------------------
// quantize kernels
// ---------------------------------------------------------------------------
// X[M][K] -> A1/A2 [K/4][M] int8x4 (transpose + quant, per-row scale)
__global__ __launch_bounds__(256) void tquant(
    const float* __restrict__ X, const float* __restrict__ mxRow,
    uint32_t* __restrict__ A1, uint32_t* __restrict__ A2, int M, int K)
{
    __shared__ float t[64][33];
    const int m0 = blockIdx.x * 32, k0 = blockIdx.y * 64;
#pragma unroll
    for (int i = threadIdx.x; i < 32 * 64; i += 256) {
        const int ml = i >> 6, kl = i & 63;
        t[kl][ml] = X[(size_t)(m0 + ml) * K + k0 + kl];
    }
    __syncthreads();
#pragma unroll
    for (int i = threadIdx.x; i < 32 * 16; i += 256) {
        const int kql = i >> 5, ml = i & 31;
        const float r127 = quant_r127(mxRow[m0 + ml]);
        int q1[4], q2[4];
#pragma unroll
        for (int j = 0; j < 4; j++)
            quant2(t[4 * kql + j][ml], r127, q1[j], q2[j]);
        const size_t o = (size_t)(k0 / 4 + kql) * M + m0 + ml;
        A1[o] = pack4(q1[0], q1[1], q1[2], q1[3]);
        A2[o] = pack4(q2[0], q2[1], q2[2], q2[3]);
    }
}

// W[K][N] -> B1/B2 [K/4][N] int8x4 (per-col scale)
__global__ __launch_bounds__(256) void quant_w(
    const float* __restrict__ W, const float* __restrict__ mxCol,
    uint32_t* __restrict__ B1, uint32_t* __restrict__ B2, int N, int total)
{
    const int i = blockIdx.x * 256 + threadIdx.x;
    if (i >= total) return;
    const int kq = i / N, n = i - kq * N;
    const float r127 = quant_r127(mxCol[n]);
    int q1[4], q2[4];
#pragma unroll
    for (int j = 0; j < 4; j++)
        quant2(W[(size_t)(4 * kq + j) * N + n], r127, q1[j], q2[j]);
    B1[i] = pack4(q1[0], q1[1], q1[2], q1[3]);
    B2[i] = pack4(q2[0], q2[1], q2[2], q2[3]);
}

// ---------------------------------------------------------------------------
// int8 split GEMM: C[M,N] = A @ B.
// A planes [K/4][AM] int8x4, B planes [K/4][N]. 128x128 tile, BK=32,
// 4-stage cp.async, 256 threads (8 warps, 4x2 of 32x64 warp tiles).
// acc1 = A1B1; acc2 = A1B2 + A2B1 (both exact s32).
// C = sA[m]*sB[n]*(acc1 + acc2/256).
// ---------------------------------------------------------------------------
#define KPT 8
#define PITCH 132
#define PLANE_W (KPT * PITCH)
#define STG_W (4 * PLANE_W)
#define STG_BYTES (STG_W * 4)
#define G2_SMEM (4 * STG_BYTES)

__device__ __forceinline__ void gemm_i8_body(
    const uint32_t* __restrict__ A1g, const uint32_t* __restrict__ A2g,
    const uint32_t* __restrict__ B1g, const uint32_t* __restrict__ B2g,
    const float* __restrict__ mxRow, const float* __restrict__ mxCol,
    float* __restrict__ C, int AM, int N, int K, int brow, int bcol)
{
    extern __shared__ uint32_t sm2[];

    const int tid  = threadIdx.x;
    const int lane = tid & 31;
    const int warp = tid >> 5;
    const int gid  = lane >> 2;
    const int tig  = lane & 3;
    const int wm   = (warp & 3) * 32;
    const int wn   = (warp >> 2) * 64;

    uint32_t sbase;
    asm("{ .reg .u64 t; cvta.to.shared.u64 t, %1; cvt.u32.u64 %0, t; }"
        : "=r"(sbase) : "l"(sm2));

    const int NK = K >> 5;          // 32 k per tile
    const int l_row = tid >> 5;     // kquad row 0..7
    const int l_ch  = tid & 31;

    auto load_stage = [&](int kt) {
        const uint32_t st = sbase + (kt & 3) * STG_BYTES;
        const size_t kqg = (size_t)(kt * KPT + l_row);
        const size_t aoff = kqg * AM + brow + l_ch * 4;
        const size_t boff = kqg * N + bcol + l_ch * 4;
        const uint32_t d0 = st + l_row * (PITCH * 4) + l_ch * 16;
        cp16(d0,                       A1g + aoff);
        cp16(d0 + PLANE_W * 4,         A2g + aoff);
        cp16(d0 + 2 * (PLANE_W * 4),   B1g + boff);
        cp16(d0 + 3 * (PLANE_W * 4),   B2g + boff);
    };

    int c1[2][8][4], c2[2][8][4];
#pragma unroll
    for (int i = 0; i < 2; i++)
#pragma unroll
        for (int j = 0; j < 8; j++)
#pragma unroll
            for (int v = 0; v < 4; v++) { c1[i][j][v] = 0; c2[i][j][v] = 0; }

    load_stage(0);
    asm volatile("cp.async.commit_group;" ::: "memory");
    load_stage(1);
    asm volatile("cp.async.commit_group;" ::: "memory");
    load_stage(2);
    asm volatile("cp.async.commit_group;" ::: "memory");

    for (int kt = 0; kt < NK; kt++) {
        asm volatile("cp.async.wait_group 2;" ::: "memory");
        __syncthreads();

        const uint32_t* A1s = sm2 + (kt & 3) * STG_W;
        const uint32_t* A2s = A1s + PLANE_W;
        const uint32_t* B1s = A1s + 2 * PLANE_W;
        const uint32_t* B2s = A1s + 3 * PLANE_W;

        uint32_t a1f[2][4], a2f[2][4];
#pragma unroll
        for (int mt = 0; mt < 2; mt++) {
            const int m0 = wm + mt * 16 + gid;
            a1f[mt][0] = A1s[tig * PITCH + m0];
            a1f[mt][1] = A1s[tig * PITCH + m0 + 8];
            a1f[mt][2] = A1s[(tig + 4) * PITCH + m0];
            a1f[mt][3] = A1s[(tig + 4) * PITCH + m0 + 8];
            a2f[mt][0] = A2s[tig * PITCH + m0];
            a2f[mt][1] = A2s[tig * PITCH + m0 + 8];
            a2f[mt][2] = A2s[(tig + 4) * PITCH + m0];
            a2f[mt][3] = A2s[(tig + 4) * PITCH + m0 + 8];
        }
#pragma unroll
        for (int nt = 0; nt < 8; nt++) {
            const int n0 = wn + nt * 8 + gid;
            const uint32_t b10 = B1s[tig * PITCH + n0];
            const uint32_t b11 = B1s[(tig + 4) * PITCH + n0];
            const uint32_t b20 = B2s[tig * PITCH + n0];
            const uint32_t b21 = B2s[(tig + 4) * PITCH + n0];
#pragma unroll
            for (int mt = 0; mt < 2; mt++) {
                int* p1 = c1[mt][nt];
                int* p2 = c2[mt][nt];
                mma_s8(p1[0], p1[1], p1[2], p1[3],
                       a1f[mt][0], a1f[mt][1], a1f[mt][2], a1f[mt][3], b10, b11);
                mma_s8(p2[0], p2[1], p2[2], p2[3],
                       a1f[mt][0], a1f[mt][1], a1f[mt][2], a1f[mt][3], b20, b21);
                mma_s8(p2[0], p2[1], p2[2], p2[3],
                       a2f[mt][0], a2f[mt][1], a2f[mt][2], a2f[mt][3], b10, b11);
            }
        }

        __syncthreads();
        if (kt + 3 < NK) load_stage(kt + 3);
        asm volatile("cp.async.commit_group;" ::: "memory");
    }

    // epilogue: apply scales
#pragma unroll
    for (int mt = 0; mt < 2; mt++) {
        const int r0 = brow + wm + mt * 16 + gid;
        const float sr0 = scl(mxRow[r0]);
        const float sr1 = scl(mxRow[r0 + 8]);
#pragma unroll
        for (int nt = 0; nt < 8; nt++) {
            const int col = bcol + wn + nt * 8 + 2 * tig;
            const float sc0 = scl(mxCol[col]);
            const float sc1 = scl(mxCol[col + 1]);
            const int* p1 = c1[mt][nt];
            const int* p2 = c2[mt][nt];
            const float v0 = (float)p1[0] + (float)p2[0] * (1.f / 256.f);
            const float v1 = (float)p1[1] + (float)p2[1] * (1.f / 256.f);
            const float v2 = (float)p1[2] + (float)p2[2] * (1.f / 256.f);
            const float v3 = (float)p1[3] + (float)p2[3] * (1.f / 256.f);
            *reinterpret_cast<float2*>(C + (size_t)r0 * N + col) =
                make_float2(sr0 * sc0 * v0, sr0 * sc1 * v1);
            *reinterpret_cast<float2*>(C + (size_t)(r0 + 8) * N + col) =
                make_float2(sr1 * sc0 * v2, sr1 * sc1 * v3);
        }
    }
}

__global__ __launch_bounds__(256) void gemm_i8(
    const uint32_t* __restrict__ A1g, const uint32_t* __restrict__ A2g,
    const uint32_t* __restrict__ B1g, const uint32_t* __restrict__ B2g,
    const float* __restrict__ mxRow, const float* __restrict__ mxCol,
    float* __restrict__ C, int AM, int N, int K)
{
    gemm_i8_body(A1g, A2g, B1g, B2g, mxRow, mxCol, C, AM, N, K,
                 blockIdx.y * 128, blockIdx.x * 128);
}

__global__ __launch_bounds__(256) void gemm_i8_kv(
    const uint32_t* __restrict__ A1g, const uint32_t* __restrict__ A2g,
    const uint32_t* __restrict__ K1g, const uint32_t* __restrict__ K2g,
    const uint32_t* __restrict__ V1g, const uint32_t* __restrict__ V2g,
    const float* __restrict__ mxRow,
    const float* __restrict__ mxK, const float* __restrict__ mxV,
    float* __restrict__ Ck, float* __restrict__ Cv, int AM, int K)
{
    const bool isv = blockIdx.x >= 4;
    const int bx = isv ? (int)blockIdx.x - 4 : (int)blockIdx.x;
    gemm_i8_body(A1g, A2g, isv ? V1g : K1g, isv ? V2g : K2g,
                 mxRow, isv ? mxV : mxK,
                 isv ? Cv : Ck, AM, 512, K, blockIdx.y * 128, bx * 128);
}

// ---------------------------------------------------------------------------
// Q: RMSNorm(2048)+RoPE -> packed bf16x2 planes [b,h,s,dpair]
// ---------------------------------------------------------------------------
__global__ __launch_bounds__(256) void q_norm_rope(
    const float* __restrict__ qraw, const float* __restrict__ qw,
    const float* __restrict__ cosb, const float* __restrict__ sinb,
    uint32_t* __restrict__ QH, uint32_t* __restrict__ QL)
{
    const int r = blockIdx.x;
    const int b = r >> 10, s = r & 1023;
    const float* row = qraw + (size_t)r * 2048;

    float ss = 0.f;
    for (int d = threadIdx.x; d < 2048; d += 256) { float x = row[d]; ss += x * x; }
    float tot = block_sum_256(ss);
    __shared__ float s_inv;
    if (threadIdx.x == 0) s_inv = rsqrtf(tot * (1.f / 2048.f) + 1e-6f);
    __syncthreads();
    const float inv = s_inv;

    const float* cs = cosb + (size_t)r * 64;
    const float* sn = sinb + (size_t)r * 64;

    for (int p = threadIdx.x; p < 1024; p += 256) {
        const int h = p >> 5, hdp = p & 31;
        float o2[2];
#pragma unroll
        for (int j = 0; j < 2; j++) {
            const int hd = 2 * hdp + j, d = h * 64 + hd;
            float val = row[d] * inv * qw[d];
            const int pd = (hd < 32) ? d + 32 : d - 32;
            float pv = row[pd] * inv * qw[pd];
            float rot = (hd < 32) ? -pv : pv;
            o2[j] = val * cs[hd] + rot * sn[hd];
        }
        const uint32_t hb = pack_hi(o2[0], o2[1]);
        const size_t oi = (((size_t)(b * NH_ + h)) * S_ + s) * 32 + hdp;
        QH[oi] = hb;
        QL[oi] = pack_lo(o2[0], o2[1], hb);
    }
}

// ---------------------------------------------------------------------------
// K: RMSNorm(512)+RoPE -> packed TRANSPOSED [b,hk,dpair,s]
// ---------------------------------------------------------------------------
__global__ __launch_bounds__(256) void k_norm_rope(
    const float* __restrict__ kraw, const float* __restrict__ kw,
    const float* __restrict__ cosb, const float* __restrict__ sinb,
    uint32_t* __restrict__ KH, uint32_t* __restrict__ KL)
{
    const int r = blockIdx.x;
    const int b = r >> 10, s = r & 1023;
    const float* row = kraw + (size_t)r * 512;

    float ss = 0.f;
    for (int d = threadIdx.x; d < 512; d += 256) { float x = row[d]; ss += x * x; }
    float tot = block_sum_256(ss);
    __shared__ float s_inv;
    if (threadIdx.x == 0) s_inv = rsqrtf(tot * (1.f / 512.f) + 1e-6f);
    __syncthreads();
    const float inv = s_inv;

    const float* cs = cosb + (size_t)r * 64;
    const float* sn = sinb + (size_t)r * 64;

    const int p = threadIdx.x;
    const int h = p >> 5, hdp = p & 31;
    float o2[2];
#pragma unroll
    for (int j = 0; j < 2; j++) {
        const int hd = 2 * hdp + j, d = h * 64 + hd;
        float val = row[d] * inv * kw[d];
        const int pd = (hd < 32) ? d + 32 : d - 32;
        float pv = row[pd] * inv * kw[pd];
        float rot = (hd < 32) ? -pv : pv;
        o2[j] = val * cs[hd] + rot * sn[hd];
    }
    const uint32_t hb = pack_hi(o2[0], o2[1]);
    const size_t oi = (((size_t)(b * NKV_ + h)) * 32 + hdp) * S_ + s;
    KH[oi] = hb;
    KL[oi] = pack_lo(o2[0], o2[1], hb);
}

// ---------------------------------------------------------------------------
// V: pack along s-pairs -> [b,hk,spair,d]
// ---------------------------------------------------------------------------
__global__ __launch_bounds__(256) void pack_v(
    const float* __restrict__ vraw,
    uint32_t* __restrict__ VH, uint32_t* __restrict__ VL)
{
    const int i = blockIdx.x * 256 + threadIdx.x;
    const int d  = i & 63;
    const int sp = (i >> 6) & 511;
    const int hk = (i >> 15) & 7;
    const int b  = i >> 18;
    const float x = vraw[((size_t)(b * 1024 + 2 * sp)) * 512 + hk * 64 + d];
    const float y = vraw[((size_t)(b * 1024 + 2 * sp + 1)) * 512 + hk * 64 + d];
    const uint32_t h = pack_hi(x, y);
    VH[i] = h;
    VL[i] = pack_lo(x, y, h);
}

// ---------------------------------------------------------------------------
// Flash attention, bf16 m16n8k16 3-split (R8, proven).
// ---------------------------------------------------------------------------
#define PP 36
#define BPP 72
#define KPLANE_W (32 * BPP)
#define FSTAGE_W (4 * KPLANE_W)
#define FSTAGE_B (FSTAGE_W * 4)
#define FLASH_SMEM (2 * FSTAGE_B + 2 * 64 * PP * 4)

__global__ __launch_bounds__(128) void flash_bf16(
    const uint32_t* __restrict__ QH, const uint32_t* __restrict__ QL,
    const uint32_t* __restrict__ KH, const uint32_t* __restrict__ KL,
    const uint32_t* __restrict__ VH, const uint32_t* __restrict__ VL,
    float* __restrict__ ctx)
{
    extern __shared__ uint32_t fsm[];
    uint32_t* pH = fsm + 2 * FSTAGE_W;
    uint32_t* pL = pH + 64 * PP;

    const int tid = threadIdx.x, lane = tid & 31, warp = tid >> 5;
    const int g = lane >> 2, t = lane & 3;
    const int wm = warp * 16;
    const int qt = blockIdx.x, h = blockIdx.y, b = blockIdx.z, hk = h >> 2;

    uint32_t sbase;
    asm("{ .reg .u64 tt; cvta.to.shared.u64 tt, %1; cvt.u32.u64 %0, tt; }"
        : "=r"(sbase) : "l"(fsm));

    const uint32_t* kbH = KH + ((size_t)(b * NKV_ + hk)) * 32 * S_;
    const uint32_t* kbL = KL + ((size_t)(b * NKV_ + hk)) * 32 * S_;
    const uint32_t* vbH = VH + ((size_t)(b * NKV_ + hk)) * 512 * 64;
    const uint32_t* vbL = VL + ((size_t)(b * NKV_ + hk)) * 512 * 64;

    uint32_t qa_h[4][4], qa_l[4][4];
    {
        const size_t qoff = (((size_t)(b * NH_ + h)) * S_ + qt * 64 + wm) * 32;
#pragma unroll
        for (int ks = 0; ks < 4; ks++) {
            qa_h[ks][0] = QH[qoff + g * 32 + ks * 8 + t];
            qa_h[ks][1] = QH[qoff + (g + 8) * 32 + ks * 8 + t];
            qa_h[ks][2] = QH[qoff + g * 32 + ks * 8 + t + 4];
            qa_h[ks][3] = QH[qoff + (g + 8) * 32 + ks * 8 + t + 4];
            qa_l[ks][0] = QL[qoff + g * 32 + ks * 8 + t];
            qa_l[ks][1] = QL[qoff + (g + 8) * 32 + ks * 8 + t];
            qa_l[ks][2] = QL[qoff + g * 32 + ks * 8 + t + 4];
            qa_l[ks][3] = QL[qoff + (g + 8) * 32 + ks * 8 + t + 4];
        }
    }

    float o[8][4];
#pragma unroll
    for (int nt = 0; nt < 8; nt++)
#pragma unroll
        for (int c = 0; c < 4; c++) o[nt][c] = 0.f;
    float m0 = -1e30f, m1 = -1e30f, l0 = 0.f, l1 = 0.f;

    const int ntiles = qt + 1;

    auto load_tile = [&](int kt) {
        const uint32_t st = sbase + (kt & 1) * FSTAGE_B;
#pragma unroll
        for (int i = 0; i < 16; i++) {
            const int plane = i >> 2;
            const int chunk = (i & 3) * 128 + tid;
            const int row = chunk >> 4;
            const int ch = chunk & 15;
            const uint32_t dst = st + plane * (KPLANE_W * 4) + row * (BPP * 4) + ch * 16;
            const uint32_t* src;
            if (plane == 0)      src = kbH + (size_t)row * S_ + kt * 64 + ch * 4;
            else if (plane == 1) src = kbL + (size_t)row * S_ + kt * 64 + ch * 4;
            else if (plane == 2) src = vbH + (size_t)(kt * 32 + row) * 64 + ch * 4;
            else                 src = vbL + (size_t)(kt * 32 + row) * 64 + ch * 4;
            cp16(dst, src);
        }
    };

    load_tile(0);
    asm volatile("cp.async.commit_group;" ::: "memory");

    for (int kt = 0; kt < ntiles; kt++) {
        if (kt + 1 < ntiles) load_tile(kt + 1);
        asm volatile("cp.async.commit_group;" ::: "memory");
        asm volatile("cp.async.wait_group 1;" ::: "memory");
        __syncthreads();

        const uint32_t* kThs = fsm + (kt & 1) * FSTAGE_W;
        const uint32_t* kTls = kThs + KPLANE_W;
        const uint32_t* vhs  = kThs + 2 * KPLANE_W;
        const uint32_t* vls  = kThs + 3 * KPLANE_W;

        float sf[8][4];
#pragma unroll
        for (int nt = 0; nt < 8; nt++)
#pragma unroll
            for (int c = 0; c < 4; c++) sf[nt][c] = 0.f;

#pragma unroll
        for (int nt = 0; nt < 8; nt++) {
#pragma unroll
            for (int ks = 0; ks < 4; ks++) {
                const uint32_t bh0 = kThs[(ks * 8 + t) * BPP + 8 * nt + g];
                const uint32_t bh1 = kThs[(ks * 8 + t + 4) * BPP + 8 * nt + g];
                const uint32_t bl0 = kTls[(ks * 8 + t) * BPP + 8 * nt + g];
                const uint32_t bl1 = kTls[(ks * 8 + t + 4) * BPP + 8 * nt + g];
                float* cc = sf[nt];
                mma_bf16(cc[0], cc[1], cc[2], cc[3],
                         qa_h[ks][0], qa_h[ks][1], qa_h[ks][2], qa_h[ks][3], bh0, bh1);
                mma_bf16(cc[0], cc[1], cc[2], cc[3],
                         qa_h[ks][0], qa_h[ks][1], qa_h[ks][2], qa_h[ks][3], bl0, bl1);
                mma_bf16(cc[0], cc[1], cc[2], cc[3],
                         qa_l[ks][0], qa_l[ks][1], qa_l[ks][2], qa_l[ks][3], bh0, bh1);
            }
        }

        const bool diag = (kt == qt);
        float mn0 = m0, mn1 = m1;
#pragma unroll
        for (int nt = 0; nt < 8; nt++) {
#pragma unroll
            for (int c = 0; c < 4; c++) {
                float v = sf[nt][c] * 0.125f;
                const int colloc = nt * 8 + 2 * t + (c & 1);
                const int rowloc = wm + g + ((c >= 2) ? 8 : 0);
                if (diag && colloc > rowloc) v = -1e30f;
                sf[nt][c] = v;
                if (c < 2) mn0 = fmaxf(mn0, v);
                else       mn1 = fmaxf(mn1, v);
            }
        }
        mn0 = fmaxf(mn0, __shfl_xor_sync(0xffffffffu, mn0, 1));
        mn0 = fmaxf(mn0, __shfl_xor_sync(0xffffffffu, mn0, 2));
        mn1 = fmaxf(mn1, __shfl_xor_sync(0xffffffffu, mn1, 1));
        mn1 = fmaxf(mn1, __shfl_xor_sync(0xffffffffu, mn1, 2));

        const float sc0 = __expf(m0 - mn0);
        const float sc1 = __expf(m1 - mn1);
        m0 = mn0; m1 = mn1;
        l0 *= sc0; l1 *= sc1;
#pragma unroll
        for (int nt = 0; nt < 8; nt++) {
            o[nt][0] *= sc0; o[nt][1] *= sc0;
            o[nt][2] *= sc1; o[nt][3] *= sc1;
        }

        float ps0 = 0.f, ps1 = 0.f;
#pragma unroll
        for (int nt = 0; nt < 8; nt++) {
            float p0 = __expf(sf[nt][0] - mn0);
            float p1 = __expf(sf[nt][1] - mn0);
            float p2 = __expf(sf[nt][2] - mn1);
            float p3 = __expf(sf[nt][3] - mn1);
            ps0 += p0 + p1;
            ps1 += p2 + p3;
            const uint32_t h01 = pack_hi(p0, p1);
            const uint32_t h23 = pack_hi(p2, p3);
            const int kp = nt * 4 + t;
            pH[(wm + g) * PP + kp] = h01;
            pH[(wm + g + 8) * PP + kp] = h23;
            pL[(wm + g) * PP + kp] = pack_lo(p0, p1, h01);
            pL[(wm + g + 8) * PP + kp] = pack_lo(p2, p3, h23);
        }
        ps0 += __shfl_xor_sync(0xffffffffu, ps0, 1);
        ps0 += __shfl_xor_sync(0xffffffffu, ps0, 2);
        ps1 += __shfl_xor_sync(0xffffffffu, ps1, 1);
        ps1 += __shfl_xor_sync(0xffffffffu, ps1, 2);
        l0 += ps0; l1 += ps1;
        __syncwarp();

#pragma unroll
        for (int ks = 0; ks < 4; ks++) {
            uint32_t pa_h[4], pa_l[4];
            pa_h[0] = pH[(wm + g) * PP + ks * 8 + t];
            pa_h[1] = pH[(wm + g + 8) * PP + ks * 8 + t];
            pa_h[2] = pH[(wm + g) * PP + ks * 8 + t + 4];
            pa_h[3] = pH[(wm + g + 8) * PP + ks * 8 + t + 4];
            pa_l[0] = pL[(wm + g) * PP + ks * 8 + t];
            pa_l[1] = pL[(wm + g + 8) * PP + ks * 8 + t];
            pa_l[2] = pL[(wm + g) * PP + ks * 8 + t + 4];
            pa_l[3] = pL[(wm + g + 8) * PP + ks * 8 + t + 4];
#pragma unroll
            for (int nt = 0; nt < 8; nt++) {
                const uint32_t bh0 = vhs[(ks * 8 + t) * BPP + 8 * nt + g];
                const uint32_t bh1 = vhs[(ks * 8 + t + 4) * BPP + 8 * nt + g];
                const uint32_t bl0 = vls[(ks * 8 + t) * BPP + 8 * nt + g];
                const uint32_t bl1 = vls[(ks * 8 + t + 4) * BPP + 8 * nt + g];
                float* cc = o[nt];
                mma_bf16(cc[0], cc[1], cc[2], cc[3],
                         pa_h[0], pa_h[1], pa_h[2], pa_h[3], bh0, bh1);
                mma_bf16(cc[0], cc[1], cc[2], cc[3],
                         pa_l[0], pa_l[1], pa_l[2], pa_l[3], bh0, bh1);
                mma_bf16(cc[0], cc[1], cc[2], cc[3],
                         pa_h[0], pa_h[1], pa_h[2], pa_h[3], bl0, bl1);
            }
        }
        __syncthreads();
    }

    const float inv0 = 1.f / l0, inv1 = 1.f / l1;
    float* crow0 = ctx + ((size_t)(b * S_ + qt * 64 + wm + g)) * 2048 + h * 64;
    float* crow1 = crow0 + (size_t)8 * 2048;
#pragma unroll
    for (int nt = 0; nt < 8; nt++) {
        const int col = nt * 8 + 2 * t;
        *reinterpret_cast<float2*>(crow0 + col) =
            make_float2(o[nt][0] * inv0, o[nt][1] * inv0);
        *reinterpret_cast<float2*>(crow1 + col) =
            make_float2(o[nt][2] * inv1, o[nt][3] * inv1);
    }
}

// ---------------------------------------------------------------------------
// Launch
// ---------------------------------------------------------------------------
extern "C" void kernel_launch(void* const* d_in, const int* in_sizes, int n_in,
                              void* d_out, int out_size)
{
    const float* X    = (const float*)d_in[0];
    const float* cosb = (const float*)d_in[1];
    const float* sinb = (const float*)d_in[2];
    // d_in[3] attention_mask unused (causal handled analytically)
    const float* wq = (const float*)d_in[4];
    const float* wk = (const float*)d_in[5];
    const float* wv = (const float*)d_in[6];
    const float* wo = (const float*)d_in[7];
    const float* qw = (const float*)d_in[8];
    const float* kw = (const float*)d_in[9];
    float* out = (float*)d_out;

    float *qraw, *kraw, *vraw, *ctx;
    uint32_t *QH, *QL, *KHp, *KLp, *VHp, *VLp;
    uint32_t *A1, *A2, *WQ1, *WQ2, *WK1, *WK2, *WV1, *WV2, *WO1, *WO2;
    float *mxA, *mxQ, *mxK, *mxV, *mxO;
    cudaGetSymbolAddress((void**)&qraw, g_qraw);
    cudaGetSymbolAddress((void**)&kraw, g_kraw);
    cudaGetSymbolAddress((void**)&vraw, g_vraw);
    cudaGetSymbolAddress((void**)&ctx,  g_ctx);
    cudaGetSymbolAddress((void**)&QH,   g_QH);
    cudaGetSymbolAddress((void**)&QL,   g_QL);
    cudaGetSymbolAddress((void**)&KHp,  g_KHp);
    cudaGetSymbolAddress((void**)&KLp,  g_KLp);
    cudaGetSymbolAddress((void**)&VHp,  g_VHp);
    cudaGetSymbolAddress((void**)&VLp,  g_VLp);
    cudaGetSymbolAddress((void**)&A1,   g_A1);
    cudaGetSymbolAddress((void**)&A2,   g_A2);
    cudaGetSymbolAddress((void**)&WQ1,  g_WQ1);
    cudaGetSymbolAddress((void**)&WQ2,  g_WQ2);
    cudaGetSymbolAddress((void**)&WK1,  g_WK1);
    cudaGetSymbolAddress((void**)&WK2,  g_WK2);
    cudaGetSymbolAddress((void**)&WV1,  g_WV1);
    cudaGetSymbolAddress((void**)&WV2,  g_WV2);
    cudaGetSymbolAddress((void**)&WO1,  g_WO1);
    cudaGetSymbolAddress((void**)&WO2,  g_WO2);
    cudaGetSymbolAddress((void**)&mxA,  g_mxA);
    cudaGetSymbolAddress((void**)&mxQ,  g_mxQ);
    cudaGetSymbolAddress((void**)&mxK,  g_mxK);
    cudaGetSymbolAddress((void**)&mxV,  g_mxV);
    cudaGetSymbolAddress((void**)&mxO,  g_mxO);

    cudaFuncSetAttribute(flash_bf16, cudaFuncAttributeMaxDynamicSharedMemorySize,
                         FLASH_SMEM);
    cudaFuncSetAttribute(gemm_i8, cudaFuncAttributeMaxDynamicSharedMemorySize, G2_SMEM);
    cudaFuncSetAttribute(gemm_i8_kv, cudaFuncAttributeMaxDynamicSharedMemorySize, G2_SMEM);

    // ---- scale prep ----
    zero_f<<<8, 256>>>(mxQ, 2048);
    zero_f<<<2, 256>>>(mxK, 512);
    zero_f<<<2, 256>>>(mxV, 512);
    zero_f<<<8, 256>>>(mxO, 2048);

    rowmax<<<2048, 256>>>(X, mxA, 2048);
    colmax<<<dim3(32, 8), 256>>>(wq, mxQ, 2048);
    colmax<<<dim3(8, 8),  256>>>(wk, mxK, 512);
    colmax<<<dim3(8, 8),  256>>>(wv, mxV, 512);
    colmax<<<dim3(32, 8), 256>>>(wo, mxO, 2048);

    // ---- quantize ----
    tquant<<<dim3(64, 32), 256>>>(X, mxA, A1, A2, 2048, 2048);
    quant_w<<<4096, 256>>>(wq, mxQ, WQ1, WQ2, 2048, 512 * 2048);
    quant_w<<<1024, 256>>>(wk, mxK, WK1, WK2, 512, 512 * 512);
    quant_w<<<1024, 256>>>(wv, mxV, WV1, WV2, 512, 512 * 512);
    quant_w<<<4096, 256>>>(wo, mxO, WO1, WO2, 2048, 512 * 2048);

    // ---- projections (int8 tensor core) ----
    gemm_i8<<<dim3(16, 16), 256, G2_SMEM>>>(A1, A2, WQ1, WQ2, mxA, mxQ,
                                            qraw, 2048, 2048, 2048);
    gemm_i8_kv<<<dim3(8, 16), 256, G2_SMEM>>>(A1, A2, WK1, WK2, WV1, WV2,
                                              mxA, mxK, mxV, kraw, vraw, 2048, 2048);

    // ---- norm / rope / pack for flash ----
    q_norm_rope<<<M_, 256>>>(qraw, qw, cosb, sinb, QH, QL);
    k_norm_rope<<<M_, 256>>>(kraw, kw, cosb, sinb, KHp, KLp);
    pack_v<<<2048, 256>>>(vraw, VHp, VLp);

    flash_bf16<<<dim3(16, NH_, B_), 128, FLASH_SMEM>>>(QH, QL, KHp, KLp, VHp, VLp, ctx);

    // ---- output projection (reuse A planes + mxA for ctx) ----
    rowmax<<<2048, 256>>>(ctx, mxA, 2048);
    tquant<<<dim3(64, 32), 256>>>(ctx, mxA, A1, A2, 2048, 2048);
    gemm_i8<<<dim3(16, 16), 256, G2_SMEM>>>(A1, A2, WO1, WO2, mxA, mxO,
                                            out, 2048, 2048, 2048);
}

// round 10
// speedup vs baseline: 5.0990x; 1.1244x over previous
#include <cuda_runtime.h>
#include <cuda_bf16.h>
#include <cstdint>

// Problem constants
#define B_  2
#define S_  1024
#define H_  2048
#define NH_ 32
#define NKV_ 8
#define HD_ 64
#define M_  2048

// ---------------------------------------------------------------------------
// Scratch (device globals)
// ---------------------------------------------------------------------------
__device__ float g_qraw[M_ * 2048];
__device__ float g_kraw[M_ * 512];
__device__ float g_vraw[M_ * 512];
__device__ float g_ctx[M_ * 2048];
// flash packed bf16x2 operands
__device__ uint32_t g_QH[M_ * 1024], g_QL[M_ * 1024];   // [b,h,s,dpair32]
__device__ uint32_t g_KHp[524288],   g_KLp[524288];     // [b,hk,dpair32,s1024]
__device__ uint32_t g_VHp[524288],   g_VLp[524288];     // [b,hk,spair512,d64]
// int8 GEMM operands
__device__ uint32_t g_A1[512 * 2048], g_A2[512 * 2048];
__device__ uint32_t g_WQ1[512 * 2048], g_WQ2[512 * 2048];
__device__ uint32_t g_WK1[512 * 512],  g_WK2[512 * 512];
__device__ uint32_t g_WV1[512 * 512],  g_WV2[512 * 512];
__device__ uint32_t g_WO1[512 * 2048], g_WO2[512 * 2048];
// abs-max arrays
__device__ float g_mxA[2048];
__device__ float g_mxQ[2048], g_mxK[512], g_mxV[512], g_mxO[2048];

// ---------------------------------------------------------------------------
// helpers
// ---------------------------------------------------------------------------
__device__ __forceinline__ void mma_bf16(
    float& c0, float& c1, float& c2, float& c3,
    uint32_t a0, uint32_t a1, uint32_t a2, uint32_t a3,
    uint32_t b0, uint32_t b1)
{
    asm volatile(
        "mma.sync.aligned.m16n8k16.row.col.f32.bf16.bf16.f32 "
        "{%0,%1,%2,%3}, {%4,%5,%6,%7}, {%8,%9}, {%0,%1,%2,%3};\n"
        : "+f"(c0), "+f"(c1), "+f"(c2), "+f"(c3)
        : "r"(a0), "r"(a1), "r"(a2), "r"(a3), "r"(b0), "r"(b1));
}

__device__ __forceinline__ void mma_s8(
    int& c0, int& c1, int& c2, int& c3,
    uint32_t a0, uint32_t a1, uint32_t a2, uint32_t a3,
    uint32_t b0, uint32_t b1)
{
    asm volatile(
        "mma.sync.aligned.m16n8k32.row.col.s32.s8.s8.s32 "
        "{%0,%1,%2,%3}, {%4,%5,%6,%7}, {%8,%9}, {%0,%1,%2,%3};\n"
        : "+r"(c0), "+r"(c1), "+r"(c2), "+r"(c3)
        : "r"(a0), "r"(a1), "r"(a2), "r"(a3), "r"(b0), "r"(b1));
}

__device__ __forceinline__ void cp16(uint32_t dst, const void* src) {
    asm volatile("cp.async.cg.shared.global [%0], [%1], 16;" :: "r"(dst), "l"(src));
}

__device__ __forceinline__ uint32_t pack_hi(float x, float y) {
    __nv_bfloat162 h = __floats2bfloat162_rn(x, y);
    return *reinterpret_cast<uint32_t*>(&h);
}
__device__ __forceinline__ uint32_t pack_lo(float x, float y, uint32_t hi) {
    __nv_bfloat162 h = *reinterpret_cast<__nv_bfloat162*>(&hi);
    float lx = x - __bfloat162float(h.x);
    float ly = y - __bfloat162float(h.y);
    __nv_bfloat162 l = __floats2bfloat162_rn(lx, ly);
    return *reinterpret_cast<uint32_t*>(&l);
}

__device__ __forceinline__ float quant_r127(float mx) {
    int e; frexpf(mx, &e);
    return 127.f * exp2f((float)(-e));
}
__device__ __forceinline__ float scl(float mx) {
    int e; frexpf(mx, &e);
    return exp2f((float)e) * (1.f / 127.f);
}
__device__ __forceinline__ void quant2(float x, float r127, int& q1, int& q2) {
    float a1 = rintf(x * r127);
    float r = fmaf(x, r127, -a1);
    float a2 = rintf(r * 256.f);
    a2 = fminf(fmaxf(a2, -127.f), 127.f);
    q1 = (int)a1; q2 = (int)a2;
}
__device__ __forceinline__ uint32_t pack4(int a, int b, int c, int d) {
    return (uint32_t)(a & 0xff) | ((uint32_t)(b & 0xff) << 8) |
           ((uint32_t)(c & 0xff) << 16) | ((uint32_t)(d & 0xff) << 24);
}

// ---------------------------------------------------------------------------
// reductions
// ---------------------------------------------------------------------------
__device__ __forceinline__ float block_sum_256(float v) {
    __shared__ float red[8];
#pragma unroll
    for (int o = 16; o > 0; o >>= 1) v += __shfl_xor_sync(0xffffffffu, v, o);
    const int lane = threadIdx.x & 31, wid = threadIdx.x >> 5;
    if (lane == 0) red[wid] = v;
    __syncthreads();
    float tot = 0.f;
    if (threadIdx.x < 8) tot = red[threadIdx.x];
#pragma unroll
    for (int o = 4; o > 0; o >>= 1) tot += __shfl_xor_sync(0xffffffffu, tot, o);
    return tot;
}

__device__ __forceinline__ float block_max_256(float v) {
    __shared__ float red[8];
#pragma unroll
    for (int o = 16; o > 0; o >>= 1) v = fmaxf(v, __shfl_xor_sync(0xffffffffu, v, o));
    const int lane = threadIdx.x & 31, wid = threadIdx.x >> 5;
    if (lane == 0) red[wid] = v;
    __syncthreads();
    float tot = 0.f;
    if (threadIdx.x < 8) tot = red[threadIdx.x];
#pragma unroll
    for (int o = 4; o > 0; o >>= 1) tot = fmaxf(tot, __shfl_xor_sync(0xffffffffu, tot, o));
    return tot;
}

// ---------------------------------------------------------------------------
// fused scale prep
// ---------------------------------------------------------------------------
__global__ __launch_bounds__(256) void zero_all(
    float* a, float* b, float* c, float* d)
{
    const int i = blockIdx.x * 256 + threadIdx.x;
    if (i < 2048) { a[i] = 0.f; d[i] = 0.f; }
    if (i < 512)  { b[i] = 0.f; c[i] = 0.f; }
}

// fused per-col abs max of all 4 weights (atomicMax on float bits, vals >= 0)
__global__ __launch_bounds__(256) void colmax_all(
    const float* __restrict__ wq, const float* __restrict__ wk,
    const float* __restrict__ wv, const float* __restrict__ wo,
    float* __restrict__ mxQ, float* __restrict__ mxK,
    float* __restrict__ mxV, float* __restrict__ mxO)
{
    __shared__ float s[4][64];
    int bx = blockIdx.x;
    const float* W; float* mx; int N;
    if (bx < 32)      { W = wq; mx = mxQ; N = 2048; }
    else if (bx < 40) { W = wk; mx = mxK; N = 512; bx -= 32; }
    else if (bx < 48) { W = wv; mx = mxV; N = 512; bx -= 40; }
    else              { W = wo; mx = mxO; N = 2048; bx -= 48; }
    const int n0 = bx * 64, k0 = blockIdx.y * 256;
    const int c = threadIdx.x & 63, r = threadIdx.x >> 6;
    float v = 0.f;
#pragma unroll 8
    for (int j = 0; j < 64; j++)
        v = fmaxf(v, fabsf(W[(size_t)(k0 + 4 * j + r) * N + n0 + c]));
    s[r][c] = v;
    __syncthreads();
    if (r == 0) {
        float m = fmaxf(fmaxf(s[0][c], s[1][c]), fmaxf(s[2][c], s[3][c]));
        atomicMax((unsigned int*)&mx[n0 + c], __float_as_uint(m));
    }
}

// fused quantize of all 4 weights: [K/4][N] int8x4 planes
__global__ __launch_bounds__(256) void quant_w_all(
    const float* __restrict__ wq, const float* __restrict__ wk,
    const float* __restrict__ wv, const float* __restrict__ wo,
    const float* __restrict__ mxQ, const float* __restrict__ mxK,
    const float* __restrict__ mxV, const float* __restrict__ mxO,
    uint32_t* __restrict__ WQ1, uint32_t* __restrict__ WQ2,
    uint32_t* __restrict__ WK1, uint32_t* __restrict__ WK2,
    uint32_t* __restrict__ WV1, uint32_t* __restrict__ WV2,
    uint32_t* __restrict__ WO1, uint32_t* __restrict__ WO2)
{
    int i = blockIdx.x * 256 + threadIdx.x;   // < 2621440
    const float* W; const float* mx; uint32_t *B1, *B2; int N;
    if (i < 1048576)      { W = wq; mx = mxQ; B1 = WQ1; B2 = WQ2; N = 2048; }
    else if (i < 1310720) { W = wk; mx = mxK; B1 = WK1; B2 = WK2; N = 512; i -= 1048576; }
    else if (i < 1572864) { W = wv; mx = mxV; B1 = WV1; B2 = WV2; N = 512; i -= 1310720; }
    else                  { W = wo; mx = mxO; B1 = WO1; B2 = WO2; N = 2048; i -= 1572864; }
    const int kq = i / N, n = i - kq * N;
    const float r127 = quant_r127(mx[n]);
    int q1[4], q2[4];
#pragma unroll
    for (int j = 0; j < 4; j++)
        quant2(W[(size_t)(4 * kq + j) * N + n], r127, q1[j], q2[j]);
    B1[i] = pack4(q1[0], q1[1], q1[2], q1[3]);
    B2[i] = pack4(q2[0], q2[1], q2[2], q2[3]);
}

// per-row abs max of X[M][K]
__global__ __launch_bounds__(256) void rowmax(
    const float* __restrict__ X, float* __restrict__ mx, int K)
{
    const int r = blockIdx.x;
    float v = 0.f;
    for (int k = threadIdx.x; k < K; k += 256)
        v = fmaxf(v, fabsf(X[(size_t)r * K + k]));
    float tot = block_max_256(v);
    if (threadIdx.x == 0) mx[r] = tot;
}

// X[M][K] -> A1/A2 [K/4][M] int8x4 (transpose + quant, per-row scale)
__global__ __launch_bounds__(256) void tquant(
    const float* __restrict__ X, const float* __restrict__ mxRow,
    uint32_t* __restrict__ A1, uint32_t* __restrict__ A2, int M, int K)
{
    __shared__ float t[64][33];
    const int m0 = blockIdx.x * 32, k0 = blockIdx.y * 64;
#pragma unroll
    for (int i = threadIdx.x; i < 32 * 64; i += 256) {
        const int ml = i >> 6, kl = i & 63;
        t[kl][ml] = X[(size_t)(m0 + ml) * K + k0 + kl];
    }
    __syncthreads();
#pragma unroll
    for (int i = threadIdx.x; i < 32 * 16; i += 256) {
        const int kql = i >> 5, ml = i & 31;
        const float r127 = quant_r127(mxRow[m0 + ml]);
        int q1[4], q2[4];
#pragma unroll
        for (int j = 0; j < 4; j++)
            quant2(t[4 * kql + j][ml], r127, q1[j], q2[j]);
        const size_t o = (size_t)(k0 / 4 + kql) * M + m0 + ml;
        A1[o] = pack4(q1[0], q1[1], q1[2], q1[3]);
        A2[o] = pack4(q2[0], q2[1], q2[2], q2[3]);
    }
}

// ---------------------------------------------------------------------------
// int8 split GEMM body (R9, proven)
// ---------------------------------------------------------------------------
#define KPT 8
#define PITCH 132
#define PLANE_W (KPT * PITCH)
#define STG_W (4 * PLANE_W)
#define STG_BYTES (STG_W * 4)
#define G2_SMEM (4 * STG_BYTES)

__device__ __forceinline__ void gemm_i8_body(
    const uint32_t* __restrict__ A1g, const uint32_t* __restrict__ A2g,
    const uint32_t* __restrict__ B1g, const uint32_t* __restrict__ B2g,
    const float* __restrict__ mxRow, const float* __restrict__ mxCol,
    float* __restrict__ C, int AM, int N, int K, int brow, int bcol)
{
    extern __shared__ uint32_t sm2[];

    const int tid  = threadIdx.x;
    const int lane = tid & 31;
    const int warp = tid >> 5;
    const int gid  = lane >> 2;
    const int tig  = lane & 3;
    const int wm   = (warp & 3) * 32;
    const int wn   = (warp >> 2) * 64;

    uint32_t sbase;
    asm("{ .reg .u64 t; cvta.to.shared.u64 t, %1; cvt.u32.u64 %0, t; }"
        : "=r"(sbase) : "l"(sm2));

    const int NK = K >> 5;
    const int l_row = tid >> 5;
    const int l_ch  = tid & 31;

    auto load_stage = [&](int kt) {
        const uint32_t st = sbase + (kt & 3) * STG_BYTES;
        const size_t kqg = (size_t)(kt * KPT + l_row);
        const size_t aoff = kqg * AM + brow + l_ch * 4;
        const size_t boff = kqg * N + bcol + l_ch * 4;
        const uint32_t d0 = st + l_row * (PITCH * 4) + l_ch * 16;
        cp16(d0,                       A1g + aoff);
        cp16(d0 + PLANE_W * 4,         A2g + aoff);
        cp16(d0 + 2 * (PLANE_W * 4),   B1g + boff);
        cp16(d0 + 3 * (PLANE_W * 4),   B2g + boff);
    };

    int c1[2][8][4], c2[2][8][4];
#pragma unroll
    for (int i = 0; i < 2; i++)
#pragma unroll
        for (int j = 0; j < 8; j++)
#pragma unroll
            for (int v = 0; v < 4; v++) { c1[i][j][v] = 0; c2[i][j][v] = 0; }

    load_stage(0);
    asm volatile("cp.async.commit_group;" ::: "memory");
    load_stage(1);
    asm volatile("cp.async.commit_group;" ::: "memory");
    load_stage(2);
    asm volatile("cp.async.commit_group;" ::: "memory");

    for (int kt = 0; kt < NK; kt++) {
        asm volatile("cp.async.wait_group 2;" ::: "memory");
        __syncthreads();

        const uint32_t* A1s = sm2 + (kt & 3) * STG_W;
        const uint32_t* A2s = A1s + PLANE_W;
        const uint32_t* B1s = A1s + 2 * PLANE_W;
        const uint32_t* B2s = A1s + 3 * PLANE_W;

        uint32_t a1f[2][4], a2f[2][4];
#pragma unroll
        for (int mt = 0; mt < 2; mt++) {
            const int m0 = wm + mt * 16 + gid;
            a1f[mt][0] = A1s[tig * PITCH + m0];
            a1f[mt][1] = A1s[tig * PITCH + m0 + 8];
            a1f[mt][2] = A1s[(tig + 4) * PITCH + m0];
            a1f[mt][3] = A1s[(tig + 4) * PITCH + m0 + 8];
            a2f[mt][0] = A2s[tig * PITCH + m0];
            a2f[mt][1] = A2s[tig * PITCH + m0 + 8];
            a2f[mt][2] = A2s[(tig + 4) * PITCH + m0];
            a2f[mt][3] = A2s[(tig + 4) * PITCH + m0 + 8];
        }
#pragma unroll
        for (int nt = 0; nt < 8; nt++) {
            const int n0 = wn + nt * 8 + gid;
            const uint32_t b10 = B1s[tig * PITCH + n0];
            const uint32_t b11 = B1s[(tig + 4) * PITCH + n0];
            const uint32_t b20 = B2s[tig * PITCH + n0];
            const uint32_t b21 = B2s[(tig + 4) * PITCH + n0];
#pragma unroll
            for (int mt = 0; mt < 2; mt++) {
                int* p1 = c1[mt][nt];
                int* p2 = c2[mt][nt];
                mma_s8(p1[0], p1[1], p1[2], p1[3],
                       a1f[mt][0], a1f[mt][1], a1f[mt][2], a1f[mt][3], b10, b11);
                mma_s8(p2[0], p2[1], p2[2], p2[3],
                       a1f[mt][0], a1f[mt][1], a1f[mt][2], a1f[mt][3], b20, b21);
                mma_s8(p2[0], p2[1], p2[2], p2[3],
                       a2f[mt][0], a2f[mt][1], a2f[mt][2], a2f[mt][3], b10, b11);
            }
        }

        __syncthreads();
        if (kt + 3 < NK) load_stage(kt + 3);
        asm volatile("cp.async.commit_group;" ::: "memory");
    }

#pragma unroll
    for (int mt = 0; mt < 2; mt++) {
        const int r0 = brow + wm + mt * 16 + gid;
        const float sr0 = scl(mxRow[r0]);
        const float sr1 = scl(mxRow[r0 + 8]);
#pragma unroll
        for (int nt = 0; nt < 8; nt++) {
            const int col = bcol + wn + nt * 8 + 2 * tig;
            const float sc0 = scl(mxCol[col]);
            const float sc1 = scl(mxCol[col + 1]);
            const int* p1 = c1[mt][nt];
            const int* p2 = c2[mt][nt];
            const float v0 = (float)p1[0] + (float)p2[0] * (1.f / 256.f);
            const float v1 = (float)p1[1] + (float)p2[1] * (1.f / 256.f);
            const float v2 = (float)p1[2] + (float)p2[2] * (1.f / 256.f);
            const float v3 = (float)p1[3] + (float)p2[3] * (1.f / 256.f);
            *reinterpret_cast<float2*>(C + (size_t)r0 * N + col) =
                make_float2(sr0 * sc0 * v0, sr0 * sc1 * v1);
            *reinterpret_cast<float2*>(C + (size_t)(r0 + 8) * N + col) =
                make_float2(sr1 * sc0 * v2, sr1 * sc1 * v3);
        }
    }
}

// fused Q + K + V projections in one launch: grid (24, 16)
__global__ __launch_bounds__(256) void gemm_i8_qkv(
    const uint32_t* __restrict__ A1g, const uint32_t* __restrict__ A2g,
    const uint32_t* __restrict__ Q1g, const uint32_t* __restrict__ Q2g,
    const uint32_t* __restrict__ K1g, const uint32_t* __restrict__ K2g,
    const uint32_t* __restrict__ V1g, const uint32_t* __restrict__ V2g,
    const float* __restrict__ mxRow,
    const float* __restrict__ mxQ, const float* __restrict__ mxK,
    const float* __restrict__ mxV,
    float* __restrict__ Cq, float* __restrict__ Ck, float* __restrict__ Cv)
{
    const int x = blockIdx.x;
    if (x < 16) {
        gemm_i8_body(A1g, A2g, Q1g, Q2g, mxRow, mxQ, Cq, 2048, 2048, 2048,
                     blockIdx.y * 128, x * 128);
    } else {
        const int xx = x - 16;
        const bool isv = xx >= 4;
        const int bx = xx & 3;
        gemm_i8_body(A1g, A2g, isv ? V1g : K1g, isv ? V2g : K2g,
                     mxRow, isv ? mxV : mxK, isv ? Cv : Ck,
                     2048, 512, 2048, blockIdx.y * 128, bx * 128);
    }
}

__global__ __launch_bounds__(256) void gemm_i8(
    const uint32_t* __restrict__ A1g, const uint32_t* __restrict__ A2g,
    const uint32_t* __restrict__ B1g, const uint32_t* __restrict__ B2g,
    const float* __restrict__ mxRow, const float* __restrict__ mxCol,
    float* __restrict__ C, int AM, int N, int K)
{
    gemm_i8_body(A1g, A2g, B1g, B2g, mxRow, mxCol, C, AM, N, K,
                 blockIdx.y * 128, blockIdx.x * 128);
}

// ---------------------------------------------------------------------------
// Fused norm/rope/pack: grid 6144
//   [0,2048)    q_norm_rope
//   [2048,4096) k_norm_rope
//   [4096,6144) pack_v
// ---------------------------------------------------------------------------
__global__ __launch_bounds__(256) void normpack_all(
    const float* __restrict__ qraw, const float* __restrict__ kraw,
    const float* __restrict__ vraw,
    const float* __restrict__ qw, const float* __restrict__ kw,
    const float* __restrict__ cosb, const float* __restrict__ sinb,
    uint32_t* __restrict__ QH, uint32_t* __restrict__ QL,
    uint32_t* __restrict__ KH, uint32_t* __restrict__ KL,
    uint32_t* __restrict__ VH, uint32_t* __restrict__ VL)
{
    const int blk = blockIdx.x;
    if (blk < 2048) {
        // ---- Q norm + rope ----
        const int r = blk;
        const int b = r >> 10, s = r & 1023;
        const float* row = qraw + (size_t)r * 2048;

        float ss = 0.f;
        for (int d = threadIdx.x; d < 2048; d += 256) { float x = row[d]; ss += x * x; }
        float tot = block_sum_256(ss);
        __shared__ float s_inv_q;
        if (threadIdx.x == 0) s_inv_q = rsqrtf(tot * (1.f / 2048.f) + 1e-6f);
        __syncthreads();
        const float inv = s_inv_q;

        const float* cs = cosb + (size_t)r * 64;
        const float* sn = sinb + (size_t)r * 64;

        for (int p = threadIdx.x; p < 1024; p += 256) {
            const int h = p >> 5, hdp = p & 31;
            float o2[2];
#pragma unroll
            for (int j = 0; j < 2; j++) {
                const int hd = 2 * hdp + j, d = h * 64 + hd;
                float val = row[d] * inv * qw[d];
                const int pd = (hd < 32) ? d + 32 : d - 32;
                float pv = row[pd] * inv * qw[pd];
                float rot = (hd < 32) ? -pv : pv;
                o2[j] = val * cs[hd] + rot * sn[hd];
            }
            const uint32_t hb = pack_hi(o2[0], o2[1]);
            const size_t oi = (((size_t)(b * NH_ + h)) * S_ + s) * 32 + hdp;
            QH[oi] = hb;
            QL[oi] = pack_lo(o2[0], o2[1], hb);
        }
    } else if (blk < 4096) {
        // ---- K norm + rope (transposed pack) ----
        const int r = blk - 2048;
        const int b = r >> 10, s = r & 1023;
        const float* row = kraw + (size_t)r * 512;

        float ss = 0.f;
        for (int d = threadIdx.x; d < 512; d += 256) { float x = row[d]; ss += x * x; }
        float tot = block_sum_256(ss);
        __shared__ float s_inv_k;
        if (threadIdx.x == 0) s_inv_k = rsqrtf(tot * (1.f / 512.f) + 1e-6f);
        __syncthreads();
        const float inv = s_inv_k;

        const float* cs = cosb + (size_t)r * 64;
        const float* sn = sinb + (size_t)r * 64;

        const int p = threadIdx.x;
        const int h = p >> 5, hdp = p & 31;
        float o2[2];
#pragma unroll
        for (int j = 0; j < 2; j++) {
            const int hd = 2 * hdp + j, d = h * 64 + hd;
            float val = row[d] * inv * kw[d];
            const int pd = (hd < 32) ? d + 32 : d - 32;
            float pv = row[pd] * inv * kw[pd];
            float rot = (hd < 32) ? -pv : pv;
            o2[j] = val * cs[hd] + rot * sn[hd];
        }
        const uint32_t hb = pack_hi(o2[0], o2[1]);
        const size_t oi = (((size_t)(b * NKV_ + h)) * 32 + hdp) * S_ + s;
        KH[oi] = hb;
        KL[oi] = pack_lo(o2[0], o2[1], hb);
    } else {
        // ---- V pack ----
        const int i = (blk - 4096) * 256 + threadIdx.x;
        const int d  = i & 63;
        const int sp = (i >> 6) & 511;
        const int hk = (i >> 15) & 7;
        const int b  = i >> 18;
        const float x = vraw[((size_t)(b * 1024 + 2 * sp)) * 512 + hk * 64 + d];
        const float y = vraw[((size_t)(b * 1024 + 2 * sp + 1)) * 512 + hk * 64 + d];
        const uint32_t h = pack_hi(x, y);
        VH[i] = h;
        VL[i] = pack_lo(x, y, h);
    }
}

// ---------------------------------------------------------------------------
// Flash attention, bf16 m16n8k16 3-split (R8, proven).
// Grid (h=32, b=2, z=16) with qt = 15 - z  (LPT: heavy tiles first).
// ---------------------------------------------------------------------------
#define PP 36
#define BPP 72
#define KPLANE_W (32 * BPP)
#define FSTAGE_W (4 * KPLANE_W)
#define FSTAGE_B (FSTAGE_W * 4)
#define FLASH_SMEM (2 * FSTAGE_B + 2 * 64 * PP * 4)

__global__ __launch_bounds__(128) void flash_bf16(
    const uint32_t* __restrict__ QH, const uint32_t* __restrict__ QL,
    const uint32_t* __restrict__ KH, const uint32_t* __restrict__ KL,
    const uint32_t* __restrict__ VH, const uint32_t* __restrict__ VL,
    float* __restrict__ ctx)
{
    extern __shared__ uint32_t fsm[];
    uint32_t* pH = fsm + 2 * FSTAGE_W;
    uint32_t* pL = pH + 64 * PP;

    const int tid = threadIdx.x, lane = tid & 31, warp = tid >> 5;
    const int g = lane >> 2, t = lane & 3;
    const int wm = warp * 16;
    const int h = blockIdx.x, b = blockIdx.y;
    const int qt = 15 - blockIdx.z;          // LPT: heaviest first
    const int hk = h >> 2;

    uint32_t sbase;
    asm("{ .reg .u64 tt; cvta.to.shared.u64 tt, %1; cvt.u32.u64 %0, tt; }"
        : "=r"(sbase) : "l"(fsm));

    const uint32_t* kbH = KH + ((size_t)(b * NKV_ + hk)) * 32 * S_;
    const uint32_t* kbL = KL + ((size_t)(b * NKV_ + hk)) * 32 * S_;
    const uint32_t* vbH = VH + ((size_t)(b * NKV_ + hk)) * 512 * 64;
    const uint32_t* vbL = VL + ((size_t)(b * NKV_ + hk)) * 512 * 64;

    uint32_t qa_h[4][4], qa_l[4][4];
    {
        const size_t qoff = (((size_t)(b * NH_ + h)) * S_ + qt * 64 + wm) * 32;
#pragma unroll
        for (int ks = 0; ks < 4; ks++) {
            qa_h[ks][0] = QH[qoff + g * 32 + ks * 8 + t];
            qa_h[ks][1] = QH[qoff + (g + 8) * 32 + ks * 8 + t];
            qa_h[ks][2] = QH[qoff + g * 32 + ks * 8 + t + 4];
            qa_h[ks][3] = QH[qoff + (g + 8) * 32 + ks * 8 + t + 4];
            qa_l[ks][0] = QL[qoff + g * 32 + ks * 8 + t];
            qa_l[ks][1] = QL[qoff + (g + 8) * 32 + ks * 8 + t];
            qa_l[ks][2] = QL[qoff + g * 32 + ks * 8 + t + 4];
            qa_l[ks][3] = QL[qoff + (g + 8) * 32 + ks * 8 + t + 4];
        }
    }

    float o[8][4];
#pragma unroll
    for (int nt = 0; nt < 8; nt++)
#pragma unroll
        for (int c = 0; c < 4; c++) o[nt][c] = 0.f;
    float m0 = -1e30f, m1 = -1e30f, l0 = 0.f, l1 = 0.f;

    const int ntiles = qt + 1;

    auto load_tile = [&](int kt) {
        const uint32_t st = sbase + (kt & 1) * FSTAGE_B;
#pragma unroll
        for (int i = 0; i < 16; i++) {
            const int plane = i >> 2;
            const int chunk = (i & 3) * 128 + tid;
            const int row = chunk >> 4;
            const int ch = chunk & 15;
            const uint32_t dst = st + plane * (KPLANE_W * 4) + row * (BPP * 4) + ch * 16;
            const uint32_t* src;
            if (plane == 0)      src = kbH + (size_t)row * S_ + kt * 64 + ch * 4;
            else if (plane == 1) src = kbL + (size_t)row * S_ + kt * 64 + ch * 4;
            else if (plane == 2) src = vbH + (size_t)(kt * 32 + row) * 64 + ch * 4;
            else                 src = vbL + (size_t)(kt * 32 + row) * 64 + ch * 4;
            cp16(dst, src);
        }
    };

    load_tile(0);
    asm volatile("cp.async.commit_group;" ::: "memory");

    for (int kt = 0; kt < ntiles; kt++) {
        if (kt + 1 < ntiles) load_tile(kt + 1);
        asm volatile("cp.async.commit_group;" ::: "memory");
        asm volatile("cp.async.wait_group 1;" ::: "memory");
        __syncthreads();

        const uint32_t* kThs = fsm + (kt & 1) * FSTAGE_W;
        const uint32_t* kTls = kThs + KPLANE_W;
        const uint32_t* vhs  = kThs + 2 * KPLANE_W;
        const uint32_t* vls  = kThs + 3 * KPLANE_W;

        float sf[8][4];
#pragma unroll
        for (int nt = 0; nt < 8; nt++)
#pragma unroll
            for (int c = 0; c < 4; c++) sf[nt][c] = 0.f;

#pragma unroll
        for (int nt = 0; nt < 8; nt++) {
#pragma unroll
            for (int ks = 0; ks < 4; ks++) {
                const uint32_t bh0 = kThs[(ks * 8 + t) * BPP + 8 * nt + g];
                const uint32_t bh1 = kThs[(ks * 8 + t + 4) * BPP + 8 * nt + g];
                const uint32_t bl0 = kTls[(ks * 8 + t) * BPP + 8 * nt + g];
                const uint32_t bl1 = kTls[(ks * 8 + t + 4) * BPP + 8 * nt + g];
                float* cc = sf[nt];
                mma_bf16(cc[0], cc[1], cc[2], cc[3],
                         qa_h[ks][0], qa_h[ks][1], qa_h[ks][2], qa_h[ks][3], bh0, bh1);
                mma_bf16(cc[0], cc[1], cc[2], cc[3],
                         qa_h[ks][0], qa_h[ks][1], qa_h[ks][2], qa_h[ks][3], bl0, bl1);
                mma_bf16(cc[0], cc[1], cc[2], cc[3],
                         qa_l[ks][0], qa_l[ks][1], qa_l[ks][2], qa_l[ks][3], bh0, bh1);
            }
        }

        const bool diag = (kt == qt);
        float mn0 = m0, mn1 = m1;
#pragma unroll
        for (int nt = 0; nt < 8; nt++) {
#pragma unroll
            for (int c = 0; c < 4; c++) {
                float v = sf[nt][c] * 0.125f;
                const int colloc = nt * 8 + 2 * t + (c & 1);
                const int rowloc = wm + g + ((c >= 2) ? 8 : 0);
                if (diag && colloc > rowloc) v = -1e30f;
                sf[nt][c] = v;
                if (c < 2) mn0 = fmaxf(mn0, v);
                else       mn1 = fmaxf(mn1, v);
            }
        }
        mn0 = fmaxf(mn0, __shfl_xor_sync(0xffffffffu, mn0, 1));
        mn0 = fmaxf(mn0, __shfl_xor_sync(0xffffffffu, mn0, 2));
        mn1 = fmaxf(mn1, __shfl_xor_sync(0xffffffffu, mn1, 1));
        mn1 = fmaxf(mn1, __shfl_xor_sync(0xffffffffu, mn1, 2));

        const float sc0 = __expf(m0 - mn0);
        const float sc1 = __expf(m1 - mn1);
        m0 = mn0; m1 = mn1;
        l0 *= sc0; l1 *= sc1;
#pragma unroll
        for (int nt = 0; nt < 8; nt++) {
            o[nt][0] *= sc0; o[nt][1] *= sc0;
            o[nt][2] *= sc1; o[nt][3] *= sc1;
        }

        float ps0 = 0.f, ps1 = 0.f;
#pragma unroll
        for (int nt = 0; nt < 8; nt++) {
            float p0 = __expf(sf[nt][0] - mn0);
            float p1 = __expf(sf[nt][1] - mn0);
            float p2 = __expf(sf[nt][2] - mn1);
            float p3 = __expf(sf[nt][3] - mn1);
            ps0 += p0 + p1;
            ps1 += p2 + p3;
            const uint32_t h01 = pack_hi(p0, p1);
            const uint32_t h23 = pack_hi(p2, p3);
            const int kp = nt * 4 + t;
            pH[(wm + g) * PP + kp] = h01;
            pH[(wm + g + 8) * PP + kp] = h23;
            pL[(wm + g) * PP + kp] = pack_lo(p0, p1, h01);
            pL[(wm + g + 8) * PP + kp] = pack_lo(p2, p3, h23);
        }
        ps0 += __shfl_xor_sync(0xffffffffu, ps0, 1);
        ps0 += __shfl_xor_sync(0xffffffffu, ps0, 2);
        ps1 += __shfl_xor_sync(0xffffffffu, ps1, 1);
        ps1 += __shfl_xor_sync(0xffffffffu, ps1, 2);
        l0 += ps0; l1 += ps1;
        __syncwarp();

#pragma unroll
        for (int ks = 0; ks < 4; ks++) {
            uint32_t pa_h[4], pa_l[4];
            pa_h[0] = pH[(wm + g) * PP + ks * 8 + t];
            pa_h[1] = pH[(wm + g + 8) * PP + ks * 8 + t];
            pa_h[2] = pH[(wm + g) * PP + ks * 8 + t + 4];
            pa_h[3] = pH[(wm + g + 8) * PP + ks * 8 + t + 4];
            pa_l[0] = pL[(wm + g) * PP + ks * 8 + t];
            pa_l[1] = pL[(wm + g + 8) * PP + ks * 8 + t];
            pa_l[2] = pL[(wm + g) * PP + ks * 8 + t + 4];
            pa_l[3] = pL[(wm + g + 8) * PP + ks * 8 + t + 4];
#pragma unroll
            for (int nt = 0; nt < 8; nt++) {
                const uint32_t bh0 = vhs[(ks * 8 + t) * BPP + 8 * nt + g];
                const uint32_t bh1 = vhs[(ks * 8 + t + 4) * BPP + 8 * nt + g];
                const uint32_t bl0 = vls[(ks * 8 + t) * BPP + 8 * nt + g];
                const uint32_t bl1 = vls[(ks * 8 + t + 4) * BPP + 8 * nt + g];
                float* cc = o[nt];
                mma_bf16(cc[0], cc[1], cc[2], cc[3],
                         pa_h[0], pa_h[1], pa_h[2], pa_h[3], bh0, bh1);
                mma_bf16(cc[0], cc[1], cc[2], cc[3],
                         pa_l[0], pa_l[1], pa_l[2], pa_l[3], bh0, bh1);
                mma_bf16(cc[0], cc[1], cc[2], cc[3],
                         pa_h[0], pa_h[1], pa_h[2], pa_h[3], bl0, bl1);
            }
        }
        __syncthreads();
    }

    const float inv0 = 1.f / l0, inv1 = 1.f / l1;
    float* crow0 = ctx + ((size_t)(b * S_ + qt * 64 + wm + g)) * 2048 + h * 64;
    float* crow1 = crow0 + (size_t)8 * 2048;
#pragma unroll
    for (int nt = 0; nt < 8; nt++) {
        const int col = nt * 8 + 2 * t;
        *reinterpret_cast<float2*>(crow0 + col) =
            make_float2(o[nt][0] * inv0, o[nt][1] * inv0);
        *reinterpret_cast<float2*>(crow1 + col) =
            make_float2(o[nt][2] * inv1, o[nt][3] * inv1);
    }
}

// ---------------------------------------------------------------------------
// Launch
// ---------------------------------------------------------------------------
extern "C" void kernel_launch(void* const* d_in, const int* in_sizes, int n_in,
                              void* d_out, int out_size)
{
    const float* X    = (const float*)d_in[0];
    const float* cosb = (const float*)d_in[1];
    const float* sinb = (const float*)d_in[2];
    // d_in[3] attention_mask unused (causal handled analytically)
    const float* wq = (const float*)d_in[4];
    const float* wk = (const float*)d_in[5];
    const float* wv = (const float*)d_in[6];
    const float* wo = (const float*)d_in[7];
    const float* qw = (const float*)d_in[8];
    const float* kw = (const float*)d_in[9];
    float* out = (float*)d_out;

    float *qraw, *kraw, *vraw, *ctx;
    uint32_t *QH, *QL, *KHp, *KLp, *VHp, *VLp;
    uint32_t *A1, *A2, *WQ1, *WQ2, *WK1, *WK2, *WV1, *WV2, *WO1, *WO2;
    float *mxA, *mxQ, *mxK, *mxV, *mxO;
    cudaGetSymbolAddress((void**)&qraw, g_qraw);
    cudaGetSymbolAddress((void**)&kraw, g_kraw);
    cudaGetSymbolAddress((void**)&vraw, g_vraw);
    cudaGetSymbolAddress((void**)&ctx,  g_ctx);
    cudaGetSymbolAddress((void**)&QH,   g_QH);
    cudaGetSymbolAddress((void**)&QL,   g_QL);
    cudaGetSymbolAddress((void**)&KHp,  g_KHp);
    cudaGetSymbolAddress((void**)&KLp,  g_KLp);
    cudaGetSymbolAddress((void**)&VHp,  g_VHp);
    cudaGetSymbolAddress((void**)&VLp,  g_VLp);
    cudaGetSymbolAddress((void**)&A1,   g_A1);
    cudaGetSymbolAddress((void**)&A2,   g_A2);
    cudaGetSymbolAddress((void**)&WQ1,  g_WQ1);
    cudaGetSymbolAddress((void**)&WQ2,  g_WQ2);
    cudaGetSymbolAddress((void**)&WK1,  g_WK1);
    cudaGetSymbolAddress((void**)&WK2,  g_WK2);
    cudaGetSymbolAddress((void**)&WV1,  g_WV1);
    cudaGetSymbolAddress((void**)&WV2,  g_WV2);
    cudaGetSymbolAddress((void**)&WO1,  g_WO1);
    cudaGetSymbolAddress((void**)&WO2,  g_WO2);
    cudaGetSymbolAddress((void**)&mxA,  g_mxA);
    cudaGetSymbolAddress((void**)&mxQ,  g_mxQ);
    cudaGetSymbolAddress((void**)&mxK,  g_mxK);
    cudaGetSymbolAddress((void**)&mxV,  g_mxV);
    cudaGetSymbolAddress((void**)&mxO,  g_mxO);

    cudaFuncSetAttribute(flash_bf16, cudaFuncAttributeMaxDynamicSharedMemorySize,
                         FLASH_SMEM);
    cudaFuncSetAttribute(gemm_i8_qkv, cudaFuncAttributeMaxDynamicSharedMemorySize, G2_SMEM);
    cudaFuncSetAttribute(gemm_i8, cudaFuncAttributeMaxDynamicSharedMemorySize, G2_SMEM);

    // ---- scale + quant prep (fused launches) ----
    zero_all<<<8, 256>>>(mxQ, mxK, mxV, mxO);
    colmax_all<<<dim3(80, 8), 256>>>(wq, wk, wv, wo, mxQ, mxK, mxV, mxO);
    quant_w_all<<<10240, 256>>>(wq, wk, wv, wo, mxQ, mxK, mxV, mxO,
                                WQ1, WQ2, WK1, WK2, WV1, WV2, WO1, WO2);
    rowmax<<<2048, 256>>>(X, mxA, 2048);
    tquant<<<dim3(64, 32), 256>>>(X, mxA, A1, A2, 2048, 2048);

    // ---- fused Q+K+V projections (one launch, 384 blocks) ----
    gemm_i8_qkv<<<dim3(24, 16), 256, G2_SMEM>>>(
        A1, A2, WQ1, WQ2, WK1, WK2, WV1, WV2,
        mxA, mxQ, mxK, mxV, qraw, kraw, vraw);

    // ---- fused norm / rope / pack ----
    normpack_all<<<6144, 256>>>(qraw, kraw, vraw, qw, kw, cosb, sinb,
                                QH, QL, KHp, KLp, VHp, VLp);

    // ---- flash (LPT grid: heavy qt first) ----
    flash_bf16<<<dim3(NH_, B_, 16), 128, FLASH_SMEM>>>(QH, QL, KHp, KLp, VHp, VLp, ctx);

    // ---- output projection ----
    rowmax<<<2048, 256>>>(ctx, mxA, 2048);
    tquant<<<dim3(64, 32), 256>>>(ctx, mxA, A1, A2, 2048, 2048);
    gemm_i8<<<dim3(16, 16), 256, G2_SMEM>>>(A1, A2, WO1, WO2, mxA, mxO,
                                            out, 2048, 2048, 2048);
}